// round 1
// baseline (speedup 1.0000x reference)
#include <cuda_runtime.h>
#include <math.h>

// ---------------- problem constants ----------------
#define BB   2
#define SS   1024
#define DD   768
#define HH   12
#define DH   64
#define FF_  3072
#define LL   12
#define VV   50257
#define MR   2048          // B*S rows
#define D3   2304          // 3*D

// ---------------- scratch (static device memory; no runtime allocs) -------
__device__ float g_x   [MR * DD];          // residual stream
__device__ float g_h   [MR * DD];          // LN output / misc
__device__ float g_qkv [MR * D3];          // qkv projections
__device__ float g_att [24u * 1024u * 1024u]; // B*H*S*S attention probs
__device__ float g_o   [MR * DD];          // attention output (merged heads)
__device__ float g_ff  [MR * FF_];         // MLP intermediate
__device__ float g_picked[MR];             // per-row picked logprob (2nd softmax)

// ---------------- block reductions ----------------
__device__ __forceinline__ float blockReduceSum(float v) {
    __shared__ float sh[32];
    int lane = threadIdx.x & 31, wid = threadIdx.x >> 5;
    #pragma unroll
    for (int o = 16; o; o >>= 1) v += __shfl_xor_sync(0xffffffffu, v, o);
    __syncthreads();
    if (lane == 0) sh[wid] = v;
    __syncthreads();
    float r = (lane < (int)(blockDim.x >> 5)) ? sh[lane] : 0.f;
    if (wid == 0) {
        #pragma unroll
        for (int o = 16; o; o >>= 1) r += __shfl_xor_sync(0xffffffffu, r, o);
        if (lane == 0) sh[0] = r;
    }
    __syncthreads();
    return sh[0];
}

__device__ __forceinline__ float blockReduceMax(float v) {
    __shared__ float shm[32];
    int lane = threadIdx.x & 31, wid = threadIdx.x >> 5;
    #pragma unroll
    for (int o = 16; o; o >>= 1) v = fmaxf(v, __shfl_xor_sync(0xffffffffu, v, o));
    __syncthreads();
    if (lane == 0) shm[wid] = v;
    __syncthreads();
    float r = (lane < (int)(blockDim.x >> 5)) ? shm[lane] : -INFINITY;
    if (wid == 0) {
        #pragma unroll
        for (int o = 16; o; o >>= 1) r = fmaxf(r, __shfl_xor_sync(0xffffffffu, r, o));
        if (lane == 0) shm[0] = r;
    }
    __syncthreads();
    return shm[0];
}

// ---------------- embedding ----------------
__global__ void embed_kernel(const int* __restrict__ tokens,
                             const float* __restrict__ wte,
                             const float* __restrict__ wpe,
                             float* __restrict__ x) {
    int i = blockIdx.x * blockDim.x + threadIdx.x;
    if (i >= MR * DD) return;
    int row = i / DD, d = i - row * DD;
    int s = row & (SS - 1);
    x[i] = wte[(size_t)tokens[row] * DD + d] + wpe[(size_t)s * DD + d];
}

// ---------------- layernorm (row=768, block=256) ----------------
__global__ void layernorm_kernel(const float* __restrict__ in,
                                 const float* __restrict__ g,
                                 const float* __restrict__ b,
                                 float* __restrict__ out) {
    int row = blockIdx.x;
    const float* x = in + (size_t)row * DD;
    int t = threadIdx.x;
    float v0 = x[t], v1 = x[t + 256], v2 = x[t + 512];
    float s = blockReduceSum(v0 + v1 + v2);
    float mu = s * (1.0f / 768.0f);
    float d0 = v0 - mu, d1 = v1 - mu, d2 = v2 - mu;
    float q = blockReduceSum(d0 * d0 + d1 * d1 + d2 * d2);
    float rstd = rsqrtf(q * (1.0f / 768.0f) + 1e-5f);
    float* o = out + (size_t)row * DD;
    o[t]       = d0 * rstd * g[t]       + b[t];
    o[t + 256] = d1 * rstd * g[t + 256] + b[t + 256];
    o[t + 512] = d2 * rstd * g[t + 512] + b[t + 512];
}

// ---------------- generic NN GEMM: C = A[MxK] @ B[KxN] (+bias)(+res)(gelu) --
// tile 64x64, BK=16, 256 threads, 4x4 per thread. Assumes M%64==N%64==K%16==0.
__global__ void gemm_nn_kernel(const float* __restrict__ A,
                               const float* __restrict__ B,
                               float* __restrict__ C,
                               const float* __restrict__ bias,
                               const float* __restrict__ res,
                               int M, int N, int K,
                               int lda, int ldb, int ldc, int act) {
    __shared__ float As[16][68];
    __shared__ float Bs[16][68];
    int m0 = blockIdx.y * 64, n0 = blockIdx.x * 64;
    int t = threadIdx.x, tx = t & 15, ty = t >> 4;
    float acc[4][4] = {};
    for (int k0 = 0; k0 < K; k0 += 16) {
        #pragma unroll
        for (int e = 0; e < 4; e++) {
            int idx = t + e * 256;
            int r = idx >> 4, kk = idx & 15;
            As[kk][r] = A[(size_t)(m0 + r) * lda + k0 + kk];
            int kk2 = idx >> 6, n = idx & 63;
            Bs[kk2][n] = B[(size_t)(k0 + kk2) * ldb + n0 + n];
        }
        __syncthreads();
        #pragma unroll
        for (int k = 0; k < 16; k++) {
            float a[4], bv[4];
            #pragma unroll
            for (int i = 0; i < 4; i++) a[i] = As[k][ty * 4 + i];
            #pragma unroll
            for (int j = 0; j < 4; j++) bv[j] = Bs[k][tx * 4 + j];
            #pragma unroll
            for (int i = 0; i < 4; i++)
                #pragma unroll
                for (int j = 0; j < 4; j++)
                    acc[i][j] += a[i] * bv[j];
        }
        __syncthreads();
    }
    #pragma unroll
    for (int i = 0; i < 4; i++) {
        int row = m0 + ty * 4 + i;
        #pragma unroll
        for (int j = 0; j < 4; j++) {
            int col = n0 + tx * 4 + j;
            float v = acc[i][j];
            if (bias) v += bias[col];
            if (res)  v += res[(size_t)row * ldc + col];
            if (act)  v = v * 0.5f * (1.0f + erff(v * 0.70710678118654752f));
            C[(size_t)row * ldc + col] = v;
        }
    }
}

// ---------------- attention scores: S = Q K^T * (1/sqrt(768)) ----------------
__global__ void attn_scores_kernel(const float* __restrict__ qkv,
                                   float* __restrict__ att) {
    int k0 = blockIdx.x * 64;
    int q0 = blockIdx.y * 64;
    if (k0 > q0 + 63) return;  // fully masked tile (softmax zero-fills it)
    int bh = blockIdx.z, b = bh / HH, h = bh - b * HH;
    const float* Q  = qkv + (size_t)b * SS * D3 + (size_t)h * DH;
    const float* Kp = qkv + (size_t)b * SS * D3 + DD + (size_t)h * DH;
    float* Cp = att + (size_t)bh * SS * SS;
    __shared__ float Qs[64][17];
    __shared__ float Ks[64][17];
    int t = threadIdx.x, tx = t & 15, ty = t >> 4;
    float acc[4][4] = {};
    for (int kt = 0; kt < DH; kt += 16) {
        #pragma unroll
        for (int e = 0; e < 4; e++) {
            int idx = t + e * 256;
            int r = idx >> 4, kk = idx & 15;
            Qs[r][kk] = Q [(size_t)(q0 + r) * D3 + kt + kk];
            Ks[r][kk] = Kp[(size_t)(k0 + r) * D3 + kt + kk];
        }
        __syncthreads();
        #pragma unroll
        for (int k = 0; k < 16; k++) {
            float a[4], bv[4];
            #pragma unroll
            for (int i = 0; i < 4; i++) a[i] = Qs[ty * 4 + i][k];
            #pragma unroll
            for (int j = 0; j < 4; j++) bv[j] = Ks[tx * 4 + j][k];
            #pragma unroll
            for (int i = 0; i < 4; i++)
                #pragma unroll
                for (int j = 0; j < 4; j++)
                    acc[i][j] += a[i] * bv[j];
        }
        __syncthreads();
    }
    const float scale = 1.0f / sqrtf(768.0f);  // faithful quirk: 1/sqrt(embed_dim)
    #pragma unroll
    for (int i = 0; i < 4; i++)
        #pragma unroll
        for (int j = 0; j < 4; j++)
            Cp[(size_t)(q0 + ty * 4 + i) * SS + k0 + tx * 4 + j] = acc[i][j] * scale;
}

// ---------------- causal softmax per (bh, q) row; zeros k>q ----------------
__global__ void softmax_causal_kernel(float* __restrict__ att) {
    int gid = blockIdx.x;           // 0..24575
    int bh = gid >> 10, q = gid & 1023;
    float* p = att + (size_t)bh * SS * SS + (size_t)q * SS;
    int t = threadIdx.x;
    float v[4];
    float m = -INFINITY;
    #pragma unroll
    for (int i = 0; i < 4; i++) {
        int idx = t + i * 256;
        v[i] = (idx <= q) ? p[idx] : -INFINITY;
        m = fmaxf(m, v[i]);
    }
    m = blockReduceMax(m);
    float s = 0.f;
    #pragma unroll
    for (int i = 0; i < 4; i++) {
        int idx = t + i * 256;
        if (idx <= q) { v[i] = expf(v[i] - m); s += v[i]; }
        else v[i] = 0.f;
    }
    s = blockReduceSum(s);
    float inv = 1.0f / s;
    #pragma unroll
    for (int i = 0; i < 4; i++) p[t + i * 256] = v[i] * inv;
}

// ---------------- O = att @ V (per bh), K-loop cut at causal boundary -------
__global__ void attn_av_kernel(const float* __restrict__ att,
                               const float* __restrict__ qkv,
                               float* __restrict__ o) {
    int q0 = blockIdx.x * 64;
    int bh = blockIdx.y, b = bh / HH, h = bh - b * HH;
    const float* A  = att + (size_t)bh * SS * SS;
    const float* Vv = qkv + (size_t)b * SS * D3 + 2 * DD + (size_t)h * DH;
    float* Cp = o + (size_t)b * SS * DD + (size_t)h * DH;
    __shared__ float As[16][68];
    __shared__ float Bs[16][68];
    int t = threadIdx.x, tx = t & 15, ty = t >> 4;
    float acc[4][4] = {};
    int kend = q0 + 64;   // att[q,k]==0 for k>q, so k>=q0+64 contributes nothing
    for (int k0 = 0; k0 < kend; k0 += 16) {
        #pragma unroll
        for (int e = 0; e < 4; e++) {
            int idx = t + e * 256;
            int r = idx >> 4, kk = idx & 15;
            As[kk][r] = A[(size_t)(q0 + r) * SS + k0 + kk];
            int kk2 = idx >> 6, n = idx & 63;
            Bs[kk2][n] = Vv[(size_t)(k0 + kk2) * D3 + n];
        }
        __syncthreads();
        #pragma unroll
        for (int k = 0; k < 16; k++) {
            float a[4], bv[4];
            #pragma unroll
            for (int i = 0; i < 4; i++) a[i] = As[k][ty * 4 + i];
            #pragma unroll
            for (int j = 0; j < 4; j++) bv[j] = Bs[k][tx * 4 + j];
            #pragma unroll
            for (int i = 0; i < 4; i++)
                #pragma unroll
                for (int j = 0; j < 4; j++)
                    acc[i][j] += a[i] * bv[j];
        }
        __syncthreads();
    }
    #pragma unroll
    for (int i = 0; i < 4; i++)
        #pragma unroll
        for (int j = 0; j < 4; j++)
            Cp[(size_t)(q0 + ty * 4 + i) * DD + tx * 4 + j] = acc[i][j];
}

// ---------------- NT GEMM (logits): C = A[MxK] @ B[NxK]^T, N bounds ---------
__global__ void gemm_nt_kernel(const float* __restrict__ A,
                               const float* __restrict__ B,
                               float* __restrict__ C,
                               int M, int N, int K,
                               int lda, int ldb, int ldc) {
    int n0 = blockIdx.x * 64, m0 = blockIdx.y * 64;
    __shared__ float As[64][17];
    __shared__ float Bs[64][17];
    int t = threadIdx.x, tx = t & 15, ty = t >> 4;
    float acc[4][4] = {};
    for (int k0 = 0; k0 < K; k0 += 16) {
        #pragma unroll
        for (int e = 0; e < 4; e++) {
            int idx = t + e * 256;
            int r = idx >> 4, kk = idx & 15;
            As[r][kk] = A[(size_t)(m0 + r) * lda + k0 + kk];
            int gn = n0 + r;
            Bs[r][kk] = (gn < N) ? B[(size_t)gn * ldb + k0 + kk] : 0.f;
        }
        __syncthreads();
        #pragma unroll
        for (int k = 0; k < 16; k++) {
            float a[4], bv[4];
            #pragma unroll
            for (int i = 0; i < 4; i++) a[i] = As[ty * 4 + i][k];
            #pragma unroll
            for (int j = 0; j < 4; j++) bv[j] = Bs[tx * 4 + j][k];
            #pragma unroll
            for (int i = 0; i < 4; i++)
                #pragma unroll
                for (int j = 0; j < 4; j++)
                    acc[i][j] += a[i] * bv[j];
        }
        __syncthreads();
    }
    #pragma unroll
    for (int i = 0; i < 4; i++) {
        int row = m0 + ty * 4 + i;
        #pragma unroll
        for (int j = 0; j < 4; j++) {
            int col = n0 + tx * 4 + j;
            if (col < N) C[(size_t)row * ldc + col] = acc[i][j];
        }
    }
}

// ---- log_softmax over V in-place + second log_softmax picked value --------
// lp = x - m - log(s). max(lp) = -log(s) exactly (same m,s), so the second
// log_softmax needs only s2 = sum exp(lp + log s).
__global__ void logsoftmax_loss_kernel(float* __restrict__ logits,
                                       const int* __restrict__ target,
                                       float* __restrict__ picked) {
    int row = blockIdx.x;
    float* x = logits + (size_t)row * VV;
    int t = threadIdx.x;
    float m = -INFINITY;
    for (int i = t; i < VV; i += 256) m = fmaxf(m, x[i]);
    m = blockReduceMax(m);
    float s = 0.f;
    for (int i = t; i < VV; i += 256) s += expf(x[i] - m);
    s = blockReduceSum(s);
    float ls = logf(s);
    float m2 = -ls;   // max of written lp values
    float s2 = 0.f;
    for (int i = t; i < VV; i += 256) {
        float lp = x[i] - m - ls;
        x[i] = lp;
        s2 += expf(lp - m2);
    }
    s2 = blockReduceSum(s2);   // syncthreads inside makes x[] writes visible
    if (t == 0) {
        int tgt = target[row];
        picked[row] = x[tgt] - m2 - logf(s2);
    }
}

__global__ void finalize_loss_kernel(const float* __restrict__ picked,
                                     float* __restrict__ out) {
    float s = 0.f;
    for (int i = threadIdx.x; i < MR; i += 256) s += picked[i];
    s = blockReduceSum(s);
    if (threadIdx.x == 0) out[(size_t)MR * VV] = -s * (1.0f / (float)MR);
}

// ---------------- host orchestration ----------------
extern "C" void kernel_launch(void* const* d_in, const int* in_sizes, int n_in,
                              void* d_out, int out_size) {
    const int*   tokens = (const int*)  d_in[0];
    const int*   target = (const int*)  d_in[1];
    const float* wte    = (const float*)d_in[2];
    const float* wpe    = (const float*)d_in[3];
    const float* ln1_g  = (const float*)d_in[4];
    const float* ln1_b  = (const float*)d_in[5];
    const float* qkv_w  = (const float*)d_in[6];
    const float* qkv_b  = (const float*)d_in[7];
    const float* proj_w = (const float*)d_in[8];
    const float* proj_b = (const float*)d_in[9];
    const float* ln2_g  = (const float*)d_in[10];
    const float* ln2_b  = (const float*)d_in[11];
    const float* fc1_w  = (const float*)d_in[12];
    const float* fc1_b  = (const float*)d_in[13];
    const float* fc2_w  = (const float*)d_in[14];
    const float* fc2_b  = (const float*)d_in[15];
    const float* lnf_g  = (const float*)d_in[16];
    const float* lnf_b  = (const float*)d_in[17];
    float* out = (float*)d_out;

    float *gx, *gh, *gqkv, *gatt, *go, *gff, *gpicked;
    cudaGetSymbolAddress((void**)&gx,      g_x);
    cudaGetSymbolAddress((void**)&gh,      g_h);
    cudaGetSymbolAddress((void**)&gqkv,    g_qkv);
    cudaGetSymbolAddress((void**)&gatt,    g_att);
    cudaGetSymbolAddress((void**)&go,      g_o);
    cudaGetSymbolAddress((void**)&gff,     g_ff);
    cudaGetSymbolAddress((void**)&gpicked, g_picked);

    embed_kernel<<<(MR * DD + 255) / 256, 256>>>(tokens, wte, wpe, gx);

    for (int l = 0; l < LL; l++) {
        layernorm_kernel<<<MR, 256>>>(gx, ln1_g + (size_t)l * DD, ln1_b + (size_t)l * DD, gh);

        gemm_nn_kernel<<<dim3(D3 / 64, MR / 64), 256>>>(
            gh, qkv_w + (size_t)l * DD * D3, gqkv,
            qkv_b + (size_t)l * D3, nullptr,
            MR, D3, DD, DD, D3, D3, 0);

        attn_scores_kernel<<<dim3(SS / 64, SS / 64, BB * HH), 256>>>(gqkv, gatt);
        softmax_causal_kernel<<<BB * HH * SS, 256>>>(gatt);
        attn_av_kernel<<<dim3(SS / 64, BB * HH), 256>>>(gatt, gqkv, go);

        gemm_nn_kernel<<<dim3(DD / 64, MR / 64), 256>>>(
            go, proj_w + (size_t)l * DD * DD, gx,
            proj_b + (size_t)l * DD, gx,
            MR, DD, DD, DD, DD, DD, 0);

        layernorm_kernel<<<MR, 256>>>(gx, ln2_g + (size_t)l * DD, ln2_b + (size_t)l * DD, gh);

        gemm_nn_kernel<<<dim3(FF_ / 64, MR / 64), 256>>>(
            gh, fc1_w + (size_t)l * DD * FF_, gff,
            fc1_b + (size_t)l * FF_, nullptr,
            MR, FF_, DD, DD, FF_, FF_, 1);

        gemm_nn_kernel<<<dim3(DD / 64, MR / 64), 256>>>(
            gff, fc2_w + (size_t)l * FF_ * DD, gx,
            fc2_b + (size_t)l * DD, gx,
            MR, DD, FF_, FF_, DD, DD, 0);
    }

    layernorm_kernel<<<MR, 256>>>(gx, lnf_g, lnf_b, gh);

    gemm_nt_kernel<<<dim3((VV + 63) / 64, MR / 64), 256>>>(
        gh, wte, out, MR, VV, DD, DD, DD, VV);

    logsoftmax_loss_kernel<<<MR, 256>>>(out, target, gpicked);
    finalize_loss_kernel<<<1, 256>>>(gpicked, out);
}

// round 3
// speedup vs baseline: 2.7373x; 2.7373x over previous
#include <cuda_runtime.h>
#include <cuda_bf16.h>
#include <math.h>
#include <stdint.h>

// ---------------- problem constants ----------------
#define BB   2
#define SS   1024
#define DD   768
#define HH   12
#define DH   64
#define FF_  3072
#define LL   12
#define VV   50257
#define MR   2048          // B*S rows
#define D3   2304          // 3*D

// ---------------- scratch (static device memory) ----------------
__device__ float g_x   [MR * DD];              // residual stream (fp32)
__device__ float g_qkv [MR * D3];              // qkv projections (fp32, for attn)
__device__ float g_att [24u * 1024u * 1024u];  // B*H*S*S attention probs
__device__ float g_picked[MR];

__device__ __nv_bfloat16 g_hb  [MR * DD];      // LN outputs (bf16 GEMM input)
__device__ __nv_bfloat16 g_ob  [MR * DD];      // attn output (bf16 GEMM input)
__device__ __nv_bfloat16 g_ffb [MR * FF_];     // GELU output (bf16 GEMM input)

__device__ __nv_bfloat16 g_wteb [VV * DD];         // wte bf16 [V, D]
__device__ __nv_bfloat16 g_qkvT [LL * DD * D3];    // [L][2304][768]
__device__ __nv_bfloat16 g_projT[LL * DD * DD];    // [L][768][768]
__device__ __nv_bfloat16 g_fc1T [LL * DD * FF_];   // [L][3072][768]
__device__ __nv_bfloat16 g_fc2T [LL * FF_ * DD];   // [L][768][3072]

// ================= low-level helpers (baseline PTX only) =================
__device__ __forceinline__ uint32_t smem_u32(const void* p) {
    uint32_t a;
    asm("{ .reg .u64 t; cvta.to.shared.u64 t, %1; cvt.u32.u64 %0, t; }" : "=r"(a) : "l"(p));
    return a;
}
__device__ __forceinline__ void cp_async16(uint32_t dst, const void* src, bool valid) {
    int sz = valid ? 16 : 0;
    asm volatile("cp.async.cg.shared.global [%0], [%1], 16, %2;"
                 :: "r"(dst), "l"(src), "r"(sz) : "memory");
}
#define CP_COMMIT()  asm volatile("cp.async.commit_group;" ::: "memory")
#define CP_WAIT(n)   asm volatile("cp.async.wait_group %0;" :: "n"(n) : "memory")

__device__ __forceinline__ void ldmatrix_x4(uint32_t& r0, uint32_t& r1,
                                            uint32_t& r2, uint32_t& r3, uint32_t addr) {
    asm volatile("ldmatrix.sync.aligned.m8n8.x4.shared.b16 {%0,%1,%2,%3}, [%4];"
                 : "=r"(r0), "=r"(r1), "=r"(r2), "=r"(r3) : "r"(addr));
}
__device__ __forceinline__ void mma_bf16(float* c, const uint32_t* a,
                                         uint32_t b0, uint32_t b1) {
    asm volatile(
        "mma.sync.aligned.m16n8k16.row.col.f32.bf16.bf16.f32 "
        "{%0,%1,%2,%3}, {%4,%5,%6,%7}, {%8,%9}, {%0,%1,%2,%3};"
        : "+f"(c[0]), "+f"(c[1]), "+f"(c[2]), "+f"(c[3])
        : "r"(a[0]), "r"(a[1]), "r"(a[2]), "r"(a[3]), "r"(b0), "r"(b1));
}

// ---------------- block reductions ----------------
__device__ __forceinline__ float blockReduceSum(float v) {
    __shared__ float sh[32];
    int lane = threadIdx.x & 31, wid = threadIdx.x >> 5;
    #pragma unroll
    for (int o = 16; o; o >>= 1) v += __shfl_xor_sync(0xffffffffu, v, o);
    __syncthreads();
    if (lane == 0) sh[wid] = v;
    __syncthreads();
    float r = (lane < (int)(blockDim.x >> 5)) ? sh[lane] : 0.f;
    if (wid == 0) {
        #pragma unroll
        for (int o = 16; o; o >>= 1) r += __shfl_xor_sync(0xffffffffu, r, o);
        if (lane == 0) sh[0] = r;
    }
    __syncthreads();
    return sh[0];
}
__device__ __forceinline__ float blockReduceMax(float v) {
    __shared__ float shm[32];
    int lane = threadIdx.x & 31, wid = threadIdx.x >> 5;
    #pragma unroll
    for (int o = 16; o; o >>= 1) v = fmaxf(v, __shfl_xor_sync(0xffffffffu, v, o));
    __syncthreads();
    if (lane == 0) shm[wid] = v;
    __syncthreads();
    float r = (lane < (int)(blockDim.x >> 5)) ? shm[lane] : -INFINITY;
    if (wid == 0) {
        #pragma unroll
        for (int o = 16; o; o >>= 1) r = fmaxf(r, __shfl_xor_sync(0xffffffffu, r, o));
        if (lane == 0) shm[0] = r;
    }
    __syncthreads();
    return shm[0];
}

// ---------------- weight prep ----------------
__global__ void transpose_to_bf16(const float* __restrict__ src,
                                  __nv_bfloat16* __restrict__ dst,
                                  int K, int N) {
    __shared__ float tile[32][33];
    const float* s = src + (size_t)blockIdx.z * K * N;
    __nv_bfloat16* d = dst + (size_t)blockIdx.z * K * N;
    int n0 = blockIdx.x * 32, k0 = blockIdx.y * 32;
    int tx = threadIdx.x, ty = threadIdx.y;  // 32 x 8
    #pragma unroll
    for (int i = 0; i < 32; i += 8)
        tile[ty + i][tx] = s[(size_t)(k0 + ty + i) * N + n0 + tx];
    __syncthreads();
    #pragma unroll
    for (int i = 0; i < 32; i += 8)
        d[(size_t)(n0 + ty + i) * K + k0 + tx] = __float2bfloat16(tile[tx][ty + i]);
}

__global__ void convert_bf16_kernel(const float* __restrict__ src,
                                    __nv_bfloat16* __restrict__ dst, long n) {
    long i = (long)blockIdx.x * blockDim.x + threadIdx.x;
    if (i < n) dst[i] = __float2bfloat16(src[i]);
}

// ---------------- embedding ----------------
__global__ void embed_kernel(const int* __restrict__ tokens,
                             const float* __restrict__ wte,
                             const float* __restrict__ wpe,
                             float* __restrict__ x) {
    int i = blockIdx.x * blockDim.x + threadIdx.x;
    if (i >= MR * DD) return;
    int row = i / DD, d = i - row * DD;
    int s = row & (SS - 1);
    x[i] = wte[(size_t)tokens[row] * DD + d] + wpe[(size_t)s * DD + d];
}

// ---------------- layernorm -> bf16 ----------------
__global__ void layernorm_kernel(const float* __restrict__ in,
                                 const float* __restrict__ g,
                                 const float* __restrict__ b,
                                 __nv_bfloat16* __restrict__ out) {
    int row = blockIdx.x;
    const float* x = in + (size_t)row * DD;
    int t = threadIdx.x;
    float v0 = x[t], v1 = x[t + 256], v2 = x[t + 512];
    float s = blockReduceSum(v0 + v1 + v2);
    float mu = s * (1.0f / 768.0f);
    float d0 = v0 - mu, d1 = v1 - mu, d2 = v2 - mu;
    float q = blockReduceSum(d0 * d0 + d1 * d1 + d2 * d2);
    float rstd = rsqrtf(q * (1.0f / 768.0f) + 1e-5f);
    __nv_bfloat16* o = out + (size_t)row * DD;
    o[t]       = __float2bfloat16(d0 * rstd * g[t]       + b[t]);
    o[t + 256] = __float2bfloat16(d1 * rstd * g[t + 256] + b[t + 256]);
    o[t + 512] = __float2bfloat16(d2 * rstd * g[t + 512] + b[t + 512]);
}

// ================= mma.sync NT GEMM =================
// C[M,N] = A[M,K] @ B[N,K]^T, A,B bf16 K-major (both NT, ldmatrix without trans).
// Block 128x128, BK=32, 256 thr / 8 warps (4x2), warp tile 32x64, m16n8k16.
#define GBM 128
#define GBN 128
#define GBK 32
#define ROWB 80           // smem row stride (64B data + 16B pad)
#define ABUF 10240        // 128 rows * 80B
#define BUFS 20480        // A+B per stage

__global__ __launch_bounds__(256, 1)
void gemm_mma_kernel(const __nv_bfloat16* __restrict__ A,
                     const __nv_bfloat16* __restrict__ B,
                     float* __restrict__ Cf,
                     __nv_bfloat16* __restrict__ Cbf,
                     const float* __restrict__ bias,
                     const float* __restrict__ res,
                     int N, int K, int ldc, int act) {
    __shared__ __align__(128) uint8_t sm[2 * BUFS];  // 40 KB
    uint32_t sbase = smem_u32(sm);
    int tid = threadIdx.x;
    int m0 = blockIdx.x * GBM, n0 = blockIdx.y * GBN;

    int nk = K / GBK;

    // --- async tile loader: 2 iterations x 256 threads x 16B, per operand ---
    auto issue = [&](int c) {
        int k0 = c * GBK;
        uint32_t dA = sbase + (c & 1) * BUFS;
        uint32_t dB = dA + ABUF;
        #pragma unroll
        for (int e = 0; e < 2; e++) {
            int idx = tid + e * 256;
            int r = idx >> 2, cc = idx & 3;
            cp_async16(dA + r * ROWB + cc * 16,
                       A + (size_t)(m0 + r) * K + k0 + cc * 8, true);
            int gn = n0 + r;
            cp_async16(dB + r * ROWB + cc * 16,
                       B + (size_t)gn * K + k0 + cc * 8, gn < N);
        }
        CP_COMMIT();
    };

    int warp = tid >> 5, lane = tid & 31;
    int wm = warp >> 1, wn = warp & 1;          // 4 x 2 warp grid
    int lr = lane & 15, lc = lane >> 4;         // ldmatrix row / col-block
    float acc[2][8][4];
    #pragma unroll
    for (int i = 0; i < 2; i++)
        #pragma unroll
        for (int j = 0; j < 8; j++)
            #pragma unroll
            for (int q = 0; q < 4; q++) acc[i][j][q] = 0.f;

    issue(0);
    for (int c = 0; c < nk; c++) {
        if (c + 1 < nk) { issue(c + 1); CP_WAIT(1); }
        else            { CP_WAIT(0); }
        __syncthreads();
        uint32_t aB = sbase + (c & 1) * BUFS;
        uint32_t bB = aB + ABUF;
        #pragma unroll
        for (int kk = 0; kk < 2; kk++) {
            uint32_t a[2][4];
            #pragma unroll
            for (int mi = 0; mi < 2; mi++) {
                uint32_t addr = aB + (uint32_t)((wm * 32 + mi * 16 + lr) * ROWB
                                                + (kk * 16 + lc * 8) * 2);
                ldmatrix_x4(a[mi][0], a[mi][1], a[mi][2], a[mi][3], addr);
            }
            #pragma unroll
            for (int nb = 0; nb < 4; nb++) {
                uint32_t b0, b1, b2, b3;
                uint32_t addr = bB + (uint32_t)((wn * 64 + nb * 16 + lr) * ROWB
                                                + (kk * 16 + lc * 8) * 2);
                ldmatrix_x4(b0, b1, b2, b3, addr);
                #pragma unroll
                for (int mi = 0; mi < 2; mi++) {
                    mma_bf16(acc[mi][nb * 2],     a[mi], b0, b2);
                    mma_bf16(acc[mi][nb * 2 + 1], a[mi], b1, b3);
                }
            }
        }
        __syncthreads();
    }

    // --- epilogue ---
    int mrow = m0 + wm * 32;
    int ncol = n0 + wn * 64;
    int tr = lane >> 2, tc = (lane & 3) * 2;
    #pragma unroll
    for (int mi = 0; mi < 2; mi++) {
        #pragma unroll
        for (int ni = 0; ni < 8; ni++) {
            #pragma unroll
            for (int h = 0; h < 2; h++) {
                int row = mrow + mi * 16 + tr + h * 8;
                int col = ncol + ni * 8 + tc;
                #pragma unroll
                for (int q = 0; q < 2; q++) {
                    int cq = col + q;
                    if (cq < N) {
                        float v = acc[mi][ni][h * 2 + q];
                        if (bias) v += bias[cq];
                        if (res)  v += res[(size_t)row * ldc + cq];
                        if (act)  v = v * 0.5f * (1.0f + erff(v * 0.70710678118654752f));
                        if (Cf)   Cf[(size_t)row * ldc + cq] = v;
                        else      Cbf[(size_t)row * ldc + cq] = __float2bfloat16(v);
                    }
                }
            }
        }
    }
}

// ---------------- attention (fp32 SIMT) ----------------
__global__ void attn_scores_kernel(const float* __restrict__ qkv,
                                   float* __restrict__ att) {
    int k0 = blockIdx.x * 64;
    int q0 = blockIdx.y * 64;
    if (k0 > q0 + 63) return;
    int bh = blockIdx.z, b = bh / HH, h = bh - b * HH;
    const float* Q  = qkv + (size_t)b * SS * D3 + (size_t)h * DH;
    const float* Kp = qkv + (size_t)b * SS * D3 + DD + (size_t)h * DH;
    float* Cp = att + (size_t)bh * SS * SS;
    __shared__ float Qs[64][17];
    __shared__ float Ks[64][17];
    int t = threadIdx.x, tx = t & 15, ty = t >> 4;
    float acc[4][4] = {};
    for (int kt = 0; kt < DH; kt += 16) {
        #pragma unroll
        for (int e = 0; e < 4; e++) {
            int idx = t + e * 256;
            int r = idx >> 4, kk = idx & 15;
            Qs[r][kk] = Q [(size_t)(q0 + r) * D3 + kt + kk];
            Ks[r][kk] = Kp[(size_t)(k0 + r) * D3 + kt + kk];
        }
        __syncthreads();
        #pragma unroll
        for (int k = 0; k < 16; k++) {
            float a[4], bv[4];
            #pragma unroll
            for (int i = 0; i < 4; i++) a[i] = Qs[ty * 4 + i][k];
            #pragma unroll
            for (int j = 0; j < 4; j++) bv[j] = Ks[tx * 4 + j][k];
            #pragma unroll
            for (int i = 0; i < 4; i++)
                #pragma unroll
                for (int j = 0; j < 4; j++)
                    acc[i][j] += a[i] * bv[j];
        }
        __syncthreads();
    }
    const float scale = 1.0f / sqrtf(768.0f);
    #pragma unroll
    for (int i = 0; i < 4; i++)
        #pragma unroll
        for (int j = 0; j < 4; j++)
            Cp[(size_t)(q0 + ty * 4 + i) * SS + k0 + tx * 4 + j] = acc[i][j] * scale;
}

__global__ void softmax_causal_kernel(float* __restrict__ att) {
    int gid = blockIdx.x;
    int bh = gid >> 10, q = gid & 1023;
    float* p = att + (size_t)bh * SS * SS + (size_t)q * SS;
    int t = threadIdx.x;
    float v[4];
    float m = -INFINITY;
    #pragma unroll
    for (int i = 0; i < 4; i++) {
        int idx = t + i * 256;
        v[i] = (idx <= q) ? p[idx] : -INFINITY;
        m = fmaxf(m, v[i]);
    }
    m = blockReduceMax(m);
    float s = 0.f;
    #pragma unroll
    for (int i = 0; i < 4; i++) {
        int idx = t + i * 256;
        if (idx <= q) { v[i] = expf(v[i] - m); s += v[i]; }
        else v[i] = 0.f;
    }
    s = blockReduceSum(s);
    float inv = 1.0f / s;
    #pragma unroll
    for (int i = 0; i < 4; i++) p[t + i * 256] = v[i] * inv;
}

__global__ void attn_av_kernel(const float* __restrict__ att,
                               const float* __restrict__ qkv,
                               __nv_bfloat16* __restrict__ o) {
    int q0 = blockIdx.x * 64;
    int bh = blockIdx.y, b = bh / HH, h = bh - b * HH;
    const float* A  = att + (size_t)bh * SS * SS;
    const float* Vv = qkv + (size_t)b * SS * D3 + 2 * DD + (size_t)h * DH;
    __nv_bfloat16* Cp = o + (size_t)b * SS * DD + (size_t)h * DH;
    __shared__ float As[16][68];
    __shared__ float Bs[16][68];
    int t = threadIdx.x, tx = t & 15, ty = t >> 4;
    float acc[4][4] = {};
    int kend = q0 + 64;
    for (int k0 = 0; k0 < kend; k0 += 16) {
        #pragma unroll
        for (int e = 0; e < 4; e++) {
            int idx = t + e * 256;
            int r = idx >> 4, kk = idx & 15;
            As[kk][r] = A[(size_t)(q0 + r) * SS + k0 + kk];
            int kk2 = idx >> 6, n = idx & 63;
            Bs[kk2][n] = Vv[(size_t)(k0 + kk2) * D3 + n];
        }
        __syncthreads();
        #pragma unroll
        for (int k = 0; k < 16; k++) {
            float a[4], bv[4];
            #pragma unroll
            for (int i = 0; i < 4; i++) a[i] = As[k][ty * 4 + i];
            #pragma unroll
            for (int j = 0; j < 4; j++) bv[j] = Bs[k][tx * 4 + j];
            #pragma unroll
            for (int i = 0; i < 4; i++)
                #pragma unroll
                for (int j = 0; j < 4; j++)
                    acc[i][j] += a[i] * bv[j];
        }
        __syncthreads();
    }
    #pragma unroll
    for (int i = 0; i < 4; i++)
        #pragma unroll
        for (int j = 0; j < 4; j++)
            Cp[(size_t)(q0 + ty * 4 + i) * DD + tx * 4 + j] = __float2bfloat16(acc[i][j]);
}

// ---- log_softmax over V in-place + second log_softmax picked value --------
__global__ void logsoftmax_loss_kernel(float* __restrict__ logits,
                                       const int* __restrict__ target,
                                       float* __restrict__ picked) {
    int row = blockIdx.x;
    float* x = logits + (size_t)row * VV;
    int t = threadIdx.x;
    float m = -INFINITY;
    for (int i = t; i < VV; i += 256) m = fmaxf(m, x[i]);
    m = blockReduceMax(m);
    float s = 0.f;
    for (int i = t; i < VV; i += 256) s += expf(x[i] - m);
    s = blockReduceSum(s);
    float ls = logf(s);
    float m2 = -ls;
    float s2 = 0.f;
    for (int i = t; i < VV; i += 256) {
        float lp = x[i] - m - ls;
        x[i] = lp;
        s2 += expf(lp - m2);
    }
    s2 = blockReduceSum(s2);
    if (t == 0) {
        int tgt = target[row];
        picked[row] = x[tgt] - m2 - logf(s2);
    }
}

__global__ void finalize_loss_kernel(const float* __restrict__ picked,
                                     float* __restrict__ out) {
    float s = 0.f;
    for (int i = threadIdx.x; i < MR; i += 256) s += picked[i];
    s = blockReduceSum(s);
    if (threadIdx.x == 0) out[(size_t)MR * VV] = -s * (1.0f / (float)MR);
}

// ---------------- host orchestration ----------------
extern "C" void kernel_launch(void* const* d_in, const int* in_sizes, int n_in,
                              void* d_out, int out_size) {
    const int*   tokens = (const int*)  d_in[0];
    const int*   target = (const int*)  d_in[1];
    const float* wte    = (const float*)d_in[2];
    const float* wpe    = (const float*)d_in[3];
    const float* ln1_g  = (const float*)d_in[4];
    const float* ln1_b  = (const float*)d_in[5];
    const float* qkv_w  = (const float*)d_in[6];
    const float* qkv_b  = (const float*)d_in[7];
    const float* proj_w = (const float*)d_in[8];
    const float* proj_b = (const float*)d_in[9];
    const float* ln2_g  = (const float*)d_in[10];
    const float* ln2_b  = (const float*)d_in[11];
    const float* fc1_w  = (const float*)d_in[12];
    const float* fc1_b  = (const float*)d_in[13];
    const float* fc2_w  = (const float*)d_in[14];
    const float* fc2_b  = (const float*)d_in[15];
    const float* lnf_g  = (const float*)d_in[16];
    const float* lnf_b  = (const float*)d_in[17];
    float* out = (float*)d_out;

    float *gx, *gqkv, *gatt, *gpicked;
    __nv_bfloat16 *ghb, *gob, *gffb, *gwteb, *gqkvT, *gprojT, *gfc1T, *gfc2T;
    cudaGetSymbolAddress((void**)&gx,     g_x);
    cudaGetSymbolAddress((void**)&gqkv,   g_qkv);
    cudaGetSymbolAddress((void**)&gatt,   g_att);
    cudaGetSymbolAddress((void**)&gpicked,g_picked);
    cudaGetSymbolAddress((void**)&ghb,    g_hb);
    cudaGetSymbolAddress((void**)&gob,    g_ob);
    cudaGetSymbolAddress((void**)&gffb,   g_ffb);
    cudaGetSymbolAddress((void**)&gwteb,  g_wteb);
    cudaGetSymbolAddress((void**)&gqkvT,  g_qkvT);
    cudaGetSymbolAddress((void**)&gprojT, g_projT);
    cudaGetSymbolAddress((void**)&gfc1T,  g_fc1T);
    cudaGetSymbolAddress((void**)&gfc2T,  g_fc2T);

    // --- weight prep (bf16, transposed to [N,K]) ---
    {
        long n = (long)VV * DD;
        convert_bf16_kernel<<<(int)((n + 255) / 256), 256>>>(wte, gwteb, n);
    }
    dim3 tb(32, 8);
    transpose_to_bf16<<<dim3(D3 / 32,  DD / 32,  LL), tb>>>(qkv_w,  gqkvT,  DD,  D3);
    transpose_to_bf16<<<dim3(DD / 32,  DD / 32,  LL), tb>>>(proj_w, gprojT, DD,  DD);
    transpose_to_bf16<<<dim3(FF_ / 32, DD / 32,  LL), tb>>>(fc1_w,  gfc1T,  DD,  FF_);
    transpose_to_bf16<<<dim3(DD / 32,  FF_ / 32, LL), tb>>>(fc2_w,  gfc2T,  FF_, DD);

    embed_kernel<<<(MR * DD + 255) / 256, 256>>>(tokens, wte, wpe, gx);

    for (int l = 0; l < LL; l++) {
        layernorm_kernel<<<MR, 256>>>(gx, ln1_g + (size_t)l * DD, ln1_b + (size_t)l * DD, ghb);

        // qkv: [2048,768] @ [2304,768]^T -> fp32 g_qkv (+bias)
        gemm_mma_kernel<<<dim3(MR / GBM, D3 / GBN), 256>>>(
            ghb, gqkvT + (size_t)l * DD * D3, gqkv, nullptr,
            qkv_b + (size_t)l * D3, nullptr, D3, DD, D3, 0);

        attn_scores_kernel<<<dim3(SS / 64, SS / 64, BB * HH), 256>>>(gqkv, gatt);
        softmax_causal_kernel<<<BB * HH * SS, 256>>>(gatt);
        attn_av_kernel<<<dim3(SS / 64, BB * HH), 256>>>(gatt, gqkv, gob);

        // proj: +bias +residual -> fp32 g_x
        gemm_mma_kernel<<<dim3(MR / GBM, DD / GBN), 256>>>(
            gob, gprojT + (size_t)l * DD * DD, gx, nullptr,
            proj_b + (size_t)l * DD, gx, DD, DD, DD, 0);

        layernorm_kernel<<<MR, 256>>>(gx, ln2_g + (size_t)l * DD, ln2_b + (size_t)l * DD, ghb);

        // fc1: +bias +gelu -> bf16 g_ffb
        gemm_mma_kernel<<<dim3(MR / GBM, FF_ / GBN), 256>>>(
            ghb, gfc1T + (size_t)l * DD * FF_, nullptr, gffb,
            fc1_b + (size_t)l * FF_, nullptr, FF_, DD, FF_, 1);

        // fc2: +bias +residual -> fp32 g_x
        gemm_mma_kernel<<<dim3(MR / GBM, DD / GBN), 256>>>(
            gffb, gfc2T + (size_t)l * FF_ * DD, gx, nullptr,
            fc2_b + (size_t)l * DD, gx, DD, FF_, DD, 0);
    }

    layernorm_kernel<<<MR, 256>>>(gx, lnf_g, lnf_b, ghb);

    // logits: [2048,768] @ [50257,768]^T -> fp32 out
    gemm_mma_kernel<<<dim3(MR / GBM, (VV + GBN - 1) / GBN), 256>>>(
        ghb, gwteb, out, nullptr, nullptr, nullptr, VV, DD, VV, 0);

    logsoftmax_loss_kernel<<<MR, 256>>>(out, target, gpicked);
    finalize_loss_kernel<<<1, 256>>>(gpicked, out);
}

// round 4
// speedup vs baseline: 4.1241x; 1.5066x over previous
#include <cuda_runtime.h>
#include <cuda_bf16.h>
#include <math.h>
#include <stdint.h>

// ---------------- problem constants ----------------
#define BB   2
#define SS   1024
#define DD   768
#define HH   12
#define DH   64
#define FF_  3072
#define LL   12
#define VV   50257
#define MR   2048          // B*S rows
#define D3   2304          // 3*D

// ---------------- scratch (static device memory) ----------------
__device__ float g_x   [MR * DD];              // residual stream (fp32)
__device__ float g_picked[MR];

__device__ __nv_bfloat16 g_hb  [MR * DD];      // LN outputs (bf16 GEMM input)
__device__ __nv_bfloat16 g_ob  [MR * DD];      // attn output (bf16 GEMM input)
__device__ __nv_bfloat16 g_ffb [MR * FF_];     // GELU output (bf16 GEMM input)
__device__ __nv_bfloat16 g_qkvb[MR * D3];      // qkv projections (bf16)

__device__ __nv_bfloat16 g_wteb [VV * DD];         // wte bf16 [V, D]
__device__ __nv_bfloat16 g_qkvT [LL * DD * D3];    // [L][2304][768]
__device__ __nv_bfloat16 g_projT[LL * DD * DD];    // [L][768][768]
__device__ __nv_bfloat16 g_fc1T [LL * DD * FF_];   // [L][3072][768]
__device__ __nv_bfloat16 g_fc2T [LL * FF_ * DD];   // [L][768][3072]

// ================= low-level helpers (baseline PTX only) =================
__device__ __forceinline__ uint32_t smem_u32(const void* p) {
    uint32_t a;
    asm("{ .reg .u64 t; cvta.to.shared.u64 t, %1; cvt.u32.u64 %0, t; }" : "=r"(a) : "l"(p));
    return a;
}
__device__ __forceinline__ void cp_async16(uint32_t dst, const void* src, bool valid) {
    int sz = valid ? 16 : 0;
    asm volatile("cp.async.cg.shared.global [%0], [%1], 16, %2;"
                 :: "r"(dst), "l"(src), "r"(sz) : "memory");
}
#define CP_COMMIT()  asm volatile("cp.async.commit_group;" ::: "memory")
#define CP_WAIT(n)   asm volatile("cp.async.wait_group %0;" :: "n"(n) : "memory")

__device__ __forceinline__ void ldmatrix_x4(uint32_t& r0, uint32_t& r1,
                                            uint32_t& r2, uint32_t& r3, uint32_t addr) {
    asm volatile("ldmatrix.sync.aligned.m8n8.x4.shared.b16 {%0,%1,%2,%3}, [%4];"
                 : "=r"(r0), "=r"(r1), "=r"(r2), "=r"(r3) : "r"(addr));
}
__device__ __forceinline__ void ldmatrix_x4_trans(uint32_t& r0, uint32_t& r1,
                                                  uint32_t& r2, uint32_t& r3, uint32_t addr) {
    asm volatile("ldmatrix.sync.aligned.m8n8.x4.trans.shared.b16 {%0,%1,%2,%3}, [%4];"
                 : "=r"(r0), "=r"(r1), "=r"(r2), "=r"(r3) : "r"(addr));
}
__device__ __forceinline__ void mma_bf16(float* c, const uint32_t* a,
                                         uint32_t b0, uint32_t b1) {
    asm volatile(
        "mma.sync.aligned.m16n8k16.row.col.f32.bf16.bf16.f32 "
        "{%0,%1,%2,%3}, {%4,%5,%6,%7}, {%8,%9}, {%0,%1,%2,%3};"
        : "+f"(c[0]), "+f"(c[1]), "+f"(c[2]), "+f"(c[3])
        : "r"(a[0]), "r"(a[1]), "r"(a[2]), "r"(a[3]), "r"(b0), "r"(b1));
}
__device__ __forceinline__ uint32_t pack_bf16x2(float lo, float hi) {
    __nv_bfloat162 h = __floats2bfloat162_rn(lo, hi);
    return *reinterpret_cast<uint32_t*>(&h);
}

// ---------------- block reductions ----------------
__device__ __forceinline__ float blockReduceSum(float v) {
    __shared__ float sh[32];
    int lane = threadIdx.x & 31, wid = threadIdx.x >> 5;
    #pragma unroll
    for (int o = 16; o; o >>= 1) v += __shfl_xor_sync(0xffffffffu, v, o);
    __syncthreads();
    if (lane == 0) sh[wid] = v;
    __syncthreads();
    float r = (lane < (int)(blockDim.x >> 5)) ? sh[lane] : 0.f;
    if (wid == 0) {
        #pragma unroll
        for (int o = 16; o; o >>= 1) r += __shfl_xor_sync(0xffffffffu, r, o);
        if (lane == 0) sh[0] = r;
    }
    __syncthreads();
    return sh[0];
}

// ---------------- weight prep ----------------
__global__ void transpose_to_bf16(const float* __restrict__ src,
                                  __nv_bfloat16* __restrict__ dst,
                                  int K, int N) {
    __shared__ float tile[32][33];
    const float* s = src + (size_t)blockIdx.z * K * N;
    __nv_bfloat16* d = dst + (size_t)blockIdx.z * K * N;
    int n0 = blockIdx.x * 32, k0 = blockIdx.y * 32;
    int tx = threadIdx.x, ty = threadIdx.y;  // 32 x 8
    #pragma unroll
    for (int i = 0; i < 32; i += 8)
        tile[ty + i][tx] = s[(size_t)(k0 + ty + i) * N + n0 + tx];
    __syncthreads();
    #pragma unroll
    for (int i = 0; i < 32; i += 8)
        d[(size_t)(n0 + ty + i) * K + k0 + tx] = __float2bfloat16(tile[tx][ty + i]);
}

__global__ void convert_bf16_kernel(const float* __restrict__ src,
                                    __nv_bfloat16* __restrict__ dst, long n) {
    long i = (long)blockIdx.x * blockDim.x + threadIdx.x;
    if (i < n) dst[i] = __float2bfloat16(src[i]);
}

// ---------------- embedding ----------------
__global__ void embed_kernel(const int* __restrict__ tokens,
                             const float* __restrict__ wte,
                             const float* __restrict__ wpe,
                             float* __restrict__ x) {
    int i = blockIdx.x * blockDim.x + threadIdx.x;
    if (i >= MR * DD) return;
    int row = i / DD, d = i - row * DD;
    int s = row & (SS - 1);
    x[i] = wte[(size_t)tokens[row] * DD + d] + wpe[(size_t)s * DD + d];
}

// ---------------- layernorm -> bf16 ----------------
__global__ void layernorm_kernel(const float* __restrict__ in,
                                 const float* __restrict__ g,
                                 const float* __restrict__ b,
                                 __nv_bfloat16* __restrict__ out) {
    int row = blockIdx.x;
    const float* x = in + (size_t)row * DD;
    int t = threadIdx.x;
    float v0 = x[t], v1 = x[t + 256], v2 = x[t + 512];
    float s = blockReduceSum(v0 + v1 + v2);
    float mu = s * (1.0f / 768.0f);
    float d0 = v0 - mu, d1 = v1 - mu, d2 = v2 - mu;
    float q = blockReduceSum(d0 * d0 + d1 * d1 + d2 * d2);
    float rstd = rsqrtf(q * (1.0f / 768.0f) + 1e-5f);
    __nv_bfloat16* o = out + (size_t)row * DD;
    o[t]       = __float2bfloat16(d0 * rstd * g[t]       + b[t]);
    o[t + 256] = __float2bfloat16(d1 * rstd * g[t + 256] + b[t + 256]);
    o[t + 512] = __float2bfloat16(d2 * rstd * g[t + 512] + b[t + 512]);
}

// ================= mma.sync NT GEMM (as validated in R3) =================
#define GBM 128
#define GBN 128
#define GBK 32
#define ROWB 80
#define ABUF 10240
#define BUFS 20480

__global__ __launch_bounds__(256, 1)
void gemm_mma_kernel(const __nv_bfloat16* __restrict__ A,
                     const __nv_bfloat16* __restrict__ B,
                     float* __restrict__ Cf,
                     __nv_bfloat16* __restrict__ Cbf,
                     const float* __restrict__ bias,
                     const float* __restrict__ res,
                     int N, int K, int ldc, int act) {
    __shared__ __align__(128) uint8_t sm[2 * BUFS];
    uint32_t sbase = smem_u32(sm);
    int tid = threadIdx.x;
    int m0 = blockIdx.x * GBM, n0 = blockIdx.y * GBN;
    int nk = K / GBK;

    auto issue = [&](int c) {
        int k0 = c * GBK;
        uint32_t dA = sbase + (c & 1) * BUFS;
        uint32_t dB = dA + ABUF;
        #pragma unroll
        for (int e = 0; e < 2; e++) {
            int idx = tid + e * 256;
            int r = idx >> 2, cc = idx & 3;
            cp_async16(dA + r * ROWB + cc * 16,
                       A + (size_t)(m0 + r) * K + k0 + cc * 8, true);
            int gn = n0 + r;
            cp_async16(dB + r * ROWB + cc * 16,
                       B + (size_t)gn * K + k0 + cc * 8, gn < N);
        }
        CP_COMMIT();
    };

    int warp = tid >> 5, lane = tid & 31;
    int wm = warp >> 1, wn = warp & 1;
    int lr = lane & 15, lc = lane >> 4;
    float acc[2][8][4];
    #pragma unroll
    for (int i = 0; i < 2; i++)
        #pragma unroll
        for (int j = 0; j < 8; j++)
            #pragma unroll
            for (int q = 0; q < 4; q++) acc[i][j][q] = 0.f;

    issue(0);
    for (int c = 0; c < nk; c++) {
        if (c + 1 < nk) { issue(c + 1); CP_WAIT(1); }
        else            { CP_WAIT(0); }
        __syncthreads();
        uint32_t aB = sbase + (c & 1) * BUFS;
        uint32_t bB = aB + ABUF;
        #pragma unroll
        for (int kk = 0; kk < 2; kk++) {
            uint32_t a[2][4];
            #pragma unroll
            for (int mi = 0; mi < 2; mi++) {
                uint32_t addr = aB + (uint32_t)((wm * 32 + mi * 16 + lr) * ROWB
                                                + (kk * 16 + lc * 8) * 2);
                ldmatrix_x4(a[mi][0], a[mi][1], a[mi][2], a[mi][3], addr);
            }
            #pragma unroll
            for (int nb = 0; nb < 4; nb++) {
                uint32_t b0, b1, b2, b3;
                uint32_t addr = bB + (uint32_t)((wn * 64 + nb * 16 + lr) * ROWB
                                                + (kk * 16 + lc * 8) * 2);
                ldmatrix_x4(b0, b1, b2, b3, addr);
                #pragma unroll
                for (int mi = 0; mi < 2; mi++) {
                    mma_bf16(acc[mi][nb * 2],     a[mi], b0, b2);
                    mma_bf16(acc[mi][nb * 2 + 1], a[mi], b1, b3);
                }
            }
        }
        __syncthreads();
    }

    int mrow = m0 + wm * 32;
    int ncol = n0 + wn * 64;
    int tr = lane >> 2, tc = (lane & 3) * 2;
    #pragma unroll
    for (int mi = 0; mi < 2; mi++) {
        #pragma unroll
        for (int ni = 0; ni < 8; ni++) {
            #pragma unroll
            for (int h = 0; h < 2; h++) {
                int row = mrow + mi * 16 + tr + h * 8;
                int col = ncol + ni * 8 + tc;
                #pragma unroll
                for (int q = 0; q < 2; q++) {
                    int cq = col + q;
                    if (cq < N) {
                        float v = acc[mi][ni][h * 2 + q];
                        if (bias) v += bias[cq];
                        if (res)  v += res[(size_t)row * ldc + cq];
                        if (act)  v = v * 0.5f * (1.0f + erff(v * 0.70710678118654752f));
                        if (Cf)   Cf[(size_t)row * ldc + cq] = v;
                        else      Cbf[(size_t)row * ldc + cq] = __float2bfloat16(v);
                    }
                }
            }
        }
    }
}

// ================= fused flash attention (bf16 tensor cores) =================
// Per CTA: one (b,h) and 128 q-rows. 256 thr = 8 warps, warp = 16 q-rows.
// kv tiles of 64, causal, online softmax fp32, scale 1/sqrt(768).
#define FQROWB 144                 // 128B data + 16B pad
#define FQ_OFF 0                   // Q: 128 * 144 = 18432
#define FK_OFF 18432               // K[2]: 2 * 64 * 144
#define FV_OFF 36864               // V[2]: 2 * 64 * 144
#define FSMEM  55296

__global__ __launch_bounds__(256, 1)
void flash_attn_kernel(const __nv_bfloat16* __restrict__ qkv,
                       __nv_bfloat16* __restrict__ o) {
    extern __shared__ __align__(128) uint8_t fsm[];
    uint32_t sbase = smem_u32(fsm);
    int tid = threadIdx.x;
    int q0 = blockIdx.x * 128;
    int bh = blockIdx.y, b = bh / HH, h = bh - b * HH;
    const size_t rowbase = (size_t)b * SS * D3;
    const int qoff = h * DH, koff = DD + h * DH, voff = 2 * DD + h * DH;

    // ---- async loads ----
    auto issue_q = [&]() {
        #pragma unroll
        for (int e = 0; e < 4; e++) {
            int idx = tid + e * 256;           // 1024 chunks
            int r = idx >> 3, c = idx & 7;
            cp_async16(sbase + FQ_OFF + r * FQROWB + c * 16,
                       qkv + rowbase + (size_t)(q0 + r) * D3 + qoff + c * 8, true);
        }
        CP_COMMIT();
    };
    auto issue_kv = [&](int t) {
        int kv0 = t * 64;
        uint32_t kd = sbase + FK_OFF + (t & 1) * (64 * FQROWB);
        uint32_t vd = sbase + FV_OFF + (t & 1) * (64 * FQROWB);
        #pragma unroll
        for (int e = 0; e < 2; e++) {
            int idx = tid + e * 256;           // 512 chunks each
            int r = idx >> 3, c = idx & 7;
            const size_t g = rowbase + (size_t)(kv0 + r) * D3;
            cp_async16(kd + r * FQROWB + c * 16, qkv + g + koff + c * 8, true);
            cp_async16(vd + r * FQROWB + c * 16, qkv + g + voff + c * 8, true);
        }
        CP_COMMIT();
    };

    int warp = tid >> 5, lane = tid & 31;
    int lr = lane & 15, lc = lane >> 4;
    int tr = lane >> 2, qd = lane & 3;
    int wq = q0 + warp * 16;

    float of[8][4];
    #pragma unroll
    for (int i = 0; i < 8; i++)
        #pragma unroll
        for (int j = 0; j < 4; j++) of[i][j] = 0.f;
    float m0r = -INFINITY, m1r = -INFINITY, l0r = 0.f, l1r = 0.f;

    int nt = q0 / 64 + 2;
    issue_q();
    issue_kv(0);

    const float sc = 0.03608439182435161f;  // 1/sqrt(768)

    for (int t = 0; t < nt; t++) {
        if (t + 1 < nt) { issue_kv(t + 1); CP_WAIT(1); }
        else            { CP_WAIT(0); }
        __syncthreads();
        int kv0 = t * 64;
        uint32_t kB = sbase + FK_OFF + (t & 1) * (64 * FQROWB);
        uint32_t vB = sbase + FV_OFF + (t & 1) * (64 * FQROWB);

        // ---- S = Q K^T ----
        float sf[8][4];
        #pragma unroll
        for (int i = 0; i < 8; i++)
            #pragma unroll
            for (int j = 0; j < 4; j++) sf[i][j] = 0.f;
        #pragma unroll
        for (int ks = 0; ks < 4; ks++) {
            uint32_t aq[4];
            uint32_t qa = sbase + FQ_OFF + (uint32_t)((warp * 16 + lr) * FQROWB
                                                      + (ks * 16 + lc * 8) * 2);
            ldmatrix_x4(aq[0], aq[1], aq[2], aq[3], qa);
            #pragma unroll
            for (int nb2 = 0; nb2 < 4; nb2++) {
                uint32_t b0, b1, b2, b3;
                uint32_t ka = kB + (uint32_t)((nb2 * 16 + lr) * FQROWB
                                              + (ks * 16 + lc * 8) * 2);
                ldmatrix_x4(b0, b1, b2, b3, ka);
                mma_bf16(sf[nb2 * 2],     aq, b0, b2);
                mma_bf16(sf[nb2 * 2 + 1], aq, b1, b3);
            }
        }
        // scale + causal mask
        #pragma unroll
        for (int i = 0; i < 8; i++)
            #pragma unroll
            for (int j = 0; j < 4; j++) sf[i][j] *= sc;
        if (kv0 + 63 > wq) {
            #pragma unroll
            for (int nb = 0; nb < 8; nb++) {
                #pragma unroll
                for (int j = 0; j < 4; j++) {
                    int col = kv0 + nb * 8 + qd * 2 + (j & 1);
                    int row = wq + tr + (j >> 1) * 8;
                    if (col > row) sf[nb][j] = -INFINITY;
                }
            }
        }
        // row maxima (rows tr and tr+8)
        float tm0 = -INFINITY, tm1 = -INFINITY;
        #pragma unroll
        for (int nb = 0; nb < 8; nb++) {
            tm0 = fmaxf(tm0, fmaxf(sf[nb][0], sf[nb][1]));
            tm1 = fmaxf(tm1, fmaxf(sf[nb][2], sf[nb][3]));
        }
        tm0 = fmaxf(tm0, __shfl_xor_sync(0xffffffffu, tm0, 1));
        tm0 = fmaxf(tm0, __shfl_xor_sync(0xffffffffu, tm0, 2));
        tm1 = fmaxf(tm1, __shfl_xor_sync(0xffffffffu, tm1, 1));
        tm1 = fmaxf(tm1, __shfl_xor_sync(0xffffffffu, tm1, 2));
        float mn0 = fmaxf(m0r, tm0), mn1 = fmaxf(m1r, tm1);
        float f0 = expf(m0r - mn0), f1 = expf(m1r - mn1);
        m0r = mn0; m1r = mn1;
        // p = exp(s - m), row sums
        float rs0 = 0.f, rs1 = 0.f;
        #pragma unroll
        for (int nb = 0; nb < 8; nb++) {
            sf[nb][0] = expf(sf[nb][0] - mn0);
            sf[nb][1] = expf(sf[nb][1] - mn0);
            sf[nb][2] = expf(sf[nb][2] - mn1);
            sf[nb][3] = expf(sf[nb][3] - mn1);
            rs0 += sf[nb][0] + sf[nb][1];
            rs1 += sf[nb][2] + sf[nb][3];
        }
        rs0 += __shfl_xor_sync(0xffffffffu, rs0, 1);
        rs0 += __shfl_xor_sync(0xffffffffu, rs0, 2);
        rs1 += __shfl_xor_sync(0xffffffffu, rs1, 1);
        rs1 += __shfl_xor_sync(0xffffffffu, rs1, 2);
        l0r = l0r * f0 + rs0;
        l1r = l1r * f1 + rs1;
        // rescale O
        #pragma unroll
        for (int nb = 0; nb < 8; nb++) {
            of[nb][0] *= f0; of[nb][1] *= f0;
            of[nb][2] *= f1; of[nb][3] *= f1;
        }
        // ---- O += P V ----
        #pragma unroll
        for (int ks = 0; ks < 4; ks++) {
            uint32_t ap[4];
            ap[0] = pack_bf16x2(sf[2 * ks][0],     sf[2 * ks][1]);
            ap[1] = pack_bf16x2(sf[2 * ks][2],     sf[2 * ks][3]);
            ap[2] = pack_bf16x2(sf[2 * ks + 1][0], sf[2 * ks + 1][1]);
            ap[3] = pack_bf16x2(sf[2 * ks + 1][2], sf[2 * ks + 1][3]);
            #pragma unroll
            for (int nb2 = 0; nb2 < 4; nb2++) {
                int g = lane >> 3;
                int kvr = ks * 16 + (g & 1) * 8 + (lane & 7);
                int dhc = nb2 * 16 + (g >> 1) * 8;
                uint32_t va = vB + (uint32_t)(kvr * FQROWB + dhc * 2);
                uint32_t r0, r1, r2, r3;
                ldmatrix_x4_trans(r0, r1, r2, r3, va);
                mma_bf16(of[nb2 * 2],     ap, r0, r1);
                mma_bf16(of[nb2 * 2 + 1], ap, r2, r3);
            }
        }
        __syncthreads();
    }

    // ---- epilogue ----
    float inv0 = 1.0f / l0r, inv1 = 1.0f / l1r;
    size_t obase = (size_t)b * SS * DD + (size_t)h * DH;
    #pragma unroll
    for (int nb = 0; nb < 8; nb++) {
        int col = nb * 8 + qd * 2;
        int row0 = wq + tr, row1 = row0 + 8;
        __nv_bfloat162 v0 = __floats2bfloat162_rn(of[nb][0] * inv0, of[nb][1] * inv0);
        __nv_bfloat162 v1 = __floats2bfloat162_rn(of[nb][2] * inv1, of[nb][3] * inv1);
        *reinterpret_cast<__nv_bfloat162*>(o + obase + (size_t)row0 * DD + col) = v0;
        *reinterpret_cast<__nv_bfloat162*>(o + obase + (size_t)row1 * DD + col) = v1;
    }
}

// ---- fused online log_softmax + second log_softmax picked value -----------
__global__ void logsoftmax_loss_kernel(float* __restrict__ logits,
                                       const int* __restrict__ target,
                                       float* __restrict__ picked) {
    __shared__ float shm[8], shs[8], bc[2];
    int row = blockIdx.x;
    float* x = logits + (size_t)row * VV;
    int t = threadIdx.x, lane = t & 31, wid = t >> 5;
    // online (m, s) per thread
    float m = -INFINITY, s = 0.f;
    for (int i = t; i < VV; i += 256) {
        float v = x[i];
        float mn = fmaxf(m, v);
        s = s * expf(m - mn) + expf(v - mn);
        m = mn;
    }
    // warp combine
    #pragma unroll
    for (int o = 16; o; o >>= 1) {
        float m2 = __shfl_xor_sync(0xffffffffu, m, o);
        float s2 = __shfl_xor_sync(0xffffffffu, s, o);
        float mn = fmaxf(m, m2);
        s = s * expf(m - mn) + s2 * expf(m2 - mn);
        m = mn;
    }
    if (lane == 0) { shm[wid] = m; shs[wid] = s; }
    __syncthreads();
    if (t == 0) {
        float M = shm[0], S = shs[0];
        #pragma unroll
        for (int i = 1; i < 8; i++) {
            float mn = fmaxf(M, shm[i]);
            S = S * expf(M - mn) + shs[i] * expf(shm[i] - mn);
            M = mn;
        }
        bc[0] = M; bc[1] = logf(S);
    }
    __syncthreads();
    float M = bc[0], ls = bc[1];
    float m2 = -ls;            // exact max of lp values
    float s2 = 0.f;
    for (int i = t; i < VV; i += 256) {
        float lp = x[i] - M - ls;
        x[i] = lp;
        s2 += expf(lp - m2);
    }
    s2 = blockReduceSum(s2);
    if (t == 0) {
        int tgt = target[row];
        picked[row] = x[tgt] - m2 - logf(s2);
    }
}

__global__ void finalize_loss_kernel(const float* __restrict__ picked,
                                     float* __restrict__ out) {
    float s = 0.f;
    for (int i = threadIdx.x; i < MR; i += 256) s += picked[i];
    s = blockReduceSum(s);
    if (threadIdx.x == 0) out[(size_t)MR * VV] = -s * (1.0f / (float)MR);
}

// ---------------- host orchestration ----------------
extern "C" void kernel_launch(void* const* d_in, const int* in_sizes, int n_in,
                              void* d_out, int out_size) {
    const int*   tokens = (const int*)  d_in[0];
    const int*   target = (const int*)  d_in[1];
    const float* wte    = (const float*)d_in[2];
    const float* wpe    = (const float*)d_in[3];
    const float* ln1_g  = (const float*)d_in[4];
    const float* ln1_b  = (const float*)d_in[5];
    const float* qkv_w  = (const float*)d_in[6];
    const float* qkv_b  = (const float*)d_in[7];
    const float* proj_w = (const float*)d_in[8];
    const float* proj_b = (const float*)d_in[9];
    const float* ln2_g  = (const float*)d_in[10];
    const float* ln2_b  = (const float*)d_in[11];
    const float* fc1_w  = (const float*)d_in[12];
    const float* fc1_b  = (const float*)d_in[13];
    const float* fc2_w  = (const float*)d_in[14];
    const float* fc2_b  = (const float*)d_in[15];
    const float* lnf_g  = (const float*)d_in[16];
    const float* lnf_b  = (const float*)d_in[17];
    float* out = (float*)d_out;

    float *gx, *gpicked;
    __nv_bfloat16 *ghb, *gob, *gffb, *gqkvb, *gwteb, *gqkvT, *gprojT, *gfc1T, *gfc2T;
    cudaGetSymbolAddress((void**)&gx,     g_x);
    cudaGetSymbolAddress((void**)&gpicked,g_picked);
    cudaGetSymbolAddress((void**)&ghb,    g_hb);
    cudaGetSymbolAddress((void**)&gob,    g_ob);
    cudaGetSymbolAddress((void**)&gffb,   g_ffb);
    cudaGetSymbolAddress((void**)&gqkvb,  g_qkvb);
    cudaGetSymbolAddress((void**)&gwteb,  g_wteb);
    cudaGetSymbolAddress((void**)&gqkvT,  g_qkvT);
    cudaGetSymbolAddress((void**)&gprojT, g_projT);
    cudaGetSymbolAddress((void**)&gfc1T,  g_fc1T);
    cudaGetSymbolAddress((void**)&gfc2T,  g_fc2T);

    cudaFuncSetAttribute(flash_attn_kernel,
                         cudaFuncAttributeMaxDynamicSharedMemorySize, FSMEM);

    // --- weight prep (bf16, transposed to [N,K]) ---
    {
        long n = (long)VV * DD;
        convert_bf16_kernel<<<(int)((n + 255) / 256), 256>>>(wte, gwteb, n);
    }
    dim3 tb(32, 8);
    transpose_to_bf16<<<dim3(D3 / 32,  DD / 32,  LL), tb>>>(qkv_w,  gqkvT,  DD,  D3);
    transpose_to_bf16<<<dim3(DD / 32,  DD / 32,  LL), tb>>>(proj_w, gprojT, DD,  DD);
    transpose_to_bf16<<<dim3(FF_ / 32, DD / 32,  LL), tb>>>(fc1_w,  gfc1T,  DD,  FF_);
    transpose_to_bf16<<<dim3(DD / 32,  FF_ / 32, LL), tb>>>(fc2_w,  gfc2T,  FF_, DD);

    embed_kernel<<<(MR * DD + 255) / 256, 256>>>(tokens, wte, wpe, gx);

    for (int l = 0; l < LL; l++) {
        layernorm_kernel<<<MR, 256>>>(gx, ln1_g + (size_t)l * DD, ln1_b + (size_t)l * DD, ghb);

        // qkv: -> bf16 g_qkvb (+bias)
        gemm_mma_kernel<<<dim3(MR / GBM, D3 / GBN), 256>>>(
            ghb, gqkvT + (size_t)l * DD * D3, nullptr, gqkvb,
            qkv_b + (size_t)l * D3, nullptr, D3, DD, D3, 0);

        flash_attn_kernel<<<dim3(SS / 128, BB * HH), 256, FSMEM>>>(gqkvb, gob);

        // proj: +bias +residual -> fp32 g_x
        gemm_mma_kernel<<<dim3(MR / GBM, DD / GBN), 256>>>(
            gob, gprojT + (size_t)l * DD * DD, gx, nullptr,
            proj_b + (size_t)l * DD, gx, DD, DD, DD, 0);

        layernorm_kernel<<<MR, 256>>>(gx, ln2_g + (size_t)l * DD, ln2_b + (size_t)l * DD, ghb);

        // fc1: +bias +gelu -> bf16 g_ffb
        gemm_mma_kernel<<<dim3(MR / GBM, FF_ / GBN), 256>>>(
            ghb, gfc1T + (size_t)l * DD * FF_, nullptr, gffb,
            fc1_b + (size_t)l * FF_, nullptr, FF_, DD, FF_, 1);

        // fc2: +bias +residual -> fp32 g_x
        gemm_mma_kernel<<<dim3(MR / GBM, DD / GBN), 256>>>(
            gffb, gfc2T + (size_t)l * FF_ * DD, gx, nullptr,
            fc2_b + (size_t)l * DD, gx, DD, FF_, DD, 0);
    }

    layernorm_kernel<<<MR, 256>>>(gx, lnf_g, lnf_b, ghb);

    // logits: [2048,768] @ [50257,768]^T -> fp32 out
    gemm_mma_kernel<<<dim3(MR / GBM, (VV + GBN - 1) / GBN), 256>>>(
        ghb, gwteb, out, nullptr, nullptr, nullptr, VV, DD, VV, 0);

    logsoftmax_loss_kernel<<<MR, 256>>>(out, target, gpicked);
    finalize_loss_kernel<<<1, 256>>>(gpicked, out);
}

// round 5
// speedup vs baseline: 4.8205x; 1.1689x over previous
#include <cuda_runtime.h>
#include <cuda_bf16.h>
#include <math.h>
#include <stdint.h>

// ---------------- problem constants ----------------
#define BB   2
#define SS   1024
#define DD   768
#define HH   12
#define DH   64
#define FF_  3072
#define LL   12
#define VV   50257
#define MR   2048          // B*S rows
#define D3   2304          // 3*D

// ---------------- scratch (static device memory) ----------------
__device__ float g_x   [MR * DD];              // residual stream (fp32)
__device__ float g_picked[MR];

__device__ __nv_bfloat16 g_hb  [MR * DD];      // LN outputs (bf16 GEMM input)
__device__ __nv_bfloat16 g_ob  [MR * DD];      // attn output (bf16 GEMM input)
__device__ __nv_bfloat16 g_ffb [MR * FF_];     // GELU output (bf16 GEMM input)
__device__ __nv_bfloat16 g_qkvb[MR * D3];      // qkv projections (bf16)

__device__ __nv_bfloat16 g_wteb [VV * DD];         // wte bf16 [V, D]
__device__ __nv_bfloat16 g_qkvT [LL * DD * D3];    // [L][2304][768]
__device__ __nv_bfloat16 g_projT[LL * DD * DD];    // [L][768][768]
__device__ __nv_bfloat16 g_fc1T [LL * DD * FF_];   // [L][3072][768]
__device__ __nv_bfloat16 g_fc2T [LL * FF_ * DD];   // [L][768][3072]

// ================= low-level helpers (baseline PTX only) =================
__device__ __forceinline__ uint32_t smem_u32(const void* p) {
    uint32_t a;
    asm("{ .reg .u64 t; cvta.to.shared.u64 t, %1; cvt.u32.u64 %0, t; }" : "=r"(a) : "l"(p));
    return a;
}
__device__ __forceinline__ void cp_async16(uint32_t dst, const void* src, bool valid) {
    int sz = valid ? 16 : 0;
    asm volatile("cp.async.cg.shared.global [%0], [%1], 16, %2;"
                 :: "r"(dst), "l"(src), "r"(sz) : "memory");
}
#define CP_COMMIT()  asm volatile("cp.async.commit_group;" ::: "memory")
#define CP_WAIT(n)   asm volatile("cp.async.wait_group %0;" :: "n"(n) : "memory")

__device__ __forceinline__ void ldmatrix_x4(uint32_t& r0, uint32_t& r1,
                                            uint32_t& r2, uint32_t& r3, uint32_t addr) {
    asm volatile("ldmatrix.sync.aligned.m8n8.x4.shared.b16 {%0,%1,%2,%3}, [%4];"
                 : "=r"(r0), "=r"(r1), "=r"(r2), "=r"(r3) : "r"(addr));
}
__device__ __forceinline__ void ldmatrix_x4_trans(uint32_t& r0, uint32_t& r1,
                                                  uint32_t& r2, uint32_t& r3, uint32_t addr) {
    asm volatile("ldmatrix.sync.aligned.m8n8.x4.trans.shared.b16 {%0,%1,%2,%3}, [%4];"
                 : "=r"(r0), "=r"(r1), "=r"(r2), "=r"(r3) : "r"(addr));
}
__device__ __forceinline__ void mma_bf16(float* c, const uint32_t* a,
                                         uint32_t b0, uint32_t b1) {
    asm volatile(
        "mma.sync.aligned.m16n8k16.row.col.f32.bf16.bf16.f32 "
        "{%0,%1,%2,%3}, {%4,%5,%6,%7}, {%8,%9}, {%0,%1,%2,%3};"
        : "+f"(c[0]), "+f"(c[1]), "+f"(c[2]), "+f"(c[3])
        : "r"(a[0]), "r"(a[1]), "r"(a[2]), "r"(a[3]), "r"(b0), "r"(b1));
}
__device__ __forceinline__ uint32_t pack_bf16x2(float lo, float hi) {
    __nv_bfloat162 h = __floats2bfloat162_rn(lo, hi);
    return *reinterpret_cast<uint32_t*>(&h);
}

// ---------------- block reductions ----------------
__device__ __forceinline__ float blockReduceSum(float v) {
    __shared__ float sh[32];
    int lane = threadIdx.x & 31, wid = threadIdx.x >> 5;
    #pragma unroll
    for (int o = 16; o; o >>= 1) v += __shfl_xor_sync(0xffffffffu, v, o);
    __syncthreads();
    if (lane == 0) sh[wid] = v;
    __syncthreads();
    float r = (lane < (int)(blockDim.x >> 5)) ? sh[lane] : 0.f;
    if (wid == 0) {
        #pragma unroll
        for (int o = 16; o; o >>= 1) r += __shfl_xor_sync(0xffffffffu, r, o);
        if (lane == 0) sh[0] = r;
    }
    __syncthreads();
    return sh[0];
}

// ---------------- weight prep ----------------
__global__ void transpose_to_bf16(const float* __restrict__ src,
                                  __nv_bfloat16* __restrict__ dst,
                                  int K, int N) {
    __shared__ float tile[32][33];
    const float* s = src + (size_t)blockIdx.z * K * N;
    __nv_bfloat16* d = dst + (size_t)blockIdx.z * K * N;
    int n0 = blockIdx.x * 32, k0 = blockIdx.y * 32;
    int tx = threadIdx.x, ty = threadIdx.y;  // 32 x 8
    #pragma unroll
    for (int i = 0; i < 32; i += 8)
        tile[ty + i][tx] = s[(size_t)(k0 + ty + i) * N + n0 + tx];
    __syncthreads();
    #pragma unroll
    for (int i = 0; i < 32; i += 8)
        d[(size_t)(n0 + ty + i) * K + k0 + tx] = __float2bfloat16(tile[tx][ty + i]);
}

__global__ void convert_bf16_kernel(const float* __restrict__ src,
                                    __nv_bfloat16* __restrict__ dst, long n) {
    long i = (long)blockIdx.x * blockDim.x + threadIdx.x;
    if (i < n) dst[i] = __float2bfloat16(src[i]);
}

// ---------------- embedding ----------------
__global__ void embed_kernel(const int* __restrict__ tokens,
                             const float* __restrict__ wte,
                             const float* __restrict__ wpe,
                             float* __restrict__ x) {
    int i = blockIdx.x * blockDim.x + threadIdx.x;
    if (i >= MR * DD) return;
    int row = i / DD, d = i - row * DD;
    int s = row & (SS - 1);
    x[i] = wte[(size_t)tokens[row] * DD + d] + wpe[(size_t)s * DD + d];
}

// ---------------- layernorm -> bf16 ----------------
__global__ void layernorm_kernel(const float* __restrict__ in,
                                 const float* __restrict__ g,
                                 const float* __restrict__ b,
                                 __nv_bfloat16* __restrict__ out) {
    int row = blockIdx.x;
    const float* x = in + (size_t)row * DD;
    int t = threadIdx.x;
    float v0 = x[t], v1 = x[t + 256], v2 = x[t + 512];
    float s = blockReduceSum(v0 + v1 + v2);
    float mu = s * (1.0f / 768.0f);
    float d0 = v0 - mu, d1 = v1 - mu, d2 = v2 - mu;
    float q = blockReduceSum(d0 * d0 + d1 * d1 + d2 * d2);
    float rstd = rsqrtf(q * (1.0f / 768.0f) + 1e-5f);
    __nv_bfloat16* o = out + (size_t)row * DD;
    o[t]       = __float2bfloat16(d0 * rstd * g[t]       + b[t]);
    o[t + 256] = __float2bfloat16(d1 * rstd * g[t + 256] + b[t + 256]);
    o[t + 512] = __float2bfloat16(d2 * rstd * g[t + 512] + b[t + 512]);
}

// ================= mma.sync NT GEMM, 3-stage pipeline, 2 CTAs/SM =============
#define GBM 128
#define GBN 128
#define GBK 32
#define ROWB 80
#define ABUF 10240
#define BUFS 20480
#define GSMEM (3 * BUFS)   // 61440

__global__ __launch_bounds__(256, 2)
void gemm_mma_kernel(const __nv_bfloat16* __restrict__ A,
                     const __nv_bfloat16* __restrict__ B,
                     float* __restrict__ Cf,
                     __nv_bfloat16* __restrict__ Cbf,
                     const float* __restrict__ bias,
                     const float* __restrict__ res,
                     int N, int K, int ldc, int act) {
    extern __shared__ __align__(128) uint8_t gsm[];
    uint32_t sbase = smem_u32(gsm);
    int tid = threadIdx.x;
    int m0 = blockIdx.x * GBM, n0 = blockIdx.y * GBN;
    int nk = K / GBK;

    auto issue = [&](int c) {
        int k0 = c * GBK;
        int st = c % 3;
        uint32_t dA = sbase + st * BUFS;
        uint32_t dB = dA + ABUF;
        #pragma unroll
        for (int e = 0; e < 2; e++) {
            int idx = tid + e * 256;
            int r = idx >> 2, cc = idx & 3;
            cp_async16(dA + r * ROWB + cc * 16,
                       A + (size_t)(m0 + r) * K + k0 + cc * 8, true);
            int gn = n0 + r;
            cp_async16(dB + r * ROWB + cc * 16,
                       B + (size_t)gn * K + k0 + cc * 8, gn < N);
        }
        CP_COMMIT();
    };

    int warp = tid >> 5, lane = tid & 31;
    int wm = warp >> 1, wn = warp & 1;
    int lr = lane & 15, lc = lane >> 4;
    float acc[2][8][4];
    #pragma unroll
    for (int i = 0; i < 2; i++)
        #pragma unroll
        for (int j = 0; j < 8; j++)
            #pragma unroll
            for (int q = 0; q < 4; q++) acc[i][j][q] = 0.f;

    issue(0);
    if (nk > 1) issue(1);
    for (int c = 0; c < nk; c++) {
        if (c + 2 < nk) { issue(c + 2); CP_WAIT(2); }
        else if (c + 1 < nk) { CP_WAIT(1); }
        else { CP_WAIT(0); }
        __syncthreads();
        uint32_t aB = sbase + (c % 3) * BUFS;
        uint32_t bB = aB + ABUF;
        #pragma unroll
        for (int kk = 0; kk < 2; kk++) {
            uint32_t a[2][4];
            #pragma unroll
            for (int mi = 0; mi < 2; mi++) {
                uint32_t addr = aB + (uint32_t)((wm * 32 + mi * 16 + lr) * ROWB
                                                + (kk * 16 + lc * 8) * 2);
                ldmatrix_x4(a[mi][0], a[mi][1], a[mi][2], a[mi][3], addr);
            }
            #pragma unroll
            for (int nb = 0; nb < 4; nb++) {
                uint32_t b0, b1, b2, b3;
                uint32_t addr = bB + (uint32_t)((wn * 64 + nb * 16 + lr) * ROWB
                                                + (kk * 16 + lc * 8) * 2);
                ldmatrix_x4(b0, b1, b2, b3, addr);
                #pragma unroll
                for (int mi = 0; mi < 2; mi++) {
                    mma_bf16(acc[mi][nb * 2],     a[mi], b0, b2);
                    mma_bf16(acc[mi][nb * 2 + 1], a[mi], b1, b3);
                }
            }
        }
        __syncthreads();
    }

    // --- epilogue (vectorized pair stores when ldc even) ---
    int mrow = m0 + wm * 32;
    int ncol = n0 + wn * 64;
    int tr = lane >> 2, tc = (lane & 3) * 2;
    bool vec = ((ldc & 1) == 0);
    #pragma unroll
    for (int mi = 0; mi < 2; mi++) {
        #pragma unroll
        for (int ni = 0; ni < 8; ni++) {
            #pragma unroll
            for (int h = 0; h < 2; h++) {
                int row = mrow + mi * 16 + tr + h * 8;
                int col = ncol + ni * 8 + tc;
                float v0 = acc[mi][ni][h * 2];
                float v1 = acc[mi][ni][h * 2 + 1];
                if (bias) { v0 += bias[col]; if (col + 1 < N) v1 += bias[col + 1]; }
                if (res) {
                    const float* rp = res + (size_t)row * ldc + col;
                    v0 += rp[0];
                    if (col + 1 < N) v1 += rp[1];
                }
                if (act) {
                    v0 = v0 * 0.5f * (1.0f + erff(v0 * 0.70710678118654752f));
                    v1 = v1 * 0.5f * (1.0f + erff(v1 * 0.70710678118654752f));
                }
                if (vec && col + 1 < N) {
                    if (Cf) *reinterpret_cast<float2*>(Cf + (size_t)row * ldc + col)
                                = make_float2(v0, v1);
                    else    *reinterpret_cast<__nv_bfloat162*>(Cbf + (size_t)row * ldc + col)
                                = __floats2bfloat162_rn(v0, v1);
                } else {
                    if (col < N) {
                        if (Cf) Cf[(size_t)row * ldc + col] = v0;
                        else    Cbf[(size_t)row * ldc + col] = __float2bfloat16(v0);
                    }
                    if (col + 1 < N) {
                        if (Cf) Cf[(size_t)row * ldc + col + 1] = v1;
                        else    Cbf[(size_t)row * ldc + col + 1] = __float2bfloat16(v1);
                    }
                }
            }
        }
    }
}

// ================= fused flash attention (bf16 tensor cores) =================
#define FQROWB 144
#define FQ_OFF 0
#define FK_OFF 18432
#define FV_OFF 36864
#define FSMEM  55296

__global__ __launch_bounds__(256, 1)
void flash_attn_kernel(const __nv_bfloat16* __restrict__ qkv,
                       __nv_bfloat16* __restrict__ o) {
    extern __shared__ __align__(128) uint8_t fsm[];
    uint32_t sbase = smem_u32(fsm);
    int tid = threadIdx.x;
    int q0 = blockIdx.x * 128;
    int bh = blockIdx.y, b = bh / HH, h = bh - b * HH;
    const size_t rowbase = (size_t)b * SS * D3;
    const int qoff = h * DH, koff = DD + h * DH, voff = 2 * DD + h * DH;

    auto issue_q = [&]() {
        #pragma unroll
        for (int e = 0; e < 4; e++) {
            int idx = tid + e * 256;
            int r = idx >> 3, c = idx & 7;
            cp_async16(sbase + FQ_OFF + r * FQROWB + c * 16,
                       qkv + rowbase + (size_t)(q0 + r) * D3 + qoff + c * 8, true);
        }
        CP_COMMIT();
    };
    auto issue_kv = [&](int t) {
        int kv0 = t * 64;
        uint32_t kd = sbase + FK_OFF + (t & 1) * (64 * FQROWB);
        uint32_t vd = sbase + FV_OFF + (t & 1) * (64 * FQROWB);
        #pragma unroll
        for (int e = 0; e < 2; e++) {
            int idx = tid + e * 256;
            int r = idx >> 3, c = idx & 7;
            const size_t g = rowbase + (size_t)(kv0 + r) * D3;
            cp_async16(kd + r * FQROWB + c * 16, qkv + g + koff + c * 8, true);
            cp_async16(vd + r * FQROWB + c * 16, qkv + g + voff + c * 8, true);
        }
        CP_COMMIT();
    };

    int warp = tid >> 5, lane = tid & 31;
    int lr = lane & 15, lc = lane >> 4;
    int tr = lane >> 2, qd = lane & 3;
    int wq = q0 + warp * 16;

    float of[8][4];
    #pragma unroll
    for (int i = 0; i < 8; i++)
        #pragma unroll
        for (int j = 0; j < 4; j++) of[i][j] = 0.f;
    float m0r = -INFINITY, m1r = -INFINITY, l0r = 0.f, l1r = 0.f;

    int nt = q0 / 64 + 2;
    issue_q();
    issue_kv(0);

    const float sc = 0.03608439182435161f;  // 1/sqrt(768)

    for (int t = 0; t < nt; t++) {
        if (t + 1 < nt) { issue_kv(t + 1); CP_WAIT(1); }
        else            { CP_WAIT(0); }
        __syncthreads();
        int kv0 = t * 64;
        uint32_t kB = sbase + FK_OFF + (t & 1) * (64 * FQROWB);
        uint32_t vB = sbase + FV_OFF + (t & 1) * (64 * FQROWB);

        float sf[8][4];
        #pragma unroll
        for (int i = 0; i < 8; i++)
            #pragma unroll
            for (int j = 0; j < 4; j++) sf[i][j] = 0.f;
        #pragma unroll
        for (int ks = 0; ks < 4; ks++) {
            uint32_t aq[4];
            uint32_t qa = sbase + FQ_OFF + (uint32_t)((warp * 16 + lr) * FQROWB
                                                      + (ks * 16 + lc * 8) * 2);
            ldmatrix_x4(aq[0], aq[1], aq[2], aq[3], qa);
            #pragma unroll
            for (int nb2 = 0; nb2 < 4; nb2++) {
                uint32_t b0, b1, b2, b3;
                uint32_t ka = kB + (uint32_t)((nb2 * 16 + lr) * FQROWB
                                              + (ks * 16 + lc * 8) * 2);
                ldmatrix_x4(b0, b1, b2, b3, ka);
                mma_bf16(sf[nb2 * 2],     aq, b0, b2);
                mma_bf16(sf[nb2 * 2 + 1], aq, b1, b3);
            }
        }
        #pragma unroll
        for (int i = 0; i < 8; i++)
            #pragma unroll
            for (int j = 0; j < 4; j++) sf[i][j] *= sc;
        if (kv0 + 63 > wq) {
            #pragma unroll
            for (int nb = 0; nb < 8; nb++) {
                #pragma unroll
                for (int j = 0; j < 4; j++) {
                    int col = kv0 + nb * 8 + qd * 2 + (j & 1);
                    int row = wq + tr + (j >> 1) * 8;
                    if (col > row) sf[nb][j] = -INFINITY;
                }
            }
        }
        float tm0 = -INFINITY, tm1 = -INFINITY;
        #pragma unroll
        for (int nb = 0; nb < 8; nb++) {
            tm0 = fmaxf(tm0, fmaxf(sf[nb][0], sf[nb][1]));
            tm1 = fmaxf(tm1, fmaxf(sf[nb][2], sf[nb][3]));
        }
        tm0 = fmaxf(tm0, __shfl_xor_sync(0xffffffffu, tm0, 1));
        tm0 = fmaxf(tm0, __shfl_xor_sync(0xffffffffu, tm0, 2));
        tm1 = fmaxf(tm1, __shfl_xor_sync(0xffffffffu, tm1, 1));
        tm1 = fmaxf(tm1, __shfl_xor_sync(0xffffffffu, tm1, 2));
        float mn0 = fmaxf(m0r, tm0), mn1 = fmaxf(m1r, tm1);
        float f0 = __expf(m0r - mn0), f1 = __expf(m1r - mn1);
        m0r = mn0; m1r = mn1;
        float rs0 = 0.f, rs1 = 0.f;
        #pragma unroll
        for (int nb = 0; nb < 8; nb++) {
            sf[nb][0] = __expf(sf[nb][0] - mn0);
            sf[nb][1] = __expf(sf[nb][1] - mn0);
            sf[nb][2] = __expf(sf[nb][2] - mn1);
            sf[nb][3] = __expf(sf[nb][3] - mn1);
            rs0 += sf[nb][0] + sf[nb][1];
            rs1 += sf[nb][2] + sf[nb][3];
        }
        rs0 += __shfl_xor_sync(0xffffffffu, rs0, 1);
        rs0 += __shfl_xor_sync(0xffffffffu, rs0, 2);
        rs1 += __shfl_xor_sync(0xffffffffu, rs1, 1);
        rs1 += __shfl_xor_sync(0xffffffffu, rs1, 2);
        l0r = l0r * f0 + rs0;
        l1r = l1r * f1 + rs1;
        #pragma unroll
        for (int nb = 0; nb < 8; nb++) {
            of[nb][0] *= f0; of[nb][1] *= f0;
            of[nb][2] *= f1; of[nb][3] *= f1;
        }
        #pragma unroll
        for (int ks = 0; ks < 4; ks++) {
            uint32_t ap[4];
            ap[0] = pack_bf16x2(sf[2 * ks][0],     sf[2 * ks][1]);
            ap[1] = pack_bf16x2(sf[2 * ks][2],     sf[2 * ks][3]);
            ap[2] = pack_bf16x2(sf[2 * ks + 1][0], sf[2 * ks + 1][1]);
            ap[3] = pack_bf16x2(sf[2 * ks + 1][2], sf[2 * ks + 1][3]);
            #pragma unroll
            for (int nb2 = 0; nb2 < 4; nb2++) {
                int g = lane >> 3;
                int kvr = ks * 16 + (g & 1) * 8 + (lane & 7);
                int dhc = nb2 * 16 + (g >> 1) * 8;
                uint32_t va = vB + (uint32_t)(kvr * FQROWB + dhc * 2);
                uint32_t r0, r1, r2, r3;
                ldmatrix_x4_trans(r0, r1, r2, r3, va);
                mma_bf16(of[nb2 * 2],     ap, r0, r1);
                mma_bf16(of[nb2 * 2 + 1], ap, r2, r3);
            }
        }
        __syncthreads();
    }

    float inv0 = 1.0f / l0r, inv1 = 1.0f / l1r;
    size_t obase = (size_t)b * SS * DD + (size_t)h * DH;
    #pragma unroll
    for (int nb = 0; nb < 8; nb++) {
        int col = nb * 8 + qd * 2;
        int row0 = wq + tr, row1 = row0 + 8;
        __nv_bfloat162 v0 = __floats2bfloat162_rn(of[nb][0] * inv0, of[nb][1] * inv0);
        __nv_bfloat162 v1 = __floats2bfloat162_rn(of[nb][2] * inv1, of[nb][3] * inv1);
        *reinterpret_cast<__nv_bfloat162*>(o + obase + (size_t)row0 * DD + col) = v0;
        *reinterpret_cast<__nv_bfloat162*>(o + obase + (size_t)row1 * DD + col) = v1;
    }
}

// ---- log_softmax over V (online) + loss pick (2nd softmax is exact no-op) --
__global__ void logsoftmax_loss_kernel(float* __restrict__ logits,
                                       const int* __restrict__ target,
                                       float* __restrict__ picked) {
    __shared__ float shm[8], shs[8], bc[2];
    int row = blockIdx.x;
    float* x = logits + (size_t)row * VV;
    int t = threadIdx.x, lane = t & 31, wid = t >> 5;
    float m = -INFINITY, s = 0.f;
    for (int i = t; i < VV; i += 256) {
        float v = x[i];
        float mn = fmaxf(m, v);
        s = s * __expf(m - mn) + __expf(v - mn);
        m = mn;
    }
    #pragma unroll
    for (int o = 16; o; o >>= 1) {
        float m2 = __shfl_xor_sync(0xffffffffu, m, o);
        float s2 = __shfl_xor_sync(0xffffffffu, s, o);
        float mn = fmaxf(m, m2);
        s = s * __expf(m - mn) + s2 * __expf(m2 - mn);
        m = mn;
    }
    if (lane == 0) { shm[wid] = m; shs[wid] = s; }
    __syncthreads();
    if (t == 0) {
        float M = shm[0], S = shs[0];
        #pragma unroll
        for (int i = 1; i < 8; i++) {
            float mn = fmaxf(M, shm[i]);
            S = S * __expf(M - mn) + shs[i] * __expf(shm[i] - mn);
            M = mn;
        }
        bc[0] = M; bc[1] = logf(S);
    }
    __syncthreads();
    float M = bc[0], ls = bc[1];
    int tgt = target[row];
    // Second log_softmax identity: lp - (-ls) - log(sum exp(x-m)) == lp exactly.
    for (int i = t; i < VV; i += 256) {
        float lp = x[i] - M - ls;
        x[i] = lp;
        if (i == tgt) picked[row] = lp;
    }
}

__global__ void finalize_loss_kernel(const float* __restrict__ picked,
                                     float* __restrict__ out) {
    float s = 0.f;
    for (int i = threadIdx.x; i < MR; i += 256) s += picked[i];
    s = blockReduceSum(s);
    if (threadIdx.x == 0) out[(size_t)MR * VV] = -s * (1.0f / (float)MR);
}

// ---------------- host orchestration ----------------
extern "C" void kernel_launch(void* const* d_in, const int* in_sizes, int n_in,
                              void* d_out, int out_size) {
    const int*   tokens = (const int*)  d_in[0];
    const int*   target = (const int*)  d_in[1];
    const float* wte    = (const float*)d_in[2];
    const float* wpe    = (const float*)d_in[3];
    const float* ln1_g  = (const float*)d_in[4];
    const float* ln1_b  = (const float*)d_in[5];
    const float* qkv_w  = (const float*)d_in[6];
    const float* qkv_b  = (const float*)d_in[7];
    const float* proj_w = (const float*)d_in[8];
    const float* proj_b = (const float*)d_in[9];
    const float* ln2_g  = (const float*)d_in[10];
    const float* ln2_b  = (const float*)d_in[11];
    const float* fc1_w  = (const float*)d_in[12];
    const float* fc1_b  = (const float*)d_in[13];
    const float* fc2_w  = (const float*)d_in[14];
    const float* fc2_b  = (const float*)d_in[15];
    const float* lnf_g  = (const float*)d_in[16];
    const float* lnf_b  = (const float*)d_in[17];
    float* out = (float*)d_out;

    float *gx, *gpicked;
    __nv_bfloat16 *ghb, *gob, *gffb, *gqkvb, *gwteb, *gqkvT, *gprojT, *gfc1T, *gfc2T;
    cudaGetSymbolAddress((void**)&gx,     g_x);
    cudaGetSymbolAddress((void**)&gpicked,g_picked);
    cudaGetSymbolAddress((void**)&ghb,    g_hb);
    cudaGetSymbolAddress((void**)&gob,    g_ob);
    cudaGetSymbolAddress((void**)&gffb,   g_ffb);
    cudaGetSymbolAddress((void**)&gqkvb,  g_qkvb);
    cudaGetSymbolAddress((void**)&gwteb,  g_wteb);
    cudaGetSymbolAddress((void**)&gqkvT,  g_qkvT);
    cudaGetSymbolAddress((void**)&gprojT, g_projT);
    cudaGetSymbolAddress((void**)&gfc1T,  g_fc1T);
    cudaGetSymbolAddress((void**)&gfc2T,  g_fc2T);

    cudaFuncSetAttribute(flash_attn_kernel,
                         cudaFuncAttributeMaxDynamicSharedMemorySize, FSMEM);
    cudaFuncSetAttribute(gemm_mma_kernel,
                         cudaFuncAttributeMaxDynamicSharedMemorySize, GSMEM);

    {
        long n = (long)VV * DD;
        convert_bf16_kernel<<<(int)((n + 255) / 256), 256>>>(wte, gwteb, n);
    }
    dim3 tb(32, 8);
    transpose_to_bf16<<<dim3(D3 / 32,  DD / 32,  LL), tb>>>(qkv_w,  gqkvT,  DD,  D3);
    transpose_to_bf16<<<dim3(DD / 32,  DD / 32,  LL), tb>>>(proj_w, gprojT, DD,  DD);
    transpose_to_bf16<<<dim3(FF_ / 32, DD / 32,  LL), tb>>>(fc1_w,  gfc1T,  DD,  FF_);
    transpose_to_bf16<<<dim3(DD / 32,  FF_ / 32, LL), tb>>>(fc2_w,  gfc2T,  FF_, DD);

    embed_kernel<<<(MR * DD + 255) / 256, 256>>>(tokens, wte, wpe, gx);

    for (int l = 0; l < LL; l++) {
        layernorm_kernel<<<MR, 256>>>(gx, ln1_g + (size_t)l * DD, ln1_b + (size_t)l * DD, ghb);

        gemm_mma_kernel<<<dim3(MR / GBM, D3 / GBN), 256, GSMEM>>>(
            ghb, gqkvT + (size_t)l * DD * D3, nullptr, gqkvb,
            qkv_b + (size_t)l * D3, nullptr, D3, DD, D3, 0);

        flash_attn_kernel<<<dim3(SS / 128, BB * HH), 256, FSMEM>>>(gqkvb, gob);

        gemm_mma_kernel<<<dim3(MR / GBM, DD / GBN), 256, GSMEM>>>(
            gob, gprojT + (size_t)l * DD * DD, gx, nullptr,
            proj_b + (size_t)l * DD, gx, DD, DD, DD, 0);

        layernorm_kernel<<<MR, 256>>>(gx, ln2_g + (size_t)l * DD, ln2_b + (size_t)l * DD, ghb);

        gemm_mma_kernel<<<dim3(MR / GBM, FF_ / GBN), 256, GSMEM>>>(
            ghb, gfc1T + (size_t)l * DD * FF_, nullptr, gffb,
            fc1_b + (size_t)l * FF_, nullptr, FF_, DD, FF_, 1);

        gemm_mma_kernel<<<dim3(MR / GBM, DD / GBN), 256, GSMEM>>>(
            gffb, gfc2T + (size_t)l * FF_ * DD, gx, nullptr,
            fc2_b + (size_t)l * DD, gx, DD, FF_, DD, 0);
    }

    layernorm_kernel<<<MR, 256>>>(gx, lnf_g, lnf_b, ghb);

    gemm_mma_kernel<<<dim3(MR / GBM, (VV + GBN - 1) / GBN), 256, GSMEM>>>(
        ghb, gwteb, out, nullptr, nullptr, nullptr, VV, DD, VV, 0);

    logsoftmax_loss_kernel<<<MR, 256>>>(out, target, gpicked);
    finalize_loss_kernel<<<1, 256>>>(gpicked, out);
}

// round 7
// speedup vs baseline: 5.3558x; 1.1111x over previous
#include <cuda_runtime.h>
#include <cuda_bf16.h>
#include <math.h>
#include <stdint.h>

// ---------------- problem constants ----------------
#define BB   2
#define SS   1024
#define DD   768
#define HH   12
#define DH   64
#define FF_  3072
#define LL   12
#define VV   50257
#define MR   2048          // B*S rows
#define D3   2304          // 3*D

// ---------------- scratch (static device memory) ----------------
__device__ float g_x   [MR * DD];              // residual stream (fp32)
__device__ float g_picked[MR];

__device__ __nv_bfloat16 g_hb  [MR * DD];      // LN outputs (bf16 GEMM input)
__device__ __nv_bfloat16 g_ob  [MR * DD];      // attn output (bf16 GEMM input)
__device__ __nv_bfloat16 g_ffb [MR * FF_];     // GELU output (bf16 GEMM input)
__device__ __nv_bfloat16 g_qkvb[MR * D3];      // qkv projections (bf16)

__device__ __nv_bfloat16 g_wteb [VV * DD];         // wte bf16 [V, D]
__device__ __nv_bfloat16 g_qkvT [LL * DD * D3];    // [L][2304][768]
__device__ __nv_bfloat16 g_projT[LL * DD * DD];    // [L][768][768]
__device__ __nv_bfloat16 g_fc1T [LL * DD * FF_];   // [L][3072][768]
__device__ __nv_bfloat16 g_fc2T [LL * FF_ * DD];   // [L][768][3072]

// ================= low-level helpers (baseline PTX only) =================
__device__ __forceinline__ uint32_t smem_u32(const void* p) {
    uint32_t a;
    asm("{ .reg .u64 t; cvta.to.shared.u64 t, %1; cvt.u32.u64 %0, t; }" : "=r"(a) : "l"(p));
    return a;
}
__device__ __forceinline__ void cp_async16(uint32_t dst, const void* src, bool valid) {
    int sz = valid ? 16 : 0;
    asm volatile("cp.async.cg.shared.global [%0], [%1], 16, %2;"
                 :: "r"(dst), "l"(src), "r"(sz) : "memory");
}
#define CP_COMMIT()  asm volatile("cp.async.commit_group;" ::: "memory")
#define CP_WAIT(n)   asm volatile("cp.async.wait_group %0;" :: "n"(n) : "memory")

__device__ __forceinline__ void ldmatrix_x4(uint32_t& r0, uint32_t& r1,
                                            uint32_t& r2, uint32_t& r3, uint32_t addr) {
    asm volatile("ldmatrix.sync.aligned.m8n8.x4.shared.b16 {%0,%1,%2,%3}, [%4];"
                 : "=r"(r0), "=r"(r1), "=r"(r2), "=r"(r3) : "r"(addr));
}
__device__ __forceinline__ void ldmatrix_x4_trans(uint32_t& r0, uint32_t& r1,
                                                  uint32_t& r2, uint32_t& r3, uint32_t addr) {
    asm volatile("ldmatrix.sync.aligned.m8n8.x4.trans.shared.b16 {%0,%1,%2,%3}, [%4];"
                 : "=r"(r0), "=r"(r1), "=r"(r2), "=r"(r3) : "r"(addr));
}
__device__ __forceinline__ void mma_bf16(float* c, const uint32_t* a,
                                         uint32_t b0, uint32_t b1) {
    asm volatile(
        "mma.sync.aligned.m16n8k16.row.col.f32.bf16.bf16.f32 "
        "{%0,%1,%2,%3}, {%4,%5,%6,%7}, {%8,%9}, {%0,%1,%2,%3};"
        : "+f"(c[0]), "+f"(c[1]), "+f"(c[2]), "+f"(c[3])
        : "r"(a[0]), "r"(a[1]), "r"(a[2]), "r"(a[3]), "r"(b0), "r"(b1));
}
__device__ __forceinline__ uint32_t pack_bf16x2(float lo, float hi) {
    __nv_bfloat162 h = __floats2bfloat162_rn(lo, hi);
    return *reinterpret_cast<uint32_t*>(&h);
}

// ---------------- block reductions ----------------
__device__ __forceinline__ float blockReduceSum(float v) {
    __shared__ float sh[32];
    int lane = threadIdx.x & 31, wid = threadIdx.x >> 5;
    #pragma unroll
    for (int o = 16; o; o >>= 1) v += __shfl_xor_sync(0xffffffffu, v, o);
    __syncthreads();
    if (lane == 0) sh[wid] = v;
    __syncthreads();
    float r = (lane < (int)(blockDim.x >> 5)) ? sh[lane] : 0.f;
    if (wid == 0) {
        #pragma unroll
        for (int o = 16; o; o >>= 1) r += __shfl_xor_sync(0xffffffffu, r, o);
        if (lane == 0) sh[0] = r;
    }
    __syncthreads();
    return sh[0];
}

// ---------------- weight prep ----------------
__global__ void transpose_to_bf16(const float* __restrict__ src,
                                  __nv_bfloat16* __restrict__ dst,
                                  int K, int N) {
    __shared__ float tile[32][33];
    const float* s = src + (size_t)blockIdx.z * K * N;
    __nv_bfloat16* d = dst + (size_t)blockIdx.z * K * N;
    int n0 = blockIdx.x * 32, k0 = blockIdx.y * 32;
    int tx = threadIdx.x, ty = threadIdx.y;  // 32 x 8
    #pragma unroll
    for (int i = 0; i < 32; i += 8)
        tile[ty + i][tx] = s[(size_t)(k0 + ty + i) * N + n0 + tx];
    __syncthreads();
    #pragma unroll
    for (int i = 0; i < 32; i += 8)
        d[(size_t)(n0 + ty + i) * K + k0 + tx] = __float2bfloat16(tile[tx][ty + i]);
}

__global__ void convert_bf16_kernel(const float* __restrict__ src,
                                    __nv_bfloat16* __restrict__ dst, long n) {
    long i = (long)blockIdx.x * blockDim.x + threadIdx.x;
    if (i < n) dst[i] = __float2bfloat16(src[i]);
}

// ---------------- embedding ----------------
__global__ void embed_kernel(const int* __restrict__ tokens,
                             const float* __restrict__ wte,
                             const float* __restrict__ wpe,
                             float* __restrict__ x) {
    int i = blockIdx.x * blockDim.x + threadIdx.x;
    if (i >= MR * DD) return;
    int row = i / DD, d = i - row * DD;
    int s = row & (SS - 1);
    x[i] = wte[(size_t)tokens[row] * DD + d] + wpe[(size_t)s * DD + d];
}

// ---------------- layernorm -> bf16 ----------------
__global__ void layernorm_kernel(const float* __restrict__ in,
                                 const float* __restrict__ g,
                                 const float* __restrict__ b,
                                 __nv_bfloat16* __restrict__ out) {
    int row = blockIdx.x;
    const float* x = in + (size_t)row * DD;
    int t = threadIdx.x;
    float v0 = x[t], v1 = x[t + 256], v2 = x[t + 512];
    float s = blockReduceSum(v0 + v1 + v2);
    float mu = s * (1.0f / 768.0f);
    float d0 = v0 - mu, d1 = v1 - mu, d2 = v2 - mu;
    float q = blockReduceSum(d0 * d0 + d1 * d1 + d2 * d2);
    float rstd = rsqrtf(q * (1.0f / 768.0f) + 1e-5f);
    __nv_bfloat16* o = out + (size_t)row * DD;
    o[t]       = __float2bfloat16(d0 * rstd * g[t]       + b[t]);
    o[t + 256] = __float2bfloat16(d1 * rstd * g[t + 256] + b[t + 256]);
    o[t + 512] = __float2bfloat16(d2 * rstd * g[t + 512] + b[t + 512]);
}

// ================= mma.sync NT GEMM, GBK=64, 3-stage, 2 CTAs/SM =============
#define GBM 128
#define GBN 128
#define GBK 64
#define ROWB 144           // 128B data + 16B pad
#define ABUF 18432         // 128 * 144
#define BUFS 36864
#define GSMEM (3 * BUFS)   // 110592

__global__ __launch_bounds__(256, 2)
void gemm_mma_kernel(const __nv_bfloat16* __restrict__ A,
                     const __nv_bfloat16* __restrict__ B,
                     float* __restrict__ Cf,
                     __nv_bfloat16* __restrict__ Cbf,
                     const float* __restrict__ bias,
                     const float* __restrict__ res,
                     int N, int K, int ldc, int act) {
    extern __shared__ __align__(128) uint8_t gsm[];
    uint32_t sbase = smem_u32(gsm);
    int tid = threadIdx.x;
    int m0 = blockIdx.x * GBM, n0 = blockIdx.y * GBN;
    int nk = K / GBK;

    auto issue = [&](int c) {
        int k0 = c * GBK;
        int st = c % 3;
        uint32_t dA = sbase + st * BUFS;
        uint32_t dB = dA + ABUF;
        #pragma unroll
        for (int e = 0; e < 4; e++) {
            int idx = tid + e * 256;           // 1024 chunks per operand
            int r = idx >> 3, cc = idx & 7;
            cp_async16(dA + r * ROWB + cc * 16,
                       A + (size_t)(m0 + r) * K + k0 + cc * 8, true);
            int gn = n0 + r;
            cp_async16(dB + r * ROWB + cc * 16,
                       B + (size_t)gn * K + k0 + cc * 8, gn < N);
        }
        CP_COMMIT();
    };

    int warp = tid >> 5, lane = tid & 31;
    int wm = warp >> 1, wn = warp & 1;
    int lr = lane & 15, lc = lane >> 4;
    float acc[2][8][4];
    #pragma unroll
    for (int i = 0; i < 2; i++)
        #pragma unroll
        for (int j = 0; j < 8; j++)
            #pragma unroll
            for (int q = 0; q < 4; q++) acc[i][j][q] = 0.f;

    issue(0);
    if (nk > 1) issue(1);
    for (int c = 0; c < nk; c++) {
        if (c + 2 < nk) { issue(c + 2); CP_WAIT(2); }
        else if (c + 1 < nk) { CP_WAIT(1); }
        else { CP_WAIT(0); }
        __syncthreads();
        uint32_t aB = sbase + (c % 3) * BUFS;
        uint32_t bB = aB + ABUF;
        #pragma unroll
        for (int kk = 0; kk < 4; kk++) {
            uint32_t a[2][4];
            #pragma unroll
            for (int mi = 0; mi < 2; mi++) {
                uint32_t addr = aB + (uint32_t)((wm * 32 + mi * 16 + lr) * ROWB
                                                + (kk * 16 + lc * 8) * 2);
                ldmatrix_x4(a[mi][0], a[mi][1], a[mi][2], a[mi][3], addr);
            }
            #pragma unroll
            for (int nb = 0; nb < 4; nb++) {
                uint32_t b0, b1, b2, b3;
                uint32_t addr = bB + (uint32_t)((wn * 64 + nb * 16 + lr) * ROWB
                                                + (kk * 16 + lc * 8) * 2);
                ldmatrix_x4(b0, b1, b2, b3, addr);
                #pragma unroll
                for (int mi = 0; mi < 2; mi++) {
                    mma_bf16(acc[mi][nb * 2],     a[mi], b0, b2);
                    mma_bf16(acc[mi][nb * 2 + 1], a[mi], b1, b3);
                }
            }
        }
        __syncthreads();
    }

    // --- epilogue (vectorized pair stores when ldc even) ---
    int mrow = m0 + wm * 32;
    int ncol = n0 + wn * 64;
    int tr = lane >> 2, tc = (lane & 3) * 2;
    bool vec = ((ldc & 1) == 0);
    #pragma unroll
    for (int mi = 0; mi < 2; mi++) {
        #pragma unroll
        for (int ni = 0; ni < 8; ni++) {
            #pragma unroll
            for (int h = 0; h < 2; h++) {
                int row = mrow + mi * 16 + tr + h * 8;
                int col = ncol + ni * 8 + tc;
                float v0 = acc[mi][ni][h * 2];
                float v1 = acc[mi][ni][h * 2 + 1];
                if (bias) { v0 += bias[col]; if (col + 1 < N) v1 += bias[col + 1]; }
                if (res) {
                    const float* rp = res + (size_t)row * ldc + col;
                    v0 += rp[0];
                    if (col + 1 < N) v1 += rp[1];
                }
                if (act) {
                    v0 = v0 * 0.5f * (1.0f + erff(v0 * 0.70710678118654752f));
                    v1 = v1 * 0.5f * (1.0f + erff(v1 * 0.70710678118654752f));
                }
                if (vec && col + 1 < N) {
                    if (Cf) *reinterpret_cast<float2*>(Cf + (size_t)row * ldc + col)
                                = make_float2(v0, v1);
                    else    *reinterpret_cast<__nv_bfloat162*>(Cbf + (size_t)row * ldc + col)
                                = __floats2bfloat162_rn(v0, v1);
                } else {
                    if (col < N) {
                        if (Cf) Cf[(size_t)row * ldc + col] = v0;
                        else    Cbf[(size_t)row * ldc + col] = __float2bfloat16(v0);
                    }
                    if (col + 1 < N) {
                        if (Cf) Cf[(size_t)row * ldc + col + 1] = v1;
                        else    Cbf[(size_t)row * ldc + col + 1] = __float2bfloat16(v1);
                    }
                }
            }
        }
    }
}

// ================= fused flash attention (bf16 tensor cores) =================
#define FQROWB 144
#define FQ_OFF 0
#define FK_OFF 18432
#define FV_OFF 36864
#define FSMEM  55296

__global__ __launch_bounds__(256, 2)
void flash_attn_kernel(const __nv_bfloat16* __restrict__ qkv,
                       __nv_bfloat16* __restrict__ o) {
    extern __shared__ __align__(128) uint8_t fsm[];
    uint32_t sbase = smem_u32(fsm);
    int tid = threadIdx.x;
    int q0 = (gridDim.x - 1 - blockIdx.x) * 128;   // heavy tiles first
    int bh = blockIdx.y, b = bh / HH, h = bh - b * HH;
    const size_t rowbase = (size_t)b * SS * D3;
    const int qoff = h * DH, koff = DD + h * DH, voff = 2 * DD + h * DH;

    auto issue_q = [&]() {
        #pragma unroll
        for (int e = 0; e < 4; e++) {
            int idx = tid + e * 256;
            int r = idx >> 3, c = idx & 7;
            cp_async16(sbase + FQ_OFF + r * FQROWB + c * 16,
                       qkv + rowbase + (size_t)(q0 + r) * D3 + qoff + c * 8, true);
        }
        CP_COMMIT();
    };
    auto issue_kv = [&](int t) {
        int kv0 = t * 64;
        uint32_t kd = sbase + FK_OFF + (t & 1) * (64 * FQROWB);
        uint32_t vd = sbase + FV_OFF + (t & 1) * (64 * FQROWB);
        #pragma unroll
        for (int e = 0; e < 2; e++) {
            int idx = tid + e * 256;
            int r = idx >> 3, c = idx & 7;
            const size_t g = rowbase + (size_t)(kv0 + r) * D3;
            cp_async16(kd + r * FQROWB + c * 16, qkv + g + koff + c * 8, true);
            cp_async16(vd + r * FQROWB + c * 16, qkv + g + voff + c * 8, true);
        }
        CP_COMMIT();
    };

    int warp = tid >> 5, lane = tid & 31;
    int lr = lane & 15, lc = lane >> 4;
    int tr = lane >> 2, qd = lane & 3;
    int wq = q0 + warp * 16;

    float of[8][4];
    #pragma unroll
    for (int i = 0; i < 8; i++)
        #pragma unroll
        for (int j = 0; j < 4; j++) of[i][j] = 0.f;
    float m0r = -INFINITY, m1r = -INFINITY, l0r = 0.f, l1r = 0.f;

    int nt = q0 / 64 + 2;
    issue_q();
    issue_kv(0);

    const float sc = 0.03608439182435161f;  // 1/sqrt(768)

    for (int t = 0; t < nt; t++) {
        if (t + 1 < nt) { issue_kv(t + 1); CP_WAIT(1); }
        else            { CP_WAIT(0); }
        __syncthreads();
        int kv0 = t * 64;
        uint32_t kB = sbase + FK_OFF + (t & 1) * (64 * FQROWB);
        uint32_t vB = sbase + FV_OFF + (t & 1) * (64 * FQROWB);

        float sf[8][4];
        #pragma unroll
        for (int i = 0; i < 8; i++)
            #pragma unroll
            for (int j = 0; j < 4; j++) sf[i][j] = 0.f;
        #pragma unroll
        for (int ks = 0; ks < 4; ks++) {
            uint32_t aq[4];
            uint32_t qa = sbase + FQ_OFF + (uint32_t)((warp * 16 + lr) * FQROWB
                                                      + (ks * 16 + lc * 8) * 2);
            ldmatrix_x4(aq[0], aq[1], aq[2], aq[3], qa);
            #pragma unroll
            for (int nb2 = 0; nb2 < 4; nb2++) {
                uint32_t b0, b1, b2, b3;
                uint32_t ka = kB + (uint32_t)((nb2 * 16 + lr) * FQROWB
                                              + (ks * 16 + lc * 8) * 2);
                ldmatrix_x4(b0, b1, b2, b3, ka);
                mma_bf16(sf[nb2 * 2],     aq, b0, b2);
                mma_bf16(sf[nb2 * 2 + 1], aq, b1, b3);
            }
        }
        #pragma unroll
        for (int i = 0; i < 8; i++)
            #pragma unroll
            for (int j = 0; j < 4; j++) sf[i][j] *= sc;
        if (kv0 + 63 > wq) {
            #pragma unroll
            for (int nb = 0; nb < 8; nb++) {
                #pragma unroll
                for (int j = 0; j < 4; j++) {
                    int col = kv0 + nb * 8 + qd * 2 + (j & 1);
                    int row = wq + tr + (j >> 1) * 8;
                    if (col > row) sf[nb][j] = -INFINITY;
                }
            }
        }
        float tm0 = -INFINITY, tm1 = -INFINITY;
        #pragma unroll
        for (int nb = 0; nb < 8; nb++) {
            tm0 = fmaxf(tm0, fmaxf(sf[nb][0], sf[nb][1]));
            tm1 = fmaxf(tm1, fmaxf(sf[nb][2], sf[nb][3]));
        }
        tm0 = fmaxf(tm0, __shfl_xor_sync(0xffffffffu, tm0, 1));
        tm0 = fmaxf(tm0, __shfl_xor_sync(0xffffffffu, tm0, 2));
        tm1 = fmaxf(tm1, __shfl_xor_sync(0xffffffffu, tm1, 1));
        tm1 = fmaxf(tm1, __shfl_xor_sync(0xffffffffu, tm1, 2));
        float mn0 = fmaxf(m0r, tm0), mn1 = fmaxf(m1r, tm1);
        float f0 = __expf(m0r - mn0), f1 = __expf(m1r - mn1);
        m0r = mn0; m1r = mn1;
        float rs0 = 0.f, rs1 = 0.f;
        #pragma unroll
        for (int nb = 0; nb < 8; nb++) {
            sf[nb][0] = __expf(sf[nb][0] - mn0);
            sf[nb][1] = __expf(sf[nb][1] - mn0);
            sf[nb][2] = __expf(sf[nb][2] - mn1);
            sf[nb][3] = __expf(sf[nb][3] - mn1);
            rs0 += sf[nb][0] + sf[nb][1];
            rs1 += sf[nb][2] + sf[nb][3];
        }
        rs0 += __shfl_xor_sync(0xffffffffu, rs0, 1);
        rs0 += __shfl_xor_sync(0xffffffffu, rs0, 2);
        rs1 += __shfl_xor_sync(0xffffffffu, rs1, 1);
        rs1 += __shfl_xor_sync(0xffffffffu, rs1, 2);
        l0r = l0r * f0 + rs0;
        l1r = l1r * f1 + rs1;
        #pragma unroll
        for (int nb = 0; nb < 8; nb++) {
            of[nb][0] *= f0; of[nb][1] *= f0;
            of[nb][2] *= f1; of[nb][3] *= f1;
        }
        #pragma unroll
        for (int ks = 0; ks < 4; ks++) {
            uint32_t ap[4];
            ap[0] = pack_bf16x2(sf[2 * ks][0],     sf[2 * ks][1]);
            ap[1] = pack_bf16x2(sf[2 * ks][2],     sf[2 * ks][3]);
            ap[2] = pack_bf16x2(sf[2 * ks + 1][0], sf[2 * ks + 1][1]);
            ap[3] = pack_bf16x2(sf[2 * ks + 1][2], sf[2 * ks + 1][3]);
            #pragma unroll
            for (int nb2 = 0; nb2 < 4; nb2++) {
                int g = lane >> 3;
                int kvr = ks * 16 + (g & 1) * 8 + (lane & 7);
                int dhc = nb2 * 16 + (g >> 1) * 8;
                uint32_t va = vB + (uint32_t)(kvr * FQROWB + dhc * 2);
                uint32_t r0, r1, r2, r3;
                ldmatrix_x4_trans(r0, r1, r2, r3, va);
                mma_bf16(of[nb2 * 2],     ap, r0, r1);
                mma_bf16(of[nb2 * 2 + 1], ap, r2, r3);
            }
        }
        __syncthreads();
    }

    float inv0 = 1.0f / l0r, inv1 = 1.0f / l1r;
    size_t obase = (size_t)b * SS * DD + (size_t)h * DH;
    #pragma unroll
    for (int nb = 0; nb < 8; nb++) {
        int col = nb * 8 + qd * 2;
        int row0 = wq + tr, row1 = row0 + 8;
        __nv_bfloat162 v0 = __floats2bfloat162_rn(of[nb][0] * inv0, of[nb][1] * inv0);
        __nv_bfloat162 v1 = __floats2bfloat162_rn(of[nb][2] * inv1, of[nb][3] * inv1);
        *reinterpret_cast<__nv_bfloat162*>(o + obase + (size_t)row0 * DD + col) = v0;
        *reinterpret_cast<__nv_bfloat162*>(o + obase + (size_t)row1 * DD + col) = v1;
    }
}

// ---- log_softmax over V (online, 512 thr, alignment-safe float4) ----------
__global__ __launch_bounds__(512)
void logsoftmax_loss_kernel(float* __restrict__ logits,
                            const int* __restrict__ target,
                            float* __restrict__ picked) {
    __shared__ float shm[16], shs[16], bc[2];
    int row = blockIdx.x;
    float* x = logits + (size_t)row * VV;
    int t = threadIdx.x, lane = t & 31, wid = t >> 5;

    // row base is only 4B-aligned in general; find scalar head to 16B boundary
    int head = (int)(((16 - ((uintptr_t)x & 15)) & 15) >> 2);  // 0..3 floats
    int nvec = (VV - head) >> 2;                                // aligned float4 count
    const float* xv = x + head;

    float m = -INFINITY, s = 0.f;
    for (int i = t; i < head; i += 512) {  // head (<=3)
        float v = x[i];
        float mn = fmaxf(m, v);
        s = s * __expf(m - mn) + __expf(v - mn);
        m = mn;
    }
    for (int i = t; i < nvec; i += 512) {
        float4 v = *reinterpret_cast<const float4*>(xv + i * 4);
        float mx = fmaxf(fmaxf(v.x, v.y), fmaxf(v.z, v.w));
        float mn = fmaxf(m, mx);
        s = s * __expf(m - mn) + __expf(v.x - mn) + __expf(v.y - mn)
            + __expf(v.z - mn) + __expf(v.w - mn);
        m = mn;
    }
    for (int i = head + nvec * 4 + t; i < VV; i += 512) {  // tail (<=3)
        float v = x[i];
        float mn = fmaxf(m, v);
        s = s * __expf(m - mn) + __expf(v - mn);
        m = mn;
    }
    #pragma unroll
    for (int o = 16; o; o >>= 1) {
        float m2 = __shfl_xor_sync(0xffffffffu, m, o);
        float s2 = __shfl_xor_sync(0xffffffffu, s, o);
        float mn = fmaxf(m, m2);
        s = s * __expf(m - mn) + s2 * __expf(m2 - mn);
        m = mn;
    }
    if (lane == 0) { shm[wid] = m; shs[wid] = s; }
    __syncthreads();
    if (t == 0) {
        float M = shm[0], S = shs[0];
        #pragma unroll
        for (int i = 1; i < 16; i++) {
            float mn = fmaxf(M, shm[i]);
            S = S * __expf(M - mn) + shs[i] * __expf(shm[i] - mn);
            M = mn;
        }
        bc[0] = M; bc[1] = logf(S);
    }
    __syncthreads();
    float sub = bc[0] + bc[1];
    int tgt = target[row];
    // Second log_softmax is an exact identity on log_softmax output.
    for (int i = t; i < head; i += 512) {
        float lp = x[i] - sub;
        x[i] = lp;
        if (i == tgt) picked[row] = lp;
    }
    for (int i = t; i < nvec; i += 512) {
        float4 v = *reinterpret_cast<const float4*>(xv + i * 4);
        v.x -= sub; v.y -= sub; v.z -= sub; v.w -= sub;
        *reinterpret_cast<float4*>(const_cast<float*>(xv) + i * 4) = v;
        int base = head + i * 4;
        if (tgt >= base && tgt < base + 4) {
            float pv = (tgt == base) ? v.x : (tgt == base + 1) ? v.y
                     : (tgt == base + 2) ? v.z : v.w;
            picked[row] = pv;
        }
    }
    for (int i = head + nvec * 4 + t; i < VV; i += 512) {
        float lp = x[i] - sub;
        x[i] = lp;
        if (i == tgt) picked[row] = lp;
    }
}

__global__ void finalize_loss_kernel(const float* __restrict__ picked,
                                     float* __restrict__ out) {
    float s = 0.f;
    for (int i = threadIdx.x; i < MR; i += 256) s += picked[i];
    s = blockReduceSum(s);
    if (threadIdx.x == 0) out[(size_t)MR * VV] = -s * (1.0f / (float)MR);
}

// ---------------- host orchestration ----------------
extern "C" void kernel_launch(void* const* d_in, const int* in_sizes, int n_in,
                              void* d_out, int out_size) {
    const int*   tokens = (const int*)  d_in[0];
    const int*   target = (const int*)  d_in[1];
    const float* wte    = (const float*)d_in[2];
    const float* wpe    = (const float*)d_in[3];
    const float* ln1_g  = (const float*)d_in[4];
    const float* ln1_b  = (const float*)d_in[5];
    const float* qkv_w  = (const float*)d_in[6];
    const float* qkv_b  = (const float*)d_in[7];
    const float* proj_w = (const float*)d_in[8];
    const float* proj_b = (const float*)d_in[9];
    const float* ln2_g  = (const float*)d_in[10];
    const float* ln2_b  = (const float*)d_in[11];
    const float* fc1_w  = (const float*)d_in[12];
    const float* fc1_b  = (const float*)d_in[13];
    const float* fc2_w  = (const float*)d_in[14];
    const float* fc2_b  = (const float*)d_in[15];
    const float* lnf_g  = (const float*)d_in[16];
    const float* lnf_b  = (const float*)d_in[17];
    float* out = (float*)d_out;

    float *gx, *gpicked;
    __nv_bfloat16 *ghb, *gob, *gffb, *gqkvb, *gwteb, *gqkvT, *gprojT, *gfc1T, *gfc2T;
    cudaGetSymbolAddress((void**)&gx,     g_x);
    cudaGetSymbolAddress((void**)&gpicked,g_picked);
    cudaGetSymbolAddress((void**)&ghb,    g_hb);
    cudaGetSymbolAddress((void**)&gob,    g_ob);
    cudaGetSymbolAddress((void**)&gffb,   g_ffb);
    cudaGetSymbolAddress((void**)&gqkvb,  g_qkvb);
    cudaGetSymbolAddress((void**)&gwteb,  g_wteb);
    cudaGetSymbolAddress((void**)&gqkvT,  g_qkvT);
    cudaGetSymbolAddress((void**)&gprojT, g_projT);
    cudaGetSymbolAddress((void**)&gfc1T,  g_fc1T);
    cudaGetSymbolAddress((void**)&gfc2T,  g_fc2T);

    cudaFuncSetAttribute(flash_attn_kernel,
                         cudaFuncAttributeMaxDynamicSharedMemorySize, FSMEM);
    cudaFuncSetAttribute(gemm_mma_kernel,
                         cudaFuncAttributeMaxDynamicSharedMemorySize, GSMEM);

    {
        long n = (long)VV * DD;
        convert_bf16_kernel<<<(int)((n + 255) / 256), 256>>>(wte, gwteb, n);
    }
    dim3 tb(32, 8);
    transpose_to_bf16<<<dim3(D3 / 32,  DD / 32,  LL), tb>>>(qkv_w,  gqkvT,  DD,  D3);
    transpose_to_bf16<<<dim3(DD / 32,  DD / 32,  LL), tb>>>(proj_w, gprojT, DD,  DD);
    transpose_to_bf16<<<dim3(FF_ / 32, DD / 32,  LL), tb>>>(fc1_w,  gfc1T,  DD,  FF_);
    transpose_to_bf16<<<dim3(DD / 32,  FF_ / 32, LL), tb>>>(fc2_w,  gfc2T,  FF_, DD);

    embed_kernel<<<(MR * DD + 255) / 256, 256>>>(tokens, wte, wpe, gx);

    for (int l = 0; l < LL; l++) {
        layernorm_kernel<<<MR, 256>>>(gx, ln1_g + (size_t)l * DD, ln1_b + (size_t)l * DD, ghb);

        gemm_mma_kernel<<<dim3(MR / GBM, D3 / GBN), 256, GSMEM>>>(
            ghb, gqkvT + (size_t)l * DD * D3, nullptr, gqkvb,
            qkv_b + (size_t)l * D3, nullptr, D3, DD, D3, 0);

        flash_attn_kernel<<<dim3(SS / 128, BB * HH), 256, FSMEM>>>(gqkvb, gob);

        gemm_mma_kernel<<<dim3(MR / GBM, DD / GBN), 256, GSMEM>>>(
            gob, gprojT + (size_t)l * DD * DD, gx, nullptr,
            proj_b + (size_t)l * DD, gx, DD, DD, DD, 0);

        layernorm_kernel<<<MR, 256>>>(gx, ln2_g + (size_t)l * DD, ln2_b + (size_t)l * DD, ghb);

        gemm_mma_kernel<<<dim3(MR / GBM, FF_ / GBN), 256, GSMEM>>>(
            ghb, gfc1T + (size_t)l * DD * FF_, nullptr, gffb,
            fc1_b + (size_t)l * FF_, nullptr, FF_, DD, FF_, 1);

        gemm_mma_kernel<<<dim3(MR / GBM, DD / GBN), 256, GSMEM>>>(
            gffb, gfc2T + (size_t)l * FF_ * DD, gx, nullptr,
            fc2_b + (size_t)l * DD, gx, DD, FF_, DD, 0);
    }

    layernorm_kernel<<<MR, 256>>>(gx, lnf_g, lnf_b, ghb);

    gemm_mma_kernel<<<dim3(MR / GBM, (VV + GBN - 1) / GBN), 256, GSMEM>>>(
        ghb, gwteb, out, nullptr, nullptr, nullptr, VV, DD, VV, 0);

    logsoftmax_loss_kernel<<<MR, 512>>>(out, target, gpicked);
    finalize_loss_kernel<<<1, 256>>>(gpicked, out);
}

// round 8
// speedup vs baseline: 5.4657x; 1.0205x over previous
#include <cuda_runtime.h>
#include <cuda_bf16.h>
#include <math.h>
#include <stdint.h>

// ---------------- problem constants ----------------
#define BB   2
#define SS   1024
#define DD   768
#define HH   12
#define DH   64
#define FF_  3072
#define LL   12
#define VV   50257
#define MR   2048          // B*S rows
#define D3   2304          // 3*D
#define NT   393           // ceil(VV/128) logits n-tiles

// ---------------- scratch (static device memory) ----------------
__device__ float g_x   [MR * DD];              // residual stream (fp32)
__device__ float g_picked[MR];
__device__ float g_pm  [MR * NT];              // logits partial max
__device__ float g_ps  [MR * NT];              // logits partial sumexp

__device__ __nv_bfloat16 g_hb  [MR * DD];
__device__ __nv_bfloat16 g_ob  [MR * DD];
__device__ __nv_bfloat16 g_ffb [MR * FF_];
__device__ __nv_bfloat16 g_qkvb[MR * D3];

__device__ __nv_bfloat16 g_wteb [VV * DD];
__device__ __nv_bfloat16 g_qkvT [LL * DD * D3];
__device__ __nv_bfloat16 g_projT[LL * DD * DD];
__device__ __nv_bfloat16 g_fc1T [LL * DD * FF_];
__device__ __nv_bfloat16 g_fc2T [LL * FF_ * DD];

// ================= low-level helpers (baseline PTX only) =================
__device__ __forceinline__ uint32_t smem_u32(const void* p) {
    uint32_t a;
    asm("{ .reg .u64 t; cvta.to.shared.u64 t, %1; cvt.u32.u64 %0, t; }" : "=r"(a) : "l"(p));
    return a;
}
__device__ __forceinline__ void cp_async16(uint32_t dst, const void* src, bool valid) {
    int sz = valid ? 16 : 0;
    asm volatile("cp.async.cg.shared.global [%0], [%1], 16, %2;"
                 :: "r"(dst), "l"(src), "r"(sz) : "memory");
}
#define CP_COMMIT()  asm volatile("cp.async.commit_group;" ::: "memory")
#define CP_WAIT(n)   asm volatile("cp.async.wait_group %0;" :: "n"(n) : "memory")

__device__ __forceinline__ void ldmatrix_x4(uint32_t& r0, uint32_t& r1,
                                            uint32_t& r2, uint32_t& r3, uint32_t addr) {
    asm volatile("ldmatrix.sync.aligned.m8n8.x4.shared.b16 {%0,%1,%2,%3}, [%4];"
                 : "=r"(r0), "=r"(r1), "=r"(r2), "=r"(r3) : "r"(addr));
}
__device__ __forceinline__ void ldmatrix_x4_trans(uint32_t& r0, uint32_t& r1,
                                                  uint32_t& r2, uint32_t& r3, uint32_t addr) {
    asm volatile("ldmatrix.sync.aligned.m8n8.x4.trans.shared.b16 {%0,%1,%2,%3}, [%4];"
                 : "=r"(r0), "=r"(r1), "=r"(r2), "=r"(r3) : "r"(addr));
}
__device__ __forceinline__ void mma_bf16(float* c, const uint32_t* a,
                                         uint32_t b0, uint32_t b1) {
    asm volatile(
        "mma.sync.aligned.m16n8k16.row.col.f32.bf16.bf16.f32 "
        "{%0,%1,%2,%3}, {%4,%5,%6,%7}, {%8,%9}, {%0,%1,%2,%3};"
        : "+f"(c[0]), "+f"(c[1]), "+f"(c[2]), "+f"(c[3])
        : "r"(a[0]), "r"(a[1]), "r"(a[2]), "r"(a[3]), "r"(b0), "r"(b1));
}
__device__ __forceinline__ uint32_t pack_bf16x2(float lo, float hi) {
    __nv_bfloat162 h = __floats2bfloat162_rn(lo, hi);
    return *reinterpret_cast<uint32_t*>(&h);
}
// (m, s) online update with one new value (v finite)
__device__ __forceinline__ void ms_update(float& m, float& s, float v) {
    if (v > m) { s = s * __expf(m - v) + 1.0f; m = v; }
    else       { s += __expf(v - m); }
}
// (m, s) pair combine; -inf safe
__device__ __forceinline__ void ms_combine(float& m, float& s, float m2, float s2) {
    float mn = fmaxf(m, m2);
    float e1 = (m  > -INFINITY) ? __expf(m  - mn) : 0.f;
    float e2 = (m2 > -INFINITY) ? __expf(m2 - mn) : 0.f;
    s = s * e1 + s2 * e2;
    m = mn;
}

// ---------------- block reductions ----------------
__device__ __forceinline__ float blockReduceSum(float v) {
    __shared__ float sh[32];
    int lane = threadIdx.x & 31, wid = threadIdx.x >> 5;
    #pragma unroll
    for (int o = 16; o; o >>= 1) v += __shfl_xor_sync(0xffffffffu, v, o);
    __syncthreads();
    if (lane == 0) sh[wid] = v;
    __syncthreads();
    float r = (lane < (int)(blockDim.x >> 5)) ? sh[lane] : 0.f;
    if (wid == 0) {
        #pragma unroll
        for (int o = 16; o; o >>= 1) r += __shfl_xor_sync(0xffffffffu, r, o);
        if (lane == 0) sh[0] = r;
    }
    __syncthreads();
    return sh[0];
}
// fused (sum, sumsq) reduce for 256-thread blocks
__device__ __forceinline__ float2 blockReduceSum2(float a, float b) {
    __shared__ float2 sh[8];
    int lane = threadIdx.x & 31, wid = threadIdx.x >> 5;
    #pragma unroll
    for (int o = 16; o; o >>= 1) {
        a += __shfl_xor_sync(0xffffffffu, a, o);
        b += __shfl_xor_sync(0xffffffffu, b, o);
    }
    if (lane == 0) sh[wid] = make_float2(a, b);
    __syncthreads();
    if (wid == 0) {
        float2 r = (lane < 8) ? sh[lane] : make_float2(0.f, 0.f);
        #pragma unroll
        for (int o = 4; o; o >>= 1) {
            r.x += __shfl_xor_sync(0xffffffffu, r.x, o);
            r.y += __shfl_xor_sync(0xffffffffu, r.y, o);
        }
        if (lane == 0) sh[0] = r;
    }
    __syncthreads();
    return sh[0];
}

// ---------------- weight prep (64x64 tiles, vectorized) ----------------
__global__ void transpose_to_bf16(const float* __restrict__ src,
                                  __nv_bfloat16* __restrict__ dst,
                                  int K, int N) {
    __shared__ float tile[64][65];
    const float* s = src + (size_t)blockIdx.z * K * N;
    __nv_bfloat16* d = dst + (size_t)blockIdx.z * K * N;
    int n0 = blockIdx.x * 64, k0 = blockIdx.y * 64;
    int tid = threadIdx.x;
    #pragma unroll
    for (int e = 0; e < 8; e++) {
        int idx = tid + e * 256;
        int r = idx >> 5, c = idx & 31;
        float2 v = *reinterpret_cast<const float2*>(s + (size_t)(k0 + r) * N + n0 + c * 2);
        tile[c * 2][r]     = v.x;
        tile[c * 2 + 1][r] = v.y;
    }
    __syncthreads();
    #pragma unroll
    for (int e = 0; e < 8; e++) {
        int idx = tid + e * 256;
        int r = idx >> 5, c = (idx & 31) * 2;
        __nv_bfloat162 v = __floats2bfloat162_rn(tile[r][c], tile[r][c + 1]);
        *reinterpret_cast<__nv_bfloat162*>(d + (size_t)(n0 + r) * K + k0 + c) = v;
    }
}

__global__ void convert_bf16_kernel4(const float4* __restrict__ src,
                                     __nv_bfloat162* __restrict__ dst, long n4) {
    long i = (long)blockIdx.x * blockDim.x + threadIdx.x;
    if (i < n4) {
        float4 v = src[i];
        dst[i * 2]     = __floats2bfloat162_rn(v.x, v.y);
        dst[i * 2 + 1] = __floats2bfloat162_rn(v.z, v.w);
    }
}

// ---------------- embedding ----------------
__global__ void embed_kernel(const int* __restrict__ tokens,
                             const float* __restrict__ wte,
                             const float* __restrict__ wpe,
                             float* __restrict__ x) {
    int i = blockIdx.x * blockDim.x + threadIdx.x;
    if (i >= MR * DD) return;
    int row = i / DD, d = i - row * DD;
    int s = row & (SS - 1);
    x[i] = wte[(size_t)tokens[row] * DD + d] + wpe[(size_t)s * DD + d];
}

// ---------------- layernorm -> bf16 (single fused reduction) ----------------
__global__ void layernorm_kernel(const float* __restrict__ in,
                                 const float* __restrict__ g,
                                 const float* __restrict__ b,
                                 __nv_bfloat16* __restrict__ out) {
    int row = blockIdx.x;
    const float* x = in + (size_t)row * DD;
    int t = threadIdx.x;
    float v0 = x[t], v1 = x[t + 256], v2 = x[t + 512];
    float2 r = blockReduceSum2(v0 + v1 + v2, v0 * v0 + v1 * v1 + v2 * v2);
    float mu = r.x * (1.0f / 768.0f);
    float var = r.y * (1.0f / 768.0f) - mu * mu;
    float rstd = rsqrtf(var + 1e-5f);
    __nv_bfloat16* o = out + (size_t)row * DD;
    o[t]       = __float2bfloat16((v0 - mu) * rstd * g[t]       + b[t]);
    o[t + 256] = __float2bfloat16((v1 - mu) * rstd * g[t + 256] + b[t + 256]);
    o[t + 512] = __float2bfloat16((v2 - mu) * rstd * g[t + 512] + b[t + 512]);
}

// ================= mma.sync NT GEMM, GBK=64, 3-stage, 2 CTAs/SM =============
// FUSE=true adds per-row (max, sumexp) partials over this CTA's n-tile.
#define GBM 128
#define GBN 128
#define GBK 64
#define ROWB 144
#define ABUF 18432
#define BUFS 36864
#define GSMEM (3 * BUFS)   // 110592

template <bool FUSE>
__global__ __launch_bounds__(256, 2)
void gemm_mma_kernel(const __nv_bfloat16* __restrict__ A,
                     const __nv_bfloat16* __restrict__ B,
                     float* __restrict__ Cf,
                     __nv_bfloat16* __restrict__ Cbf,
                     const float* __restrict__ bias,
                     const float* __restrict__ res,
                     int N, int K, int ldc, int act,
                     float* __restrict__ pm, float* __restrict__ ps) {
    extern __shared__ __align__(128) uint8_t gsm[];
    uint32_t sbase = smem_u32(gsm);
    int tid = threadIdx.x;
    int m0 = blockIdx.x * GBM, n0 = blockIdx.y * GBN;
    int nk = K / GBK;

    auto issue = [&](int c) {
        int k0 = c * GBK;
        int st = c % 3;
        uint32_t dA = sbase + st * BUFS;
        uint32_t dB = dA + ABUF;
        #pragma unroll
        for (int e = 0; e < 4; e++) {
            int idx = tid + e * 256;
            int r = idx >> 3, cc = idx & 7;
            cp_async16(dA + r * ROWB + cc * 16,
                       A + (size_t)(m0 + r) * K + k0 + cc * 8, true);
            int gn = n0 + r;
            cp_async16(dB + r * ROWB + cc * 16,
                       B + (size_t)gn * K + k0 + cc * 8, gn < N);
        }
        CP_COMMIT();
    };

    int warp = tid >> 5, lane = tid & 31;
    int wm = warp >> 1, wn = warp & 1;
    int lr = lane & 15, lc = lane >> 4;
    float acc[2][8][4];
    #pragma unroll
    for (int i = 0; i < 2; i++)
        #pragma unroll
        for (int j = 0; j < 8; j++)
            #pragma unroll
            for (int q = 0; q < 4; q++) acc[i][j][q] = 0.f;

    issue(0);
    if (nk > 1) issue(1);
    for (int c = 0; c < nk; c++) {
        if (c + 2 < nk) { issue(c + 2); CP_WAIT(2); }
        else if (c + 1 < nk) { CP_WAIT(1); }
        else { CP_WAIT(0); }
        __syncthreads();
        uint32_t aB = sbase + (c % 3) * BUFS;
        uint32_t bB = aB + ABUF;
        #pragma unroll
        for (int kk = 0; kk < 4; kk++) {
            uint32_t a[2][4];
            #pragma unroll
            for (int mi = 0; mi < 2; mi++) {
                uint32_t addr = aB + (uint32_t)((wm * 32 + mi * 16 + lr) * ROWB
                                                + (kk * 16 + lc * 8) * 2);
                ldmatrix_x4(a[mi][0], a[mi][1], a[mi][2], a[mi][3], addr);
            }
            #pragma unroll
            for (int nb = 0; nb < 4; nb++) {
                uint32_t b0, b1, b2, b3;
                uint32_t addr = bB + (uint32_t)((wn * 64 + nb * 16 + lr) * ROWB
                                                + (kk * 16 + lc * 8) * 2);
                ldmatrix_x4(b0, b1, b2, b3, addr);
                #pragma unroll
                for (int mi = 0; mi < 2; mi++) {
                    mma_bf16(acc[mi][nb * 2],     a[mi], b0, b2);
                    mma_bf16(acc[mi][nb * 2 + 1], a[mi], b1, b3);
                }
            }
        }
        __syncthreads();
    }

    // --- epilogue ---
    int mrow = m0 + wm * 32;
    int ncol = n0 + wn * 64;
    int tr = lane >> 2, tc = (lane & 3) * 2;
    bool vec = ((ldc & 1) == 0);
    float tm[2][2], ts[2][2];
    if (FUSE) {
        #pragma unroll
        for (int i = 0; i < 2; i++)
            #pragma unroll
            for (int j = 0; j < 2; j++) { tm[i][j] = -INFINITY; ts[i][j] = 0.f; }
    }
    #pragma unroll
    for (int mi = 0; mi < 2; mi++) {
        #pragma unroll
        for (int ni = 0; ni < 8; ni++) {
            #pragma unroll
            for (int h = 0; h < 2; h++) {
                int row = mrow + mi * 16 + tr + h * 8;
                int col = ncol + ni * 8 + tc;
                float v0 = acc[mi][ni][h * 2];
                float v1 = acc[mi][ni][h * 2 + 1];
                if (bias) { v0 += bias[col]; if (col + 1 < N) v1 += bias[col + 1]; }
                if (res) {
                    const float* rp = res + (size_t)row * ldc + col;
                    v0 += rp[0];
                    if (col + 1 < N) v1 += rp[1];
                }
                if (act) {
                    v0 = v0 * 0.5f * (1.0f + erff(v0 * 0.70710678118654752f));
                    v1 = v1 * 0.5f * (1.0f + erff(v1 * 0.70710678118654752f));
                }
                if (FUSE) {
                    if (col < N)     ms_update(tm[mi][h], ts[mi][h], v0);
                    if (col + 1 < N) ms_update(tm[mi][h], ts[mi][h], v1);
                }
                if (vec && col + 1 < N) {
                    if (Cf) *reinterpret_cast<float2*>(Cf + (size_t)row * ldc + col)
                                = make_float2(v0, v1);
                    else    *reinterpret_cast<__nv_bfloat162*>(Cbf + (size_t)row * ldc + col)
                                = __floats2bfloat162_rn(v0, v1);
                } else {
                    if (col < N) {
                        if (Cf) Cf[(size_t)row * ldc + col] = v0;
                        else    Cbf[(size_t)row * ldc + col] = __float2bfloat16(v0);
                    }
                    if (col + 1 < N) {
                        if (Cf) Cf[(size_t)row * ldc + col + 1] = v1;
                        else    Cbf[(size_t)row * ldc + col + 1] = __float2bfloat16(v1);
                    }
                }
            }
        }
    }
    if (FUSE) {
        // reduce across the 4 lanes sharing each row (qd = lane & 3)
        float2* red = reinterpret_cast<float2*>(gsm);   // [128 rows][2 wn]
        #pragma unroll
        for (int mi = 0; mi < 2; mi++) {
            #pragma unroll
            for (int h = 0; h < 2; h++) {
                float m = tm[mi][h], s = ts[mi][h];
                #pragma unroll
                for (int o = 1; o <= 2; o <<= 1) {
                    float m2 = __shfl_xor_sync(0xffffffffu, m, o);
                    float s2 = __shfl_xor_sync(0xffffffffu, s, o);
                    ms_combine(m, s, m2, s2);
                }
                if ((lane & 3) == 0) {
                    int row_local = wm * 32 + mi * 16 + tr + h * 8;
                    red[row_local * 2 + wn] = make_float2(m, s);
                }
            }
        }
        __syncthreads();
        if (tid < 128) {
            float2 p0 = red[tid * 2], p1 = red[tid * 2 + 1];
            float m = p0.x, s = p0.y;
            ms_combine(m, s, p1.x, p1.y);
            pm[(size_t)(m0 + tid) * NT + blockIdx.y] = m;
            ps[(size_t)(m0 + tid) * NT + blockIdx.y] = s;
        }
    }
}

// ================= fused flash attention (bf16 tensor cores) =================
#define FQROWB 144
#define FQ_OFF 0
#define FK_OFF 18432
#define FV_OFF 36864
#define FSMEM  55296

__global__ __launch_bounds__(256, 2)
void flash_attn_kernel(const __nv_bfloat16* __restrict__ qkv,
                       __nv_bfloat16* __restrict__ o) {
    extern __shared__ __align__(128) uint8_t fsm[];
    uint32_t sbase = smem_u32(fsm);
    int tid = threadIdx.x;
    int q0 = (gridDim.x - 1 - blockIdx.x) * 128;
    int bh = blockIdx.y, b = bh / HH, h = bh - b * HH;
    const size_t rowbase = (size_t)b * SS * D3;
    const int qoff = h * DH, koff = DD + h * DH, voff = 2 * DD + h * DH;

    auto issue_q = [&]() {
        #pragma unroll
        for (int e = 0; e < 4; e++) {
            int idx = tid + e * 256;
            int r = idx >> 3, c = idx & 7;
            cp_async16(sbase + FQ_OFF + r * FQROWB + c * 16,
                       qkv + rowbase + (size_t)(q0 + r) * D3 + qoff + c * 8, true);
        }
        CP_COMMIT();
    };
    auto issue_kv = [&](int t) {
        int kv0 = t * 64;
        uint32_t kd = sbase + FK_OFF + (t & 1) * (64 * FQROWB);
        uint32_t vd = sbase + FV_OFF + (t & 1) * (64 * FQROWB);
        #pragma unroll
        for (int e = 0; e < 2; e++) {
            int idx = tid + e * 256;
            int r = idx >> 3, c = idx & 7;
            const size_t g = rowbase + (size_t)(kv0 + r) * D3;
            cp_async16(kd + r * FQROWB + c * 16, qkv + g + koff + c * 8, true);
            cp_async16(vd + r * FQROWB + c * 16, qkv + g + voff + c * 8, true);
        }
        CP_COMMIT();
    };

    int warp = tid >> 5, lane = tid & 31;
    int lr = lane & 15, lc = lane >> 4;
    int tr = lane >> 2, qd = lane & 3;
    int wq = q0 + warp * 16;

    float of[8][4];
    #pragma unroll
    for (int i = 0; i < 8; i++)
        #pragma unroll
        for (int j = 0; j < 4; j++) of[i][j] = 0.f;
    float m0r = -INFINITY, m1r = -INFINITY, l0r = 0.f, l1r = 0.f;

    int nt = q0 / 64 + 2;
    issue_q();
    issue_kv(0);

    const float sc = 0.03608439182435161f;  // 1/sqrt(768)

    for (int t = 0; t < nt; t++) {
        if (t + 1 < nt) { issue_kv(t + 1); CP_WAIT(1); }
        else            { CP_WAIT(0); }
        __syncthreads();
        int kv0 = t * 64;
        uint32_t kB = sbase + FK_OFF + (t & 1) * (64 * FQROWB);
        uint32_t vB = sbase + FV_OFF + (t & 1) * (64 * FQROWB);

        float sf[8][4];
        #pragma unroll
        for (int i = 0; i < 8; i++)
            #pragma unroll
            for (int j = 0; j < 4; j++) sf[i][j] = 0.f;
        #pragma unroll
        for (int ks = 0; ks < 4; ks++) {
            uint32_t aq[4];
            uint32_t qa = sbase + FQ_OFF + (uint32_t)((warp * 16 + lr) * FQROWB
                                                      + (ks * 16 + lc * 8) * 2);
            ldmatrix_x4(aq[0], aq[1], aq[2], aq[3], qa);
            #pragma unroll
            for (int nb2 = 0; nb2 < 4; nb2++) {
                uint32_t b0, b1, b2, b3;
                uint32_t ka = kB + (uint32_t)((nb2 * 16 + lr) * FQROWB
                                              + (ks * 16 + lc * 8) * 2);
                ldmatrix_x4(b0, b1, b2, b3, ka);
                mma_bf16(sf[nb2 * 2],     aq, b0, b2);
                mma_bf16(sf[nb2 * 2 + 1], aq, b1, b3);
            }
        }
        #pragma unroll
        for (int i = 0; i < 8; i++)
            #pragma unroll
            for (int j = 0; j < 4; j++) sf[i][j] *= sc;
        if (kv0 + 63 > wq) {
            #pragma unroll
            for (int nb = 0; nb < 8; nb++) {
                #pragma unroll
                for (int j = 0; j < 4; j++) {
                    int col = kv0 + nb * 8 + qd * 2 + (j & 1);
                    int row = wq + tr + (j >> 1) * 8;
                    if (col > row) sf[nb][j] = -INFINITY;
                }
            }
        }
        float tm0 = -INFINITY, tm1 = -INFINITY;
        #pragma unroll
        for (int nb = 0; nb < 8; nb++) {
            tm0 = fmaxf(tm0, fmaxf(sf[nb][0], sf[nb][1]));
            tm1 = fmaxf(tm1, fmaxf(sf[nb][2], sf[nb][3]));
        }
        tm0 = fmaxf(tm0, __shfl_xor_sync(0xffffffffu, tm0, 1));
        tm0 = fmaxf(tm0, __shfl_xor_sync(0xffffffffu, tm0, 2));
        tm1 = fmaxf(tm1, __shfl_xor_sync(0xffffffffu, tm1, 1));
        tm1 = fmaxf(tm1, __shfl_xor_sync(0xffffffffu, tm1, 2));
        float mn0 = fmaxf(m0r, tm0), mn1 = fmaxf(m1r, tm1);
        float f0 = __expf(m0r - mn0), f1 = __expf(m1r - mn1);
        m0r = mn0; m1r = mn1;
        float rs0 = 0.f, rs1 = 0.f;
        #pragma unroll
        for (int nb = 0; nb < 8; nb++) {
            sf[nb][0] = __expf(sf[nb][0] - mn0);
            sf[nb][1] = __expf(sf[nb][1] - mn0);
            sf[nb][2] = __expf(sf[nb][2] - mn1);
            sf[nb][3] = __expf(sf[nb][3] - mn1);
            rs0 += sf[nb][0] + sf[nb][1];
            rs1 += sf[nb][2] + sf[nb][3];
        }
        rs0 += __shfl_xor_sync(0xffffffffu, rs0, 1);
        rs0 += __shfl_xor_sync(0xffffffffu, rs0, 2);
        rs1 += __shfl_xor_sync(0xffffffffu, rs1, 1);
        rs1 += __shfl_xor_sync(0xffffffffu, rs1, 2);
        l0r = l0r * f0 + rs0;
        l1r = l1r * f1 + rs1;
        #pragma unroll
        for (int nb = 0; nb < 8; nb++) {
            of[nb][0] *= f0; of[nb][1] *= f0;
            of[nb][2] *= f1; of[nb][3] *= f1;
        }
        #pragma unroll
        for (int ks = 0; ks < 4; ks++) {
            uint32_t ap[4];
            ap[0] = pack_bf16x2(sf[2 * ks][0],     sf[2 * ks][1]);
            ap[1] = pack_bf16x2(sf[2 * ks][2],     sf[2 * ks][3]);
            ap[2] = pack_bf16x2(sf[2 * ks + 1][0], sf[2 * ks + 1][1]);
            ap[3] = pack_bf16x2(sf[2 * ks + 1][2], sf[2 * ks + 1][3]);
            #pragma unroll
            for (int nb2 = 0; nb2 < 4; nb2++) {
                int g = lane >> 3;
                int kvr = ks * 16 + (g & 1) * 8 + (lane & 7);
                int dhc = nb2 * 16 + (g >> 1) * 8;
                uint32_t va = vB + (uint32_t)(kvr * FQROWB + dhc * 2);
                uint32_t r0, r1, r2, r3;
                ldmatrix_x4_trans(r0, r1, r2, r3, va);
                mma_bf16(of[nb2 * 2],     ap, r0, r1);
                mma_bf16(of[nb2 * 2 + 1], ap, r2, r3);
            }
        }
        __syncthreads();
    }

    float inv0 = 1.0f / l0r, inv1 = 1.0f / l1r;
    size_t obase = (size_t)b * SS * DD + (size_t)h * DH;
    #pragma unroll
    for (int nb = 0; nb < 8; nb++) {
        int col = nb * 8 + qd * 2;
        int row0 = wq + tr, row1 = row0 + 8;
        __nv_bfloat162 v0 = __floats2bfloat162_rn(of[nb][0] * inv0, of[nb][1] * inv0);
        __nv_bfloat162 v1 = __floats2bfloat162_rn(of[nb][2] * inv1, of[nb][3] * inv1);
        *reinterpret_cast<__nv_bfloat162*>(o + obase + (size_t)row0 * DD + col) = v0;
        *reinterpret_cast<__nv_bfloat162*>(o + obase + (size_t)row1 * DD + col) = v1;
    }
}

// ---- finish log_softmax from GEMM partials: single read+write pass ---------
__global__ __launch_bounds__(512)
void logsoftmax_finish_kernel(float* __restrict__ logits,
                              const float* __restrict__ pm,
                              const float* __restrict__ ps,
                              const int* __restrict__ target,
                              float* __restrict__ picked) {
    __shared__ float shm[16], shs[16], bc[1];
    int row = blockIdx.x;
    float* x = logits + (size_t)row * VV;
    int t = threadIdx.x, lane = t & 31, wid = t >> 5;

    float m = -INFINITY, s = 0.f;
    const float* pmr = pm + (size_t)row * NT;
    const float* psr = ps + (size_t)row * NT;
    for (int i = t; i < NT; i += 512)
        ms_combine(m, s, pmr[i], psr[i]);
    #pragma unroll
    for (int o = 16; o; o >>= 1) {
        float m2 = __shfl_xor_sync(0xffffffffu, m, o);
        float s2 = __shfl_xor_sync(0xffffffffu, s, o);
        ms_combine(m, s, m2, s2);
    }
    if (lane == 0) { shm[wid] = m; shs[wid] = s; }
    __syncthreads();
    if (t == 0) {
        float M = shm[0], S = shs[0];
        #pragma unroll
        for (int i = 1; i < 16; i++)
            ms_combine(M, S, shm[i], shs[i]);
        bc[0] = M + logf(S);
    }
    __syncthreads();
    float sub = bc[0];
    int tgt = target[row];

    // alignment-safe vectorized pass (row base only 4B aligned in general)
    int head = (int)(((16 - ((uintptr_t)x & 15)) & 15) >> 2);
    int nvec = (VV - head) >> 2;
    float* xv = x + head;
    for (int i = t; i < head; i += 512) {
        float lp = x[i] - sub;
        x[i] = lp;
        if (i == tgt) picked[row] = lp;
    }
    for (int i = t; i < nvec; i += 512) {
        float4 v = *reinterpret_cast<const float4*>(xv + i * 4);
        v.x -= sub; v.y -= sub; v.z -= sub; v.w -= sub;
        *reinterpret_cast<float4*>(xv + i * 4) = v;
        int base = head + i * 4;
        if (tgt >= base && tgt < base + 4) {
            float pv = (tgt == base) ? v.x : (tgt == base + 1) ? v.y
                     : (tgt == base + 2) ? v.z : v.w;
            picked[row] = pv;
        }
    }
    for (int i = head + nvec * 4 + t; i < VV; i += 512) {
        float lp = x[i] - sub;
        x[i] = lp;
        if (i == tgt) picked[row] = lp;
    }
}

__global__ void finalize_loss_kernel(const float* __restrict__ picked,
                                     float* __restrict__ out) {
    float s = 0.f;
    for (int i = threadIdx.x; i < MR; i += 256) s += picked[i];
    s = blockReduceSum(s);
    if (threadIdx.x == 0) out[(size_t)MR * VV] = -s * (1.0f / (float)MR);
}

// ---------------- host orchestration ----------------
extern "C" void kernel_launch(void* const* d_in, const int* in_sizes, int n_in,
                              void* d_out, int out_size) {
    const int*   tokens = (const int*)  d_in[0];
    const int*   target = (const int*)  d_in[1];
    const float* wte    = (const float*)d_in[2];
    const float* wpe    = (const float*)d_in[3];
    const float* ln1_g  = (const float*)d_in[4];
    const float* ln1_b  = (const float*)d_in[5];
    const float* qkv_w  = (const float*)d_in[6];
    const float* qkv_b  = (const float*)d_in[7];
    const float* proj_w = (const float*)d_in[8];
    const float* proj_b = (const float*)d_in[9];
    const float* ln2_g  = (const float*)d_in[10];
    const float* ln2_b  = (const float*)d_in[11];
    const float* fc1_w  = (const float*)d_in[12];
    const float* fc1_b  = (const float*)d_in[13];
    const float* fc2_w  = (const float*)d_in[14];
    const float* fc2_b  = (const float*)d_in[15];
    const float* lnf_g  = (const float*)d_in[16];
    const float* lnf_b  = (const float*)d_in[17];
    float* out = (float*)d_out;

    float *gx, *gpicked, *gpm, *gps;
    __nv_bfloat16 *ghb, *gob, *gffb, *gqkvb, *gwteb, *gqkvT, *gprojT, *gfc1T, *gfc2T;
    cudaGetSymbolAddress((void**)&gx,     g_x);
    cudaGetSymbolAddress((void**)&gpicked,g_picked);
    cudaGetSymbolAddress((void**)&gpm,    g_pm);
    cudaGetSymbolAddress((void**)&gps,    g_ps);
    cudaGetSymbolAddress((void**)&ghb,    g_hb);
    cudaGetSymbolAddress((void**)&gob,    g_ob);
    cudaGetSymbolAddress((void**)&gffb,   g_ffb);
    cudaGetSymbolAddress((void**)&gqkvb,  g_qkvb);
    cudaGetSymbolAddress((void**)&gwteb,  g_wteb);
    cudaGetSymbolAddress((void**)&gqkvT,  g_qkvT);
    cudaGetSymbolAddress((void**)&gprojT, g_projT);
    cudaGetSymbolAddress((void**)&gfc1T,  g_fc1T);
    cudaGetSymbolAddress((void**)&gfc2T,  g_fc2T);

    cudaFuncSetAttribute(flash_attn_kernel,
                         cudaFuncAttributeMaxDynamicSharedMemorySize, FSMEM);
    cudaFuncSetAttribute(gemm_mma_kernel<false>,
                         cudaFuncAttributeMaxDynamicSharedMemorySize, GSMEM);
    cudaFuncSetAttribute(gemm_mma_kernel<true>,
                         cudaFuncAttributeMaxDynamicSharedMemorySize, GSMEM);

    {
        long n4 = (long)VV * DD / 4;
        convert_bf16_kernel4<<<(int)((n4 + 255) / 256), 256>>>(
            (const float4*)wte, (__nv_bfloat162*)gwteb, n4);
    }
    transpose_to_bf16<<<dim3(D3 / 64,  DD / 64,  LL), 256>>>(qkv_w,  gqkvT,  DD,  D3);
    transpose_to_bf16<<<dim3(DD / 64,  DD / 64,  LL), 256>>>(proj_w, gprojT, DD,  DD);
    transpose_to_bf16<<<dim3(FF_ / 64, DD / 64,  LL), 256>>>(fc1_w,  gfc1T,  DD,  FF_);
    transpose_to_bf16<<<dim3(DD / 64,  FF_ / 64, LL), 256>>>(fc2_w,  gfc2T,  FF_, DD);

    embed_kernel<<<(MR * DD + 255) / 256, 256>>>(tokens, wte, wpe, gx);

    for (int l = 0; l < LL; l++) {
        layernorm_kernel<<<MR, 256>>>(gx, ln1_g + (size_t)l * DD, ln1_b + (size_t)l * DD, ghb);

        gemm_mma_kernel<false><<<dim3(MR / GBM, D3 / GBN), 256, GSMEM>>>(
            ghb, gqkvT + (size_t)l * DD * D3, nullptr, gqkvb,
            qkv_b + (size_t)l * D3, nullptr, D3, DD, D3, 0, nullptr, nullptr);

        flash_attn_kernel<<<dim3(SS / 128, BB * HH), 256, FSMEM>>>(gqkvb, gob);

        gemm_mma_kernel<false><<<dim3(MR / GBM, DD / GBN), 256, GSMEM>>>(
            gob, gprojT + (size_t)l * DD * DD, gx, nullptr,
            proj_b + (size_t)l * DD, gx, DD, DD, DD, 0, nullptr, nullptr);

        layernorm_kernel<<<MR, 256>>>(gx, ln2_g + (size_t)l * DD, ln2_b + (size_t)l * DD, ghb);

        gemm_mma_kernel<false><<<dim3(MR / GBM, FF_ / GBN), 256, GSMEM>>>(
            ghb, gfc1T + (size_t)l * DD * FF_, nullptr, gffb,
            fc1_b + (size_t)l * FF_, nullptr, FF_, DD, FF_, 1, nullptr, nullptr);

        gemm_mma_kernel<false><<<dim3(MR / GBM, DD / GBN), 256, GSMEM>>>(
            gffb, gfc2T + (size_t)l * FF_ * DD, gx, nullptr,
            fc2_b + (size_t)l * DD, gx, DD, FF_, DD, 0, nullptr, nullptr);
    }

    layernorm_kernel<<<MR, 256>>>(gx, lnf_g, lnf_b, ghb);

    // logits GEMM with fused per-tile (max, sumexp) partials
    gemm_mma_kernel<true><<<dim3(MR / GBM, NT), 256, GSMEM>>>(
        ghb, gwteb, out, nullptr, nullptr, nullptr, VV, DD, VV, 0, gpm, gps);

    logsoftmax_finish_kernel<<<MR, 512>>>(out, gpm, gps, target, gpicked);
    finalize_loss_kernel<<<1, 256>>>(gpicked, out);
}

// round 9
// speedup vs baseline: 5.7201x; 1.0465x over previous
#include <cuda_runtime.h>
#include <cuda_bf16.h>
#include <math.h>
#include <stdint.h>

// ---------------- problem constants ----------------
#define BB   2
#define SS   1024
#define DD   768
#define HH   12
#define DH   64
#define FF_  3072
#define LL   12
#define VV   50257
#define MR   2048          // B*S rows
#define D3   2304          // 3*D
#define NT   393           // ceil(VV/128) logits n-tiles

// ---------------- scratch (static device memory) ----------------
__device__ float g_x   [MR * DD];
__device__ float g_picked[MR];
__device__ float g_pm  [MR * NT];
__device__ float g_ps  [MR * NT];

__device__ __nv_bfloat16 g_hb  [MR * DD];
__device__ __nv_bfloat16 g_ob  [MR * DD];
__device__ __nv_bfloat16 g_ffb [MR * FF_];
__device__ __nv_bfloat16 g_qkvb[MR * D3];

__device__ __nv_bfloat16 g_wteb [VV * DD];
__device__ __nv_bfloat16 g_qkvT [LL * DD * D3];
__device__ __nv_bfloat16 g_projT[LL * DD * DD];
__device__ __nv_bfloat16 g_fc1T [LL * DD * FF_];
__device__ __nv_bfloat16 g_fc2T [LL * FF_ * DD];

// ================= low-level helpers (baseline PTX only) =================
__device__ __forceinline__ uint32_t smem_u32(const void* p) {
    uint32_t a;
    asm("{ .reg .u64 t; cvta.to.shared.u64 t, %1; cvt.u32.u64 %0, t; }" : "=r"(a) : "l"(p));
    return a;
}
__device__ __forceinline__ void cp_async16(uint32_t dst, const void* src, bool valid) {
    int sz = valid ? 16 : 0;
    asm volatile("cp.async.cg.shared.global [%0], [%1], 16, %2;"
                 :: "r"(dst), "l"(src), "r"(sz) : "memory");
}
#define CP_COMMIT()  asm volatile("cp.async.commit_group;" ::: "memory")
#define CP_WAIT(n)   asm volatile("cp.async.wait_group %0;" :: "n"(n) : "memory")

__device__ __forceinline__ void ldmatrix_x4(uint32_t& r0, uint32_t& r1,
                                            uint32_t& r2, uint32_t& r3, uint32_t addr) {
    asm volatile("ldmatrix.sync.aligned.m8n8.x4.shared.b16 {%0,%1,%2,%3}, [%4];"
                 : "=r"(r0), "=r"(r1), "=r"(r2), "=r"(r3) : "r"(addr));
}
__device__ __forceinline__ void ldmatrix_x4_trans(uint32_t& r0, uint32_t& r1,
                                                  uint32_t& r2, uint32_t& r3, uint32_t addr) {
    asm volatile("ldmatrix.sync.aligned.m8n8.x4.trans.shared.b16 {%0,%1,%2,%3}, [%4];"
                 : "=r"(r0), "=r"(r1), "=r"(r2), "=r"(r3) : "r"(addr));
}
__device__ __forceinline__ void mma_bf16(float* c, const uint32_t* a,
                                         uint32_t b0, uint32_t b1) {
    asm volatile(
        "mma.sync.aligned.m16n8k16.row.col.f32.bf16.bf16.f32 "
        "{%0,%1,%2,%3}, {%4,%5,%6,%7}, {%8,%9}, {%0,%1,%2,%3};"
        : "+f"(c[0]), "+f"(c[1]), "+f"(c[2]), "+f"(c[3])
        : "r"(a[0]), "r"(a[1]), "r"(a[2]), "r"(a[3]), "r"(b0), "r"(b1));
}
__device__ __forceinline__ uint32_t pack_bf16x2(float lo, float hi) {
    __nv_bfloat162 h = __floats2bfloat162_rn(lo, hi);
    return *reinterpret_cast<uint32_t*>(&h);
}
__device__ __forceinline__ void ms_update(float& m, float& s, float v) {
    if (v > m) { s = s * __expf(m - v) + 1.0f; m = v; }
    else       { s += __expf(v - m); }
}
__device__ __forceinline__ void ms_combine(float& m, float& s, float m2, float s2) {
    float mn = fmaxf(m, m2);
    float e1 = (m  > -INFINITY) ? __expf(m  - mn) : 0.f;
    float e2 = (m2 > -INFINITY) ? __expf(m2 - mn) : 0.f;
    s = s * e1 + s2 * e2;
    m = mn;
}

// ---------------- block reductions ----------------
__device__ __forceinline__ float blockReduceSum(float v) {
    __shared__ float sh[32];
    int lane = threadIdx.x & 31, wid = threadIdx.x >> 5;
    #pragma unroll
    for (int o = 16; o; o >>= 1) v += __shfl_xor_sync(0xffffffffu, v, o);
    __syncthreads();
    if (lane == 0) sh[wid] = v;
    __syncthreads();
    float r = (lane < (int)(blockDim.x >> 5)) ? sh[lane] : 0.f;
    if (wid == 0) {
        #pragma unroll
        for (int o = 16; o; o >>= 1) r += __shfl_xor_sync(0xffffffffu, r, o);
        if (lane == 0) sh[0] = r;
    }
    __syncthreads();
    return sh[0];
}
__device__ __forceinline__ float2 blockReduceSum2(float a, float b) {
    __shared__ float2 sh[8];
    int lane = threadIdx.x & 31, wid = threadIdx.x >> 5;
    #pragma unroll
    for (int o = 16; o; o >>= 1) {
        a += __shfl_xor_sync(0xffffffffu, a, o);
        b += __shfl_xor_sync(0xffffffffu, b, o);
    }
    if (lane == 0) sh[wid] = make_float2(a, b);
    __syncthreads();
    if (wid == 0) {
        float2 r = (lane < 8) ? sh[lane] : make_float2(0.f, 0.f);
        #pragma unroll
        for (int o = 4; o; o >>= 1) {
            r.x += __shfl_xor_sync(0xffffffffu, r.x, o);
            r.y += __shfl_xor_sync(0xffffffffu, r.y, o);
        }
        if (lane == 0) sh[0] = r;
    }
    __syncthreads();
    return sh[0];
}

// ---------------- weight prep ----------------
__global__ void transpose_to_bf16(const float* __restrict__ src,
                                  __nv_bfloat16* __restrict__ dst,
                                  int K, int N) {
    __shared__ float tile[64][65];
    const float* s = src + (size_t)blockIdx.z * K * N;
    __nv_bfloat16* d = dst + (size_t)blockIdx.z * K * N;
    int n0 = blockIdx.x * 64, k0 = blockIdx.y * 64;
    int tid = threadIdx.x;
    #pragma unroll
    for (int e = 0; e < 8; e++) {
        int idx = tid + e * 256;
        int r = idx >> 5, c = idx & 31;
        float2 v = *reinterpret_cast<const float2*>(s + (size_t)(k0 + r) * N + n0 + c * 2);
        tile[c * 2][r]     = v.x;
        tile[c * 2 + 1][r] = v.y;
    }
    __syncthreads();
    #pragma unroll
    for (int e = 0; e < 8; e++) {
        int idx = tid + e * 256;
        int r = idx >> 5, c = (idx & 31) * 2;
        __nv_bfloat162 v = __floats2bfloat162_rn(tile[r][c], tile[r][c + 1]);
        *reinterpret_cast<__nv_bfloat162*>(d + (size_t)(n0 + r) * K + k0 + c) = v;
    }
}

__global__ void convert_bf16_kernel4(const float4* __restrict__ src,
                                     __nv_bfloat162* __restrict__ dst, long n4) {
    long i = (long)blockIdx.x * blockDim.x + threadIdx.x;
    if (i < n4) {
        float4 v = src[i];
        dst[i * 2]     = __floats2bfloat162_rn(v.x, v.y);
        dst[i * 2 + 1] = __floats2bfloat162_rn(v.z, v.w);
    }
}

// ---------------- embedding ----------------
__global__ void embed_kernel(const int* __restrict__ tokens,
                             const float* __restrict__ wte,
                             const float* __restrict__ wpe,
                             float* __restrict__ x) {
    int i = blockIdx.x * blockDim.x + threadIdx.x;
    if (i >= MR * DD) return;
    int row = i / DD, d = i - row * DD;
    int s = row & (SS - 1);
    x[i] = wte[(size_t)tokens[row] * DD + d] + wpe[(size_t)s * DD + d];
}

// ---------------- layernorm -> bf16 ----------------
__global__ void layernorm_kernel(const float* __restrict__ in,
                                 const float* __restrict__ g,
                                 const float* __restrict__ b,
                                 __nv_bfloat16* __restrict__ out) {
    int row = blockIdx.x;
    const float* x = in + (size_t)row * DD;
    int t = threadIdx.x;
    float v0 = x[t], v1 = x[t + 256], v2 = x[t + 512];
    float2 r = blockReduceSum2(v0 + v1 + v2, v0 * v0 + v1 * v1 + v2 * v2);
    float mu = r.x * (1.0f / 768.0f);
    float var = r.y * (1.0f / 768.0f) - mu * mu;
    float rstd = rsqrtf(var + 1e-5f);
    __nv_bfloat16* o = out + (size_t)row * DD;
    o[t]       = __float2bfloat16((v0 - mu) * rstd * g[t]       + b[t]);
    o[t + 256] = __float2bfloat16((v1 - mu) * rstd * g[t + 256] + b[t + 256]);
    o[t + 512] = __float2bfloat16((v2 - mu) * rstd * g[t + 512] + b[t + 512]);
}

// ================= mma.sync NT GEMM, templated BN (128 or 64) ===============
#define GBM 128
#define GBK 64
#define ROWB 144
#define ABUF 18432   // 128 * 144

template <bool FUSE, int BN>
__global__ __launch_bounds__(256, 2)
void gemm_mma_kernel(const __nv_bfloat16* __restrict__ A,
                     const __nv_bfloat16* __restrict__ B,
                     float* __restrict__ Cf,
                     __nv_bfloat16* __restrict__ Cbf,
                     const float* __restrict__ bias,
                     const float* __restrict__ res,
                     int N, int K, int ldc, int act,
                     float* __restrict__ pm, float* __restrict__ ps) {
    constexpr int BBUF = BN * ROWB;
    constexpr int BUFS = ABUF + BBUF;
    constexpr int NNB  = BN / 32;        // warp n-subtiles of 16 (per wn half)
    extern __shared__ __align__(128) uint8_t gsm[];
    uint32_t sbase = smem_u32(gsm);
    int tid = threadIdx.x;
    int m0 = blockIdx.x * GBM, n0 = blockIdx.y * BN;
    int nk = K / GBK;

    auto issue = [&](int c) {
        int k0 = c * GBK;
        int st = c % 3;
        uint32_t dA = sbase + st * BUFS;
        uint32_t dB = dA + ABUF;
        #pragma unroll
        for (int e = 0; e < 4; e++) {
            int idx = tid + e * 256;
            int r = idx >> 3, cc = idx & 7;
            cp_async16(dA + r * ROWB + cc * 16,
                       A + (size_t)(m0 + r) * K + k0 + cc * 8, true);
        }
        #pragma unroll
        for (int e = 0; e < BN / 32; e++) {
            int idx = tid + e * 256;
            int r = idx >> 3, cc = idx & 7;
            int gn = n0 + r;
            cp_async16(dB + r * ROWB + cc * 16,
                       B + (size_t)gn * K + k0 + cc * 8, gn < N);
        }
        CP_COMMIT();
    };

    int warp = tid >> 5, lane = tid & 31;
    int wm = warp >> 1, wn = warp & 1;
    int lr = lane & 15, lc = lane >> 4;
    float acc[2][2 * NNB][4];
    #pragma unroll
    for (int i = 0; i < 2; i++)
        #pragma unroll
        for (int j = 0; j < 2 * NNB; j++)
            #pragma unroll
            for (int q = 0; q < 4; q++) acc[i][j][q] = 0.f;

    issue(0);
    if (nk > 1) issue(1);
    for (int c = 0; c < nk; c++) {
        if (c + 2 < nk) { issue(c + 2); CP_WAIT(2); }
        else if (c + 1 < nk) { CP_WAIT(1); }
        else { CP_WAIT(0); }
        __syncthreads();
        uint32_t aB = sbase + (c % 3) * BUFS;
        uint32_t bB = aB + ABUF;
        #pragma unroll
        for (int kk = 0; kk < 4; kk++) {
            uint32_t a[2][4];
            #pragma unroll
            for (int mi = 0; mi < 2; mi++) {
                uint32_t addr = aB + (uint32_t)((wm * 32 + mi * 16 + lr) * ROWB
                                                + (kk * 16 + lc * 8) * 2);
                ldmatrix_x4(a[mi][0], a[mi][1], a[mi][2], a[mi][3], addr);
            }
            #pragma unroll
            for (int nb = 0; nb < NNB; nb++) {
                uint32_t b0, b1, b2, b3;
                uint32_t addr = bB + (uint32_t)((wn * (BN / 2) + nb * 16 + lr) * ROWB
                                                + (kk * 16 + lc * 8) * 2);
                ldmatrix_x4(b0, b1, b2, b3, addr);
                #pragma unroll
                for (int mi = 0; mi < 2; mi++) {
                    mma_bf16(acc[mi][nb * 2],     a[mi], b0, b2);
                    mma_bf16(acc[mi][nb * 2 + 1], a[mi], b1, b3);
                }
            }
        }
        __syncthreads();
    }

    // --- epilogue ---
    int mrow = m0 + wm * 32;
    int ncol = n0 + wn * (BN / 2);
    int tr = lane >> 2, tc = (lane & 3) * 2;
    bool vec = ((ldc & 1) == 0);
    float tm[2][2], ts[2][2];
    if (FUSE) {
        #pragma unroll
        for (int i = 0; i < 2; i++)
            #pragma unroll
            for (int j = 0; j < 2; j++) { tm[i][j] = -INFINITY; ts[i][j] = 0.f; }
    }
    #pragma unroll
    for (int mi = 0; mi < 2; mi++) {
        #pragma unroll
        for (int ni = 0; ni < 2 * NNB; ni++) {
            #pragma unroll
            for (int h = 0; h < 2; h++) {
                int row = mrow + mi * 16 + tr + h * 8;
                int col = ncol + ni * 8 + tc;
                float v0 = acc[mi][ni][h * 2];
                float v1 = acc[mi][ni][h * 2 + 1];
                if (bias) { v0 += bias[col]; if (col + 1 < N) v1 += bias[col + 1]; }
                if (res) {
                    const float* rp = res + (size_t)row * ldc + col;
                    v0 += rp[0];
                    if (col + 1 < N) v1 += rp[1];
                }
                if (act) {
                    v0 = v0 * 0.5f * (1.0f + erff(v0 * 0.70710678118654752f));
                    v1 = v1 * 0.5f * (1.0f + erff(v1 * 0.70710678118654752f));
                }
                if (FUSE) {
                    if (col < N)     ms_update(tm[mi][h], ts[mi][h], v0);
                    if (col + 1 < N) ms_update(tm[mi][h], ts[mi][h], v1);
                }
                if (vec && col + 1 < N) {
                    if (Cf) *reinterpret_cast<float2*>(Cf + (size_t)row * ldc + col)
                                = make_float2(v0, v1);
                    else    *reinterpret_cast<__nv_bfloat162*>(Cbf + (size_t)row * ldc + col)
                                = __floats2bfloat162_rn(v0, v1);
                } else {
                    if (col < N) {
                        if (Cf) Cf[(size_t)row * ldc + col] = v0;
                        else    Cbf[(size_t)row * ldc + col] = __float2bfloat16(v0);
                    }
                    if (col + 1 < N) {
                        if (Cf) Cf[(size_t)row * ldc + col + 1] = v1;
                        else    Cbf[(size_t)row * ldc + col + 1] = __float2bfloat16(v1);
                    }
                }
            }
        }
    }
    if (FUSE) {
        float2* red = reinterpret_cast<float2*>(gsm);
        #pragma unroll
        for (int mi = 0; mi < 2; mi++) {
            #pragma unroll
            for (int h = 0; h < 2; h++) {
                float m = tm[mi][h], s = ts[mi][h];
                #pragma unroll
                for (int o = 1; o <= 2; o <<= 1) {
                    float m2 = __shfl_xor_sync(0xffffffffu, m, o);
                    float s2 = __shfl_xor_sync(0xffffffffu, s, o);
                    ms_combine(m, s, m2, s2);
                }
                if ((lane & 3) == 0) {
                    int row_local = wm * 32 + mi * 16 + tr + h * 8;
                    red[row_local * 2 + wn] = make_float2(m, s);
                }
            }
        }
        __syncthreads();
        if (tid < 128) {
            float2 p0 = red[tid * 2], p1 = red[tid * 2 + 1];
            float m = p0.x, s = p0.y;
            ms_combine(m, s, p1.x, p1.y);
            pm[(size_t)(m0 + tid) * NT + blockIdx.y] = m;
            ps[(size_t)(m0 + tid) * NT + blockIdx.y] = s;
        }
    }
}

#define GS128 (3 * (ABUF + 128 * ROWB))   // 110592
#define GS64  (3 * (ABUF + 64 * ROWB))    // 82944

// ================= fused flash attention (bf16 tensor cores) =================
#define FQROWB 144
#define FQ_OFF 0
#define FK_OFF 18432
#define FV_OFF 36864
#define FSMEM  55296

__global__ __launch_bounds__(256, 2)
void flash_attn_kernel(const __nv_bfloat16* __restrict__ qkv,
                       __nv_bfloat16* __restrict__ o) {
    extern __shared__ __align__(128) uint8_t fsm[];
    uint32_t sbase = smem_u32(fsm);
    int tid = threadIdx.x;
    int q0 = (gridDim.x - 1 - blockIdx.x) * 128;
    int bh = blockIdx.y, b = bh / HH, h = bh - b * HH;
    const size_t rowbase = (size_t)b * SS * D3;
    const int qoff = h * DH, koff = DD + h * DH, voff = 2 * DD + h * DH;

    auto issue_q = [&]() {
        #pragma unroll
        for (int e = 0; e < 4; e++) {
            int idx = tid + e * 256;
            int r = idx >> 3, c = idx & 7;
            cp_async16(sbase + FQ_OFF + r * FQROWB + c * 16,
                       qkv + rowbase + (size_t)(q0 + r) * D3 + qoff + c * 8, true);
        }
        CP_COMMIT();
    };
    auto issue_kv = [&](int t) {
        int kv0 = t * 64;
        uint32_t kd = sbase + FK_OFF + (t & 1) * (64 * FQROWB);
        uint32_t vd = sbase + FV_OFF + (t & 1) * (64 * FQROWB);
        #pragma unroll
        for (int e = 0; e < 2; e++) {
            int idx = tid + e * 256;
            int r = idx >> 3, c = idx & 7;
            const size_t g = rowbase + (size_t)(kv0 + r) * D3;
            cp_async16(kd + r * FQROWB + c * 16, qkv + g + koff + c * 8, true);
            cp_async16(vd + r * FQROWB + c * 16, qkv + g + voff + c * 8, true);
        }
        CP_COMMIT();
    };

    int warp = tid >> 5, lane = tid & 31;
    int lr = lane & 15, lc = lane >> 4;
    int tr = lane >> 2, qd = lane & 3;
    int wq = q0 + warp * 16;

    float of[8][4];
    #pragma unroll
    for (int i = 0; i < 8; i++)
        #pragma unroll
        for (int j = 0; j < 4; j++) of[i][j] = 0.f;
    float m0r = -INFINITY, m1r = -INFINITY, l0r = 0.f, l1r = 0.f;

    int nt = q0 / 64 + 2;
    issue_q();
    issue_kv(0);

    const float sc = 0.03608439182435161f;  // 1/sqrt(768)

    for (int t = 0; t < nt; t++) {
        if (t + 1 < nt) { issue_kv(t + 1); CP_WAIT(1); }
        else            { CP_WAIT(0); }
        __syncthreads();
        int kv0 = t * 64;
        uint32_t kB = sbase + FK_OFF + (t & 1) * (64 * FQROWB);
        uint32_t vB = sbase + FV_OFF + (t & 1) * (64 * FQROWB);

        float sf[8][4];
        #pragma unroll
        for (int i = 0; i < 8; i++)
            #pragma unroll
            for (int j = 0; j < 4; j++) sf[i][j] = 0.f;
        #pragma unroll
        for (int ks = 0; ks < 4; ks++) {
            uint32_t aq[4];
            uint32_t qa = sbase + FQ_OFF + (uint32_t)((warp * 16 + lr) * FQROWB
                                                      + (ks * 16 + lc * 8) * 2);
            ldmatrix_x4(aq[0], aq[1], aq[2], aq[3], qa);
            #pragma unroll
            for (int nb2 = 0; nb2 < 4; nb2++) {
                uint32_t b0, b1, b2, b3;
                uint32_t ka = kB + (uint32_t)((nb2 * 16 + lr) * FQROWB
                                              + (ks * 16 + lc * 8) * 2);
                ldmatrix_x4(b0, b1, b2, b3, ka);
                mma_bf16(sf[nb2 * 2],     aq, b0, b2);
                mma_bf16(sf[nb2 * 2 + 1], aq, b1, b3);
            }
        }
        #pragma unroll
        for (int i = 0; i < 8; i++)
            #pragma unroll
            for (int j = 0; j < 4; j++) sf[i][j] *= sc;
        if (kv0 + 63 > wq) {
            #pragma unroll
            for (int nb = 0; nb < 8; nb++) {
                #pragma unroll
                for (int j = 0; j < 4; j++) {
                    int col = kv0 + nb * 8 + qd * 2 + (j & 1);
                    int row = wq + tr + (j >> 1) * 8;
                    if (col > row) sf[nb][j] = -INFINITY;
                }
            }
        }
        float tm0 = -INFINITY, tm1 = -INFINITY;
        #pragma unroll
        for (int nb = 0; nb < 8; nb++) {
            tm0 = fmaxf(tm0, fmaxf(sf[nb][0], sf[nb][1]));
            tm1 = fmaxf(tm1, fmaxf(sf[nb][2], sf[nb][3]));
        }
        tm0 = fmaxf(tm0, __shfl_xor_sync(0xffffffffu, tm0, 1));
        tm0 = fmaxf(tm0, __shfl_xor_sync(0xffffffffu, tm0, 2));
        tm1 = fmaxf(tm1, __shfl_xor_sync(0xffffffffu, tm1, 1));
        tm1 = fmaxf(tm1, __shfl_xor_sync(0xffffffffu, tm1, 2));
        float mn0 = fmaxf(m0r, tm0), mn1 = fmaxf(m1r, tm1);
        float f0 = __expf(m0r - mn0), f1 = __expf(m1r - mn1);
        m0r = mn0; m1r = mn1;
        float rs0 = 0.f, rs1 = 0.f;
        #pragma unroll
        for (int nb = 0; nb < 8; nb++) {
            sf[nb][0] = __expf(sf[nb][0] - mn0);
            sf[nb][1] = __expf(sf[nb][1] - mn0);
            sf[nb][2] = __expf(sf[nb][2] - mn1);
            sf[nb][3] = __expf(sf[nb][3] - mn1);
            rs0 += sf[nb][0] + sf[nb][1];
            rs1 += sf[nb][2] + sf[nb][3];
        }
        rs0 += __shfl_xor_sync(0xffffffffu, rs0, 1);
        rs0 += __shfl_xor_sync(0xffffffffu, rs0, 2);
        rs1 += __shfl_xor_sync(0xffffffffu, rs1, 1);
        rs1 += __shfl_xor_sync(0xffffffffu, rs1, 2);
        l0r = l0r * f0 + rs0;
        l1r = l1r * f1 + rs1;
        #pragma unroll
        for (int nb = 0; nb < 8; nb++) {
            of[nb][0] *= f0; of[nb][1] *= f0;
            of[nb][2] *= f1; of[nb][3] *= f1;
        }
        #pragma unroll
        for (int ks = 0; ks < 4; ks++) {
            uint32_t ap[4];
            ap[0] = pack_bf16x2(sf[2 * ks][0],     sf[2 * ks][1]);
            ap[1] = pack_bf16x2(sf[2 * ks][2],     sf[2 * ks][3]);
            ap[2] = pack_bf16x2(sf[2 * ks + 1][0], sf[2 * ks + 1][1]);
            ap[3] = pack_bf16x2(sf[2 * ks + 1][2], sf[2 * ks + 1][3]);
            #pragma unroll
            for (int nb2 = 0; nb2 < 4; nb2++) {
                int g = lane >> 3;
                int kvr = ks * 16 + (g & 1) * 8 + (lane & 7);
                int dhc = nb2 * 16 + (g >> 1) * 8;
                uint32_t va = vB + (uint32_t)(kvr * FQROWB + dhc * 2);
                uint32_t r0, r1, r2, r3;
                ldmatrix_x4_trans(r0, r1, r2, r3, va);
                mma_bf16(of[nb2 * 2],     ap, r0, r1);
                mma_bf16(of[nb2 * 2 + 1], ap, r2, r3);
            }
        }
        __syncthreads();
    }

    float inv0 = 1.0f / l0r, inv1 = 1.0f / l1r;
    size_t obase = (size_t)b * SS * DD + (size_t)h * DH;
    #pragma unroll
    for (int nb = 0; nb < 8; nb++) {
        int col = nb * 8 + qd * 2;
        int row0 = wq + tr, row1 = row0 + 8;
        __nv_bfloat162 v0 = __floats2bfloat162_rn(of[nb][0] * inv0, of[nb][1] * inv0);
        __nv_bfloat162 v1 = __floats2bfloat162_rn(of[nb][2] * inv1, of[nb][3] * inv1);
        *reinterpret_cast<__nv_bfloat162*>(o + obase + (size_t)row0 * DD + col) = v0;
        *reinterpret_cast<__nv_bfloat162*>(o + obase + (size_t)row1 * DD + col) = v1;
    }
}

// ---- finish log_softmax from GEMM partials ---------------------------------
__global__ __launch_bounds__(512)
void logsoftmax_finish_kernel(float* __restrict__ logits,
                              const float* __restrict__ pm,
                              const float* __restrict__ ps,
                              const int* __restrict__ target,
                              float* __restrict__ picked) {
    __shared__ float shm[16], shs[16], bc[1];
    int row = blockIdx.x;
    float* x = logits + (size_t)row * VV;
    int t = threadIdx.x, lane = t & 31, wid = t >> 5;

    float m = -INFINITY, s = 0.f;
    const float* pmr = pm + (size_t)row * NT;
    const float* psr = ps + (size_t)row * NT;
    for (int i = t; i < NT; i += 512)
        ms_combine(m, s, pmr[i], psr[i]);
    #pragma unroll
    for (int o = 16; o; o >>= 1) {
        float m2 = __shfl_xor_sync(0xffffffffu, m, o);
        float s2 = __shfl_xor_sync(0xffffffffu, s, o);
        ms_combine(m, s, m2, s2);
    }
    if (lane == 0) { shm[wid] = m; shs[wid] = s; }
    __syncthreads();
    if (t == 0) {
        float M = shm[0], S = shs[0];
        #pragma unroll
        for (int i = 1; i < 16; i++)
            ms_combine(M, S, shm[i], shs[i]);
        bc[0] = M + logf(S);
    }
    __syncthreads();
    float sub = bc[0];
    int tgt = target[row];

    int head = (int)(((16 - ((uintptr_t)x & 15)) & 15) >> 2);
    int nvec = (VV - head) >> 2;
    float* xv = x + head;
    for (int i = t; i < head; i += 512) {
        float lp = x[i] - sub;
        x[i] = lp;
        if (i == tgt) picked[row] = lp;
    }
    for (int i = t; i < nvec; i += 512) {
        float4 v = *reinterpret_cast<const float4*>(xv + i * 4);
        v.x -= sub; v.y -= sub; v.z -= sub; v.w -= sub;
        *reinterpret_cast<float4*>(xv + i * 4) = v;
        int base = head + i * 4;
        if (tgt >= base && tgt < base + 4) {
            float pv = (tgt == base) ? v.x : (tgt == base + 1) ? v.y
                     : (tgt == base + 2) ? v.z : v.w;
            picked[row] = pv;
        }
    }
    for (int i = head + nvec * 4 + t; i < VV; i += 512) {
        float lp = x[i] - sub;
        x[i] = lp;
        if (i == tgt) picked[row] = lp;
    }
}

__global__ void finalize_loss_kernel(const float* __restrict__ picked,
                                     float* __restrict__ out) {
    float s = 0.f;
    for (int i = threadIdx.x; i < MR; i += 256) s += picked[i];
    s = blockReduceSum(s);
    if (threadIdx.x == 0) out[(size_t)MR * VV] = -s * (1.0f / (float)MR);
}

// ---------------- host orchestration ----------------
extern "C" void kernel_launch(void* const* d_in, const int* in_sizes, int n_in,
                              void* d_out, int out_size) {
    const int*   tokens = (const int*)  d_in[0];
    const int*   target = (const int*)  d_in[1];
    const float* wte    = (const float*)d_in[2];
    const float* wpe    = (const float*)d_in[3];
    const float* ln1_g  = (const float*)d_in[4];
    const float* ln1_b  = (const float*)d_in[5];
    const float* qkv_w  = (const float*)d_in[6];
    const float* qkv_b  = (const float*)d_in[7];
    const float* proj_w = (const float*)d_in[8];
    const float* proj_b = (const float*)d_in[9];
    const float* ln2_g  = (const float*)d_in[10];
    const float* ln2_b  = (const float*)d_in[11];
    const float* fc1_w  = (const float*)d_in[12];
    const float* fc1_b  = (const float*)d_in[13];
    const float* fc2_w  = (const float*)d_in[14];
    const float* fc2_b  = (const float*)d_in[15];
    const float* lnf_g  = (const float*)d_in[16];
    const float* lnf_b  = (const float*)d_in[17];
    float* out = (float*)d_out;

    float *gx, *gpicked, *gpm, *gps;
    __nv_bfloat16 *ghb, *gob, *gffb, *gqkvb, *gwteb, *gqkvT, *gprojT, *gfc1T, *gfc2T;
    cudaGetSymbolAddress((void**)&gx,     g_x);
    cudaGetSymbolAddress((void**)&gpicked,g_picked);
    cudaGetSymbolAddress((void**)&gpm,    g_pm);
    cudaGetSymbolAddress((void**)&gps,    g_ps);
    cudaGetSymbolAddress((void**)&ghb,    g_hb);
    cudaGetSymbolAddress((void**)&gob,    g_ob);
    cudaGetSymbolAddress((void**)&gffb,   g_ffb);
    cudaGetSymbolAddress((void**)&gqkvb,  g_qkvb);
    cudaGetSymbolAddress((void**)&gwteb,  g_wteb);
    cudaGetSymbolAddress((void**)&gqkvT,  g_qkvT);
    cudaGetSymbolAddress((void**)&gprojT, g_projT);
    cudaGetSymbolAddress((void**)&gfc1T,  g_fc1T);
    cudaGetSymbolAddress((void**)&gfc2T,  g_fc2T);

    cudaFuncSetAttribute(flash_attn_kernel,
                         cudaFuncAttributeMaxDynamicSharedMemorySize, FSMEM);
    cudaFuncSetAttribute(gemm_mma_kernel<false, 128>,
                         cudaFuncAttributeMaxDynamicSharedMemorySize, GS128);
    cudaFuncSetAttribute(gemm_mma_kernel<true, 128>,
                         cudaFuncAttributeMaxDynamicSharedMemorySize, GS128);
    cudaFuncSetAttribute(gemm_mma_kernel<false, 64>,
                         cudaFuncAttributeMaxDynamicSharedMemorySize, GS64);

    {
        long n4 = (long)VV * DD / 4;
        convert_bf16_kernel4<<<(int)((n4 + 255) / 256), 256>>>(
            (const float4*)wte, (__nv_bfloat162*)gwteb, n4);
    }
    transpose_to_bf16<<<dim3(D3 / 64,  DD / 64,  LL), 256>>>(qkv_w,  gqkvT,  DD,  D3);
    transpose_to_bf16<<<dim3(DD / 64,  DD / 64,  LL), 256>>>(proj_w, gprojT, DD,  DD);
    transpose_to_bf16<<<dim3(FF_ / 64, DD / 64,  LL), 256>>>(fc1_w,  gfc1T,  DD,  FF_);
    transpose_to_bf16<<<dim3(DD / 64,  FF_ / 64, LL), 256>>>(fc2_w,  gfc2T,  FF_, DD);

    embed_kernel<<<(MR * DD + 255) / 256, 256>>>(tokens, wte, wpe, gx);

    for (int l = 0; l < LL; l++) {
        layernorm_kernel<<<MR, 256>>>(gx, ln1_g + (size_t)l * DD, ln1_b + (size_t)l * DD, ghb);

        gemm_mma_kernel<false, 128><<<dim3(MR / GBM, D3 / 128), 256, GS128>>>(
            ghb, gqkvT + (size_t)l * DD * D3, nullptr, gqkvb,
            qkv_b + (size_t)l * D3, nullptr, D3, DD, D3, 0, nullptr, nullptr);

        flash_attn_kernel<<<dim3(SS / 128, BB * HH), 256, FSMEM>>>(gqkvb, gob);

        // proj: N=768 -> BN=64 variant for occupancy (192 CTAs)
        gemm_mma_kernel<false, 64><<<dim3(MR / GBM, DD / 64), 256, GS64>>>(
            gob, gprojT + (size_t)l * DD * DD, gx, nullptr,
            proj_b + (size_t)l * DD, gx, DD, DD, DD, 0, nullptr, nullptr);

        layernorm_kernel<<<MR, 256>>>(gx, ln2_g + (size_t)l * DD, ln2_b + (size_t)l * DD, ghb);

        gemm_mma_kernel<false, 128><<<dim3(MR / GBM, FF_ / 128), 256, GS128>>>(
            ghb, gfc1T + (size_t)l * DD * FF_, nullptr, gffb,
            fc1_b + (size_t)l * FF_, nullptr, FF_, DD, FF_, 1, nullptr, nullptr);

        // fc2: N=768, K=3072 -> BN=64 variant (192 CTAs)
        gemm_mma_kernel<false, 64><<<dim3(MR / GBM, DD / 64), 256, GS64>>>(
            gffb, gfc2T + (size_t)l * FF_ * DD, gx, nullptr,
            fc2_b + (size_t)l * DD, gx, DD, FF_, DD, 0, nullptr, nullptr);
    }

    layernorm_kernel<<<MR, 256>>>(gx, lnf_g, lnf_b, ghb);

    gemm_mma_kernel<true, 128><<<dim3(MR / GBM, NT), 256, GS128>>>(
        ghb, gwteb, out, nullptr, nullptr, nullptr, VV, DD, VV, 0, gpm, gps);

    logsoftmax_finish_kernel<<<MR, 512>>>(out, gpm, gps, target, gpicked);
    finalize_loss_kernel<<<1, 256>>>(gpicked, out);
}

// round 10
// speedup vs baseline: 5.9889x; 1.0470x over previous
#include <cuda_runtime.h>
#include <cuda_bf16.h>
#include <math.h>
#include <stdint.h>

// ---------------- problem constants ----------------
#define BB   2
#define SS   1024
#define DD   768
#define HH   12
#define DH   64
#define FF_  3072
#define LL   12
#define VV   50257
#define MR   2048          // B*S rows
#define D3   2304          // 3*D
#define NT   393           // ceil(VV/128) logits n-tiles

// ---------------- scratch (static device memory) ----------------
__device__ float g_x   [MR * DD];
__device__ float g_picked[MR];
__device__ float g_pm  [MR * NT];
__device__ float g_ps  [MR * NT];

__device__ __nv_bfloat16 g_hb  [MR * DD];
__device__ __nv_bfloat16 g_ob  [MR * DD];
__device__ __nv_bfloat16 g_ffb [MR * FF_];
__device__ __nv_bfloat16 g_qkvb[MR * D3];

__device__ __nv_bfloat16 g_wteb [VV * DD];
__device__ __nv_bfloat16 g_qkvT [LL * DD * D3];
__device__ __nv_bfloat16 g_projT[LL * DD * DD];
__device__ __nv_bfloat16 g_fc1T [LL * DD * FF_];
__device__ __nv_bfloat16 g_fc2T [LL * FF_ * DD];

// ================= low-level helpers (baseline PTX only) =================
__device__ __forceinline__ uint32_t smem_u32(const void* p) {
    uint32_t a;
    asm("{ .reg .u64 t; cvta.to.shared.u64 t, %1; cvt.u32.u64 %0, t; }" : "=r"(a) : "l"(p));
    return a;
}
__device__ __forceinline__ void cp_async16(uint32_t dst, const void* src, bool valid) {
    int sz = valid ? 16 : 0;
    asm volatile("cp.async.cg.shared.global [%0], [%1], 16, %2;"
                 :: "r"(dst), "l"(src), "r"(sz) : "memory");
}
#define CP_COMMIT()  asm volatile("cp.async.commit_group;" ::: "memory")
#define CP_WAIT(n)   asm volatile("cp.async.wait_group %0;" :: "n"(n) : "memory")

__device__ __forceinline__ void ldmatrix_x4(uint32_t& r0, uint32_t& r1,
                                            uint32_t& r2, uint32_t& r3, uint32_t addr) {
    asm volatile("ldmatrix.sync.aligned.m8n8.x4.shared.b16 {%0,%1,%2,%3}, [%4];"
                 : "=r"(r0), "=r"(r1), "=r"(r2), "=r"(r3) : "r"(addr));
}
__device__ __forceinline__ void ldmatrix_x4_trans(uint32_t& r0, uint32_t& r1,
                                                  uint32_t& r2, uint32_t& r3, uint32_t addr) {
    asm volatile("ldmatrix.sync.aligned.m8n8.x4.trans.shared.b16 {%0,%1,%2,%3}, [%4];"
                 : "=r"(r0), "=r"(r1), "=r"(r2), "=r"(r3) : "r"(addr));
}
__device__ __forceinline__ void mma_bf16(float* c, const uint32_t* a,
                                         uint32_t b0, uint32_t b1) {
    asm volatile(
        "mma.sync.aligned.m16n8k16.row.col.f32.bf16.bf16.f32 "
        "{%0,%1,%2,%3}, {%4,%5,%6,%7}, {%8,%9}, {%0,%1,%2,%3};"
        : "+f"(c[0]), "+f"(c[1]), "+f"(c[2]), "+f"(c[3])
        : "r"(a[0]), "r"(a[1]), "r"(a[2]), "r"(a[3]), "r"(b0), "r"(b1));
}
__device__ __forceinline__ uint32_t pack_bf16x2(float lo, float hi) {
    __nv_bfloat162 h = __floats2bfloat162_rn(lo, hi);
    return *reinterpret_cast<uint32_t*>(&h);
}
__device__ __forceinline__ void ms_update(float& m, float& s, float v) {
    if (v > m) { s = s * __expf(m - v) + 1.0f; m = v; }
    else       { s += __expf(v - m); }
}
__device__ __forceinline__ void ms_combine(float& m, float& s, float m2, float s2) {
    float mn = fmaxf(m, m2);
    float e1 = (m  > -INFINITY) ? __expf(m  - mn) : 0.f;
    float e2 = (m2 > -INFINITY) ? __expf(m2 - mn) : 0.f;
    s = s * e1 + s2 * e2;
    m = mn;
}

// ---------------- block reductions ----------------
__device__ __forceinline__ float blockReduceSum(float v) {
    __shared__ float sh[32];
    int lane = threadIdx.x & 31, wid = threadIdx.x >> 5;
    #pragma unroll
    for (int o = 16; o; o >>= 1) v += __shfl_xor_sync(0xffffffffu, v, o);
    __syncthreads();
    if (lane == 0) sh[wid] = v;
    __syncthreads();
    float r = (lane < (int)(blockDim.x >> 5)) ? sh[lane] : 0.f;
    if (wid == 0) {
        #pragma unroll
        for (int o = 16; o; o >>= 1) r += __shfl_xor_sync(0xffffffffu, r, o);
        if (lane == 0) sh[0] = r;
    }
    __syncthreads();
    return sh[0];
}
__device__ __forceinline__ float2 blockReduceSum2(float a, float b) {
    __shared__ float2 sh[8];
    int lane = threadIdx.x & 31, wid = threadIdx.x >> 5;
    #pragma unroll
    for (int o = 16; o; o >>= 1) {
        a += __shfl_xor_sync(0xffffffffu, a, o);
        b += __shfl_xor_sync(0xffffffffu, b, o);
    }
    if (lane == 0) sh[wid] = make_float2(a, b);
    __syncthreads();
    if (wid == 0) {
        float2 r = (lane < 8) ? sh[lane] : make_float2(0.f, 0.f);
        #pragma unroll
        for (int o = 4; o; o >>= 1) {
            r.x += __shfl_xor_sync(0xffffffffu, r.x, o);
            r.y += __shfl_xor_sync(0xffffffffu, r.y, o);
        }
        if (lane == 0) sh[0] = r;
    }
    __syncthreads();
    return sh[0];
}

// ---------------- weight prep ----------------
__global__ void transpose_to_bf16(const float* __restrict__ src,
                                  __nv_bfloat16* __restrict__ dst,
                                  int K, int N) {
    __shared__ float tile[64][65];
    const float* s = src + (size_t)blockIdx.z * K * N;
    __nv_bfloat16* d = dst + (size_t)blockIdx.z * K * N;
    int n0 = blockIdx.x * 64, k0 = blockIdx.y * 64;
    int tid = threadIdx.x;
    #pragma unroll
    for (int e = 0; e < 8; e++) {
        int idx = tid + e * 256;
        int r = idx >> 5, c = idx & 31;
        float2 v = *reinterpret_cast<const float2*>(s + (size_t)(k0 + r) * N + n0 + c * 2);
        tile[c * 2][r]     = v.x;
        tile[c * 2 + 1][r] = v.y;
    }
    __syncthreads();
    #pragma unroll
    for (int e = 0; e < 8; e++) {
        int idx = tid + e * 256;
        int r = idx >> 5, c = (idx & 31) * 2;
        __nv_bfloat162 v = __floats2bfloat162_rn(tile[r][c], tile[r][c + 1]);
        *reinterpret_cast<__nv_bfloat162*>(d + (size_t)(n0 + r) * K + k0 + c) = v;
    }
}

__global__ void convert_bf16_kernel4(const float4* __restrict__ src,
                                     __nv_bfloat162* __restrict__ dst, long n4) {
    long i = (long)blockIdx.x * blockDim.x + threadIdx.x;
    if (i < n4) {
        float4 v = src[i];
        dst[i * 2]     = __floats2bfloat162_rn(v.x, v.y);
        dst[i * 2 + 1] = __floats2bfloat162_rn(v.z, v.w);
    }
}

// ---------------- embedding ----------------
__global__ void embed_kernel(const int* __restrict__ tokens,
                             const float* __restrict__ wte,
                             const float* __restrict__ wpe,
                             float* __restrict__ x) {
    int i = blockIdx.x * blockDim.x + threadIdx.x;
    if (i >= MR * DD) return;
    int row = i / DD, d = i - row * DD;
    int s = row & (SS - 1);
    x[i] = wte[(size_t)tokens[row] * DD + d] + wpe[(size_t)s * DD + d];
}

// ---------------- layernorm -> bf16 ----------------
__global__ void layernorm_kernel(const float* __restrict__ in,
                                 const float* __restrict__ g,
                                 const float* __restrict__ b,
                                 __nv_bfloat16* __restrict__ out) {
    int row = blockIdx.x;
    const float* x = in + (size_t)row * DD;
    int t = threadIdx.x;
    float v0 = x[t], v1 = x[t + 256], v2 = x[t + 512];
    float2 r = blockReduceSum2(v0 + v1 + v2, v0 * v0 + v1 * v1 + v2 * v2);
    float mu = r.x * (1.0f / 768.0f);
    float var = r.y * (1.0f / 768.0f) - mu * mu;
    float rstd = rsqrtf(var + 1e-5f);
    __nv_bfloat16* o = out + (size_t)row * DD;
    o[t]       = __float2bfloat16((v0 - mu) * rstd * g[t]       + b[t]);
    o[t + 256] = __float2bfloat16((v1 - mu) * rstd * g[t + 256] + b[t + 256]);
    o[t + 512] = __float2bfloat16((v2 - mu) * rstd * g[t + 512] + b[t + 512]);
}

// ================= mma.sync NT GEMM, templated BN / ATOMIC split-K ==========
#define GBM 128
#define GBK 64
#define ROWB 144
#define ABUF 18432   // 128 * 144

// ATOMIC=true: grid.z splits K; each CTA atomicAdd's its partial into Cf
// (Cf must be pre-loaded with the residual). bias added only by z==0.
template <bool FUSE, int BN, bool ATOMIC>
__global__ __launch_bounds__(256, 2)
void gemm_mma_kernel(const __nv_bfloat16* __restrict__ A,
                     const __nv_bfloat16* __restrict__ B,
                     float* __restrict__ Cf,
                     __nv_bfloat16* __restrict__ Cbf,
                     const float* __restrict__ bias,
                     const float* __restrict__ res,
                     int N, int K, int ldc, int act,
                     float* __restrict__ pm, float* __restrict__ ps) {
    constexpr int BBUF = BN * ROWB;
    constexpr int BUFS = ABUF + BBUF;
    constexpr int NNB  = BN / 32;
    extern __shared__ __align__(128) uint8_t gsm[];
    uint32_t sbase = smem_u32(gsm);
    int tid = threadIdx.x;
    int m0 = blockIdx.x * GBM, n0 = blockIdx.y * BN;
    int nk = K / GBK;
    int kbase = 0;
    if (ATOMIC) {
        nk = K / GBK / gridDim.z;
        kbase = blockIdx.z * nk;
    }

    auto issue = [&](int c) {
        int k0 = (kbase + c) * GBK;
        int st = c % 3;
        uint32_t dA = sbase + st * BUFS;
        uint32_t dB = dA + ABUF;
        #pragma unroll
        for (int e = 0; e < 4; e++) {
            int idx = tid + e * 256;
            int r = idx >> 3, cc = idx & 7;
            cp_async16(dA + r * ROWB + cc * 16,
                       A + (size_t)(m0 + r) * K + k0 + cc * 8, true);
        }
        #pragma unroll
        for (int e = 0; e < BN / 32; e++) {
            int idx = tid + e * 256;
            int r = idx >> 3, cc = idx & 7;
            int gn = n0 + r;
            cp_async16(dB + r * ROWB + cc * 16,
                       B + (size_t)gn * K + k0 + cc * 8, gn < N);
        }
        CP_COMMIT();
    };

    int warp = tid >> 5, lane = tid & 31;
    int wm = warp >> 1, wn = warp & 1;
    int lr = lane & 15, lc = lane >> 4;
    float acc[2][2 * NNB][4];
    #pragma unroll
    for (int i = 0; i < 2; i++)
        #pragma unroll
        for (int j = 0; j < 2 * NNB; j++)
            #pragma unroll
            for (int q = 0; q < 4; q++) acc[i][j][q] = 0.f;

    issue(0);
    if (nk > 1) issue(1);
    for (int c = 0; c < nk; c++) {
        if (c + 2 < nk) { issue(c + 2); CP_WAIT(2); }
        else if (c + 1 < nk) { CP_WAIT(1); }
        else { CP_WAIT(0); }
        __syncthreads();
        uint32_t aB = sbase + (c % 3) * BUFS;
        uint32_t bB = aB + ABUF;
        #pragma unroll
        for (int kk = 0; kk < 4; kk++) {
            uint32_t a[2][4];
            #pragma unroll
            for (int mi = 0; mi < 2; mi++) {
                uint32_t addr = aB + (uint32_t)((wm * 32 + mi * 16 + lr) * ROWB
                                                + (kk * 16 + lc * 8) * 2);
                ldmatrix_x4(a[mi][0], a[mi][1], a[mi][2], a[mi][3], addr);
            }
            #pragma unroll
            for (int nb = 0; nb < NNB; nb++) {
                uint32_t b0, b1, b2, b3;
                uint32_t addr = bB + (uint32_t)((wn * (BN / 2) + nb * 16 + lr) * ROWB
                                                + (kk * 16 + lc * 8) * 2);
                ldmatrix_x4(b0, b1, b2, b3, addr);
                #pragma unroll
                for (int mi = 0; mi < 2; mi++) {
                    mma_bf16(acc[mi][nb * 2],     a[mi], b0, b2);
                    mma_bf16(acc[mi][nb * 2 + 1], a[mi], b1, b3);
                }
            }
        }
        __syncthreads();
    }

    // --- epilogue ---
    int mrow = m0 + wm * 32;
    int ncol = n0 + wn * (BN / 2);
    int tr = lane >> 2, tc = (lane & 3) * 2;
    bool vec = ((ldc & 1) == 0);
    float tm[2][2], ts[2][2];
    if (FUSE) {
        #pragma unroll
        for (int i = 0; i < 2; i++)
            #pragma unroll
            for (int j = 0; j < 2; j++) { tm[i][j] = -INFINITY; ts[i][j] = 0.f; }
    }
    #pragma unroll
    for (int mi = 0; mi < 2; mi++) {
        #pragma unroll
        for (int ni = 0; ni < 2 * NNB; ni++) {
            #pragma unroll
            for (int h = 0; h < 2; h++) {
                int row = mrow + mi * 16 + tr + h * 8;
                int col = ncol + ni * 8 + tc;
                float v0 = acc[mi][ni][h * 2];
                float v1 = acc[mi][ni][h * 2 + 1];
                if (ATOMIC) {
                    if (bias && blockIdx.z == 0) {
                        v0 += bias[col];
                        if (col + 1 < N) v1 += bias[col + 1];
                    }
                    if (col < N)     atomicAdd(Cf + (size_t)row * ldc + col, v0);
                    if (col + 1 < N) atomicAdd(Cf + (size_t)row * ldc + col + 1, v1);
                    continue;
                }
                if (bias) { v0 += bias[col]; if (col + 1 < N) v1 += bias[col + 1]; }
                if (res) {
                    const float* rp = res + (size_t)row * ldc + col;
                    v0 += rp[0];
                    if (col + 1 < N) v1 += rp[1];
                }
                if (act) {
                    v0 = v0 * 0.5f * (1.0f + erff(v0 * 0.70710678118654752f));
                    v1 = v1 * 0.5f * (1.0f + erff(v1 * 0.70710678118654752f));
                }
                if (FUSE) {
                    if (col < N)     ms_update(tm[mi][h], ts[mi][h], v0);
                    if (col + 1 < N) ms_update(tm[mi][h], ts[mi][h], v1);
                }
                if (vec && col + 1 < N) {
                    if (Cf) *reinterpret_cast<float2*>(Cf + (size_t)row * ldc + col)
                                = make_float2(v0, v1);
                    else    *reinterpret_cast<__nv_bfloat162*>(Cbf + (size_t)row * ldc + col)
                                = __floats2bfloat162_rn(v0, v1);
                } else {
                    if (col < N) {
                        if (Cf) Cf[(size_t)row * ldc + col] = v0;
                        else    Cbf[(size_t)row * ldc + col] = __float2bfloat16(v0);
                    }
                    if (col + 1 < N) {
                        if (Cf) Cf[(size_t)row * ldc + col + 1] = v1;
                        else    Cbf[(size_t)row * ldc + col + 1] = __float2bfloat16(v1);
                    }
                }
            }
        }
    }
    if (FUSE) {
        float2* red = reinterpret_cast<float2*>(gsm);
        #pragma unroll
        for (int mi = 0; mi < 2; mi++) {
            #pragma unroll
            for (int h = 0; h < 2; h++) {
                float m = tm[mi][h], s = ts[mi][h];
                #pragma unroll
                for (int o = 1; o <= 2; o <<= 1) {
                    float m2 = __shfl_xor_sync(0xffffffffu, m, o);
                    float s2 = __shfl_xor_sync(0xffffffffu, s, o);
                    ms_combine(m, s, m2, s2);
                }
                if ((lane & 3) == 0) {
                    int row_local = wm * 32 + mi * 16 + tr + h * 8;
                    red[row_local * 2 + wn] = make_float2(m, s);
                }
            }
        }
        __syncthreads();
        if (tid < 128) {
            float2 p0 = red[tid * 2], p1 = red[tid * 2 + 1];
            float m = p0.x, s = p0.y;
            ms_combine(m, s, p1.x, p1.y);
            pm[(size_t)(m0 + tid) * NT + blockIdx.y] = m;
            ps[(size_t)(m0 + tid) * NT + blockIdx.y] = s;
        }
    }
}

#define GS128 (3 * (ABUF + 128 * ROWB))   // 110592
#define GS64  (3 * (ABUF + 64 * ROWB))    // 82944

// ================= fused flash attention (bf16 tensor cores) =================
#define FQROWB 144
#define FQ_OFF 0
#define FK_OFF 18432
#define FV_OFF 36864
#define FSMEM  55296

__global__ __launch_bounds__(256, 2)
void flash_attn_kernel(const __nv_bfloat16* __restrict__ qkv,
                       __nv_bfloat16* __restrict__ o) {
    extern __shared__ __align__(128) uint8_t fsm[];
    uint32_t sbase = smem_u32(fsm);
    int tid = threadIdx.x;
    int q0 = (gridDim.x - 1 - blockIdx.x) * 128;
    int bh = blockIdx.y, b = bh / HH, h = bh - b * HH;
    const size_t rowbase = (size_t)b * SS * D3;
    const int qoff = h * DH, koff = DD + h * DH, voff = 2 * DD + h * DH;

    auto issue_q = [&]() {
        #pragma unroll
        for (int e = 0; e < 4; e++) {
            int idx = tid + e * 256;
            int r = idx >> 3, c = idx & 7;
            cp_async16(sbase + FQ_OFF + r * FQROWB + c * 16,
                       qkv + rowbase + (size_t)(q0 + r) * D3 + qoff + c * 8, true);
        }
        CP_COMMIT();
    };
    auto issue_kv = [&](int t) {
        int kv0 = t * 64;
        uint32_t kd = sbase + FK_OFF + (t & 1) * (64 * FQROWB);
        uint32_t vd = sbase + FV_OFF + (t & 1) * (64 * FQROWB);
        #pragma unroll
        for (int e = 0; e < 2; e++) {
            int idx = tid + e * 256;
            int r = idx >> 3, c = idx & 7;
            const size_t g = rowbase + (size_t)(kv0 + r) * D3;
            cp_async16(kd + r * FQROWB + c * 16, qkv + g + koff + c * 8, true);
            cp_async16(vd + r * FQROWB + c * 16, qkv + g + voff + c * 8, true);
        }
        CP_COMMIT();
    };

    int warp = tid >> 5, lane = tid & 31;
    int lr = lane & 15, lc = lane >> 4;
    int tr = lane >> 2, qd = lane & 3;
    int wq = q0 + warp * 16;

    float of[8][4];
    #pragma unroll
    for (int i = 0; i < 8; i++)
        #pragma unroll
        for (int j = 0; j < 4; j++) of[i][j] = 0.f;
    float m0r = -INFINITY, m1r = -INFINITY, l0r = 0.f, l1r = 0.f;

    int nt = q0 / 64 + 2;
    issue_q();
    issue_kv(0);

    const float sc = 0.03608439182435161f;  // 1/sqrt(768)

    for (int t = 0; t < nt; t++) {
        if (t + 1 < nt) { issue_kv(t + 1); CP_WAIT(1); }
        else            { CP_WAIT(0); }
        __syncthreads();
        int kv0 = t * 64;
        uint32_t kB = sbase + FK_OFF + (t & 1) * (64 * FQROWB);
        uint32_t vB = sbase + FV_OFF + (t & 1) * (64 * FQROWB);

        float sf[8][4];
        #pragma unroll
        for (int i = 0; i < 8; i++)
            #pragma unroll
            for (int j = 0; j < 4; j++) sf[i][j] = 0.f;
        #pragma unroll
        for (int ks = 0; ks < 4; ks++) {
            uint32_t aq[4];
            uint32_t qa = sbase + FQ_OFF + (uint32_t)((warp * 16 + lr) * FQROWB
                                                      + (ks * 16 + lc * 8) * 2);
            ldmatrix_x4(aq[0], aq[1], aq[2], aq[3], qa);
            #pragma unroll
            for (int nb2 = 0; nb2 < 4; nb2++) {
                uint32_t b0, b1, b2, b3;
                uint32_t ka = kB + (uint32_t)((nb2 * 16 + lr) * FQROWB
                                              + (ks * 16 + lc * 8) * 2);
                ldmatrix_x4(b0, b1, b2, b3, ka);
                mma_bf16(sf[nb2 * 2],     aq, b0, b2);
                mma_bf16(sf[nb2 * 2 + 1], aq, b1, b3);
            }
        }
        #pragma unroll
        for (int i = 0; i < 8; i++)
            #pragma unroll
            for (int j = 0; j < 4; j++) sf[i][j] *= sc;
        if (kv0 + 63 > wq) {
            #pragma unroll
            for (int nb = 0; nb < 8; nb++) {
                #pragma unroll
                for (int j = 0; j < 4; j++) {
                    int col = kv0 + nb * 8 + qd * 2 + (j & 1);
                    int row = wq + tr + (j >> 1) * 8;
                    if (col > row) sf[nb][j] = -INFINITY;
                }
            }
        }
        float tm0 = -INFINITY, tm1 = -INFINITY;
        #pragma unroll
        for (int nb = 0; nb < 8; nb++) {
            tm0 = fmaxf(tm0, fmaxf(sf[nb][0], sf[nb][1]));
            tm1 = fmaxf(tm1, fmaxf(sf[nb][2], sf[nb][3]));
        }
        tm0 = fmaxf(tm0, __shfl_xor_sync(0xffffffffu, tm0, 1));
        tm0 = fmaxf(tm0, __shfl_xor_sync(0xffffffffu, tm0, 2));
        tm1 = fmaxf(tm1, __shfl_xor_sync(0xffffffffu, tm1, 1));
        tm1 = fmaxf(tm1, __shfl_xor_sync(0xffffffffu, tm1, 2));
        float mn0 = fmaxf(m0r, tm0), mn1 = fmaxf(m1r, tm1);
        float f0 = __expf(m0r - mn0), f1 = __expf(m1r - mn1);
        m0r = mn0; m1r = mn1;
        float rs0 = 0.f, rs1 = 0.f;
        #pragma unroll
        for (int nb = 0; nb < 8; nb++) {
            sf[nb][0] = __expf(sf[nb][0] - mn0);
            sf[nb][1] = __expf(sf[nb][1] - mn0);
            sf[nb][2] = __expf(sf[nb][2] - mn1);
            sf[nb][3] = __expf(sf[nb][3] - mn1);
            rs0 += sf[nb][0] + sf[nb][1];
            rs1 += sf[nb][2] + sf[nb][3];
        }
        rs0 += __shfl_xor_sync(0xffffffffu, rs0, 1);
        rs0 += __shfl_xor_sync(0xffffffffu, rs0, 2);
        rs1 += __shfl_xor_sync(0xffffffffu, rs1, 1);
        rs1 += __shfl_xor_sync(0xffffffffu, rs1, 2);
        l0r = l0r * f0 + rs0;
        l1r = l1r * f1 + rs1;
        #pragma unroll
        for (int nb = 0; nb < 8; nb++) {
            of[nb][0] *= f0; of[nb][1] *= f0;
            of[nb][2] *= f1; of[nb][3] *= f1;
        }
        #pragma unroll
        for (int ks = 0; ks < 4; ks++) {
            uint32_t ap[4];
            ap[0] = pack_bf16x2(sf[2 * ks][0],     sf[2 * ks][1]);
            ap[1] = pack_bf16x2(sf[2 * ks][2],     sf[2 * ks][3]);
            ap[2] = pack_bf16x2(sf[2 * ks + 1][0], sf[2 * ks + 1][1]);
            ap[3] = pack_bf16x2(sf[2 * ks + 1][2], sf[2 * ks + 1][3]);
            #pragma unroll
            for (int nb2 = 0; nb2 < 4; nb2++) {
                int g = lane >> 3;
                int kvr = ks * 16 + (g & 1) * 8 + (lane & 7);
                int dhc = nb2 * 16 + (g >> 1) * 8;
                uint32_t va = vB + (uint32_t)(kvr * FQROWB + dhc * 2);
                uint32_t r0, r1, r2, r3;
                ldmatrix_x4_trans(r0, r1, r2, r3, va);
                mma_bf16(of[nb2 * 2],     ap, r0, r1);
                mma_bf16(of[nb2 * 2 + 1], ap, r2, r3);
            }
        }
        __syncthreads();
    }

    float inv0 = 1.0f / l0r, inv1 = 1.0f / l1r;
    size_t obase = (size_t)b * SS * DD + (size_t)h * DH;
    #pragma unroll
    for (int nb = 0; nb < 8; nb++) {
        int col = nb * 8 + qd * 2;
        int row0 = wq + tr, row1 = row0 + 8;
        __nv_bfloat162 v0 = __floats2bfloat162_rn(of[nb][0] * inv0, of[nb][1] * inv0);
        __nv_bfloat162 v1 = __floats2bfloat162_rn(of[nb][2] * inv1, of[nb][3] * inv1);
        *reinterpret_cast<__nv_bfloat162*>(o + obase + (size_t)row0 * DD + col) = v0;
        *reinterpret_cast<__nv_bfloat162*>(o + obase + (size_t)row1 * DD + col) = v1;
    }
}

// ---- finish log_softmax from GEMM partials ---------------------------------
__global__ __launch_bounds__(512)
void logsoftmax_finish_kernel(float* __restrict__ logits,
                              const float* __restrict__ pm,
                              const float* __restrict__ ps,
                              const int* __restrict__ target,
                              float* __restrict__ picked) {
    __shared__ float shm[16], shs[16], bc[1];
    int row = blockIdx.x;
    float* x = logits + (size_t)row * VV;
    int t = threadIdx.x, lane = t & 31, wid = t >> 5;

    float m = -INFINITY, s = 0.f;
    const float* pmr = pm + (size_t)row * NT;
    const float* psr = ps + (size_t)row * NT;
    for (int i = t; i < NT; i += 512)
        ms_combine(m, s, pmr[i], psr[i]);
    #pragma unroll
    for (int o = 16; o; o >>= 1) {
        float m2 = __shfl_xor_sync(0xffffffffu, m, o);
        float s2 = __shfl_xor_sync(0xffffffffu, s, o);
        ms_combine(m, s, m2, s2);
    }
    if (lane == 0) { shm[wid] = m; shs[wid] = s; }
    __syncthreads();
    if (t == 0) {
        float M = shm[0], S = shs[0];
        #pragma unroll
        for (int i = 1; i < 16; i++)
            ms_combine(M, S, shm[i], shs[i]);
        bc[0] = M + logf(S);
    }
    __syncthreads();
    float sub = bc[0];
    int tgt = target[row];

    int head = (int)(((16 - ((uintptr_t)x & 15)) & 15) >> 2);
    int nvec = (VV - head) >> 2;
    float* xv = x + head;
    for (int i = t; i < head; i += 512) {
        float lp = x[i] - sub;
        x[i] = lp;
        if (i == tgt) picked[row] = lp;
    }
    for (int i = t; i < nvec; i += 512) {
        float4 v = *reinterpret_cast<const float4*>(xv + i * 4);
        v.x -= sub; v.y -= sub; v.z -= sub; v.w -= sub;
        *reinterpret_cast<float4*>(xv + i * 4) = v;
        int base = head + i * 4;
        if (tgt >= base && tgt < base + 4) {
            float pv = (tgt == base) ? v.x : (tgt == base + 1) ? v.y
                     : (tgt == base + 2) ? v.z : v.w;
            picked[row] = pv;
        }
    }
    for (int i = head + nvec * 4 + t; i < VV; i += 512) {
        float lp = x[i] - sub;
        x[i] = lp;
        if (i == tgt) picked[row] = lp;
    }
}

__global__ void finalize_loss_kernel(const float* __restrict__ picked,
                                     float* __restrict__ out) {
    float s = 0.f;
    for (int i = threadIdx.x; i < MR; i += 256) s += picked[i];
    s = blockReduceSum(s);
    if (threadIdx.x == 0) out[(size_t)MR * VV] = -s * (1.0f / (float)MR);
}

// ---------------- host orchestration ----------------
extern "C" void kernel_launch(void* const* d_in, const int* in_sizes, int n_in,
                              void* d_out, int out_size) {
    const int*   tokens = (const int*)  d_in[0];
    const int*   target = (const int*)  d_in[1];
    const float* wte    = (const float*)d_in[2];
    const float* wpe    = (const float*)d_in[3];
    const float* ln1_g  = (const float*)d_in[4];
    const float* ln1_b  = (const float*)d_in[5];
    const float* qkv_w  = (const float*)d_in[6];
    const float* qkv_b  = (const float*)d_in[7];
    const float* proj_w = (const float*)d_in[8];
    const float* proj_b = (const float*)d_in[9];
    const float* ln2_g  = (const float*)d_in[10];
    const float* ln2_b  = (const float*)d_in[11];
    const float* fc1_w  = (const float*)d_in[12];
    const float* fc1_b  = (const float*)d_in[13];
    const float* fc2_w  = (const float*)d_in[14];
    const float* fc2_b  = (const float*)d_in[15];
    const float* lnf_g  = (const float*)d_in[16];
    const float* lnf_b  = (const float*)d_in[17];
    float* out = (float*)d_out;

    float *gx, *gpicked, *gpm, *gps;
    __nv_bfloat16 *ghb, *gob, *gffb, *gqkvb, *gwteb, *gqkvT, *gprojT, *gfc1T, *gfc2T;
    cudaGetSymbolAddress((void**)&gx,     g_x);
    cudaGetSymbolAddress((void**)&gpicked,g_picked);
    cudaGetSymbolAddress((void**)&gpm,    g_pm);
    cudaGetSymbolAddress((void**)&gps,    g_ps);
    cudaGetSymbolAddress((void**)&ghb,    g_hb);
    cudaGetSymbolAddress((void**)&gob,    g_ob);
    cudaGetSymbolAddress((void**)&gffb,   g_ffb);
    cudaGetSymbolAddress((void**)&gqkvb,  g_qkvb);
    cudaGetSymbolAddress((void**)&gwteb,  g_wteb);
    cudaGetSymbolAddress((void**)&gqkvT,  g_qkvT);
    cudaGetSymbolAddress((void**)&gprojT, g_projT);
    cudaGetSymbolAddress((void**)&gfc1T,  g_fc1T);
    cudaGetSymbolAddress((void**)&gfc2T,  g_fc2T);

    cudaFuncSetAttribute(flash_attn_kernel,
                         cudaFuncAttributeMaxDynamicSharedMemorySize, FSMEM);
    cudaFuncSetAttribute(gemm_mma_kernel<false, 128, false>,
                         cudaFuncAttributeMaxDynamicSharedMemorySize, GS128);
    cudaFuncSetAttribute(gemm_mma_kernel<true, 128, false>,
                         cudaFuncAttributeMaxDynamicSharedMemorySize, GS128);
    cudaFuncSetAttribute(gemm_mma_kernel<false, 64, false>,
                         cudaFuncAttributeMaxDynamicSharedMemorySize, GS64);
    cudaFuncSetAttribute(gemm_mma_kernel<false, 64, true>,
                         cudaFuncAttributeMaxDynamicSharedMemorySize, GS64);

    {
        long n4 = (long)VV * DD / 4;
        convert_bf16_kernel4<<<(int)((n4 + 255) / 256), 256>>>(
            (const float4*)wte, (__nv_bfloat162*)gwteb, n4);
    }
    transpose_to_bf16<<<dim3(D3 / 64,  DD / 64,  LL), 256>>>(qkv_w,  gqkvT,  DD,  D3);
    transpose_to_bf16<<<dim3(DD / 64,  DD / 64,  LL), 256>>>(proj_w, gprojT, DD,  DD);
    transpose_to_bf16<<<dim3(FF_ / 64, DD / 64,  LL), 256>>>(fc1_w,  gfc1T,  DD,  FF_);
    transpose_to_bf16<<<dim3(DD / 64,  FF_ / 64, LL), 256>>>(fc2_w,  gfc2T,  FF_, DD);

    embed_kernel<<<(MR * DD + 255) / 256, 256>>>(tokens, wte, wpe, gx);

    for (int l = 0; l < LL; l++) {
        layernorm_kernel<<<MR, 256>>>(gx, ln1_g + (size_t)l * DD, ln1_b + (size_t)l * DD, ghb);

        gemm_mma_kernel<false, 128, false><<<dim3(MR / GBM, D3 / 128), 256, GS128>>>(
            ghb, gqkvT + (size_t)l * DD * D3, nullptr, gqkvb,
            qkv_b + (size_t)l * D3, nullptr, D3, DD, D3, 0, nullptr, nullptr);

        flash_attn_kernel<<<dim3(SS / 128, BB * HH), 256, FSMEM>>>(gqkvb, gob);

        // proj: split-K=2, atomic accumulate into gx (gx holds residual)
        gemm_mma_kernel<false, 64, true><<<dim3(MR / GBM, DD / 64, 2), 256, GS64>>>(
            gob, gprojT + (size_t)l * DD * DD, gx, nullptr,
            proj_b + (size_t)l * DD, nullptr, DD, DD, DD, 0, nullptr, nullptr);

        layernorm_kernel<<<MR, 256>>>(gx, ln2_g + (size_t)l * DD, ln2_b + (size_t)l * DD, ghb);

        // fc1: BN=64 for finer wave quantization (768 CTAs)
        gemm_mma_kernel<false, 64, false><<<dim3(MR / GBM, FF_ / 64), 256, GS64>>>(
            ghb, gfc1T + (size_t)l * DD * FF_, nullptr, gffb,
            fc1_b + (size_t)l * FF_, nullptr, FF_, DD, FF_, 1, nullptr, nullptr);

        // fc2: split-K=2, atomic accumulate into gx
        gemm_mma_kernel<false, 64, true><<<dim3(MR / GBM, DD / 64, 2), 256, GS64>>>(
            gffb, gfc2T + (size_t)l * FF_ * DD, gx, nullptr,
            fc2_b + (size_t)l * DD, nullptr, DD, FF_, DD, 0, nullptr, nullptr);
    }

    layernorm_kernel<<<MR, 256>>>(gx, lnf_g, lnf_b, ghb);

    gemm_mma_kernel<true, 128, false><<<dim3(MR / GBM, NT), 256, GS128>>>(
        ghb, gwteb, out, nullptr, nullptr, nullptr, VV, DD, VV, 0, gpm, gps);

    logsoftmax_finish_kernel<<<MR, 512>>>(out, gpm, gps, target, gpicked);
    finalize_loss_kernel<<<1, 256>>>(gpicked, out);
}

// round 11
// speedup vs baseline: 6.2814x; 1.0488x over previous
#include <cuda_runtime.h>
#include <cuda_bf16.h>
#include <math.h>
#include <stdint.h>

// ---------------- problem constants ----------------
#define BB   2
#define SS   1024
#define DD   768
#define HH   12
#define DH   64
#define FF_  3072
#define LL   12
#define VV   50257
#define MR   2048          // B*S rows
#define D3   2304          // 3*D
#define NT   393           // ceil(VV/128) logits n-tiles

// ---------------- scratch (static device memory) ----------------
__device__ float g_x   [MR * DD];
__device__ float g_picked[MR];
__device__ float g_pm  [MR * NT];
__device__ float g_ps  [MR * NT];

__device__ __nv_bfloat16 g_hb  [MR * DD];
__device__ __nv_bfloat16 g_ob  [MR * DD];
__device__ __nv_bfloat16 g_ffb [MR * FF_];
__device__ __nv_bfloat16 g_qkvb[MR * D3];

__device__ __nv_bfloat16 g_wteb [VV * DD];
__device__ __nv_bfloat16 g_qkvT [LL * DD * D3];
__device__ __nv_bfloat16 g_projT[LL * DD * DD];
__device__ __nv_bfloat16 g_fc1T [LL * DD * FF_];
__device__ __nv_bfloat16 g_fc2T [LL * FF_ * DD];

// ================= low-level helpers (baseline PTX only) =================
__device__ __forceinline__ uint32_t smem_u32(const void* p) {
    uint32_t a;
    asm("{ .reg .u64 t; cvta.to.shared.u64 t, %1; cvt.u32.u64 %0, t; }" : "=r"(a) : "l"(p));
    return a;
}
__device__ __forceinline__ void cp_async16(uint32_t dst, const void* src, bool valid) {
    int sz = valid ? 16 : 0;
    asm volatile("cp.async.cg.shared.global [%0], [%1], 16, %2;"
                 :: "r"(dst), "l"(src), "r"(sz) : "memory");
}
#define CP_COMMIT()  asm volatile("cp.async.commit_group;" ::: "memory")
#define CP_WAIT(n)   asm volatile("cp.async.wait_group %0;" :: "n"(n) : "memory")

__device__ __forceinline__ void ldmatrix_x4(uint32_t& r0, uint32_t& r1,
                                            uint32_t& r2, uint32_t& r3, uint32_t addr) {
    asm volatile("ldmatrix.sync.aligned.m8n8.x4.shared.b16 {%0,%1,%2,%3}, [%4];"
                 : "=r"(r0), "=r"(r1), "=r"(r2), "=r"(r3) : "r"(addr));
}
__device__ __forceinline__ void ldmatrix_x4_trans(uint32_t& r0, uint32_t& r1,
                                                  uint32_t& r2, uint32_t& r3, uint32_t addr) {
    asm volatile("ldmatrix.sync.aligned.m8n8.x4.trans.shared.b16 {%0,%1,%2,%3}, [%4];"
                 : "=r"(r0), "=r"(r1), "=r"(r2), "=r"(r3) : "r"(addr));
}
__device__ __forceinline__ void mma_bf16(float* c, const uint32_t* a,
                                         uint32_t b0, uint32_t b1) {
    asm volatile(
        "mma.sync.aligned.m16n8k16.row.col.f32.bf16.bf16.f32 "
        "{%0,%1,%2,%3}, {%4,%5,%6,%7}, {%8,%9}, {%0,%1,%2,%3};"
        : "+f"(c[0]), "+f"(c[1]), "+f"(c[2]), "+f"(c[3])
        : "r"(a[0]), "r"(a[1]), "r"(a[2]), "r"(a[3]), "r"(b0), "r"(b1));
}
__device__ __forceinline__ uint32_t pack_bf16x2(float lo, float hi) {
    __nv_bfloat162 h = __floats2bfloat162_rn(lo, hi);
    return *reinterpret_cast<uint32_t*>(&h);
}
__device__ __forceinline__ void ms_update(float& m, float& s, float v) {
    if (v > m) { s = s * __expf(m - v) + 1.0f; m = v; }
    else       { s += __expf(v - m); }
}
__device__ __forceinline__ void ms_combine(float& m, float& s, float m2, float s2) {
    float mn = fmaxf(m, m2);
    float e1 = (m  > -INFINITY) ? __expf(m  - mn) : 0.f;
    float e2 = (m2 > -INFINITY) ? __expf(m2 - mn) : 0.f;
    s = s * e1 + s2 * e2;
    m = mn;
}

// ---------------- block reductions ----------------
__device__ __forceinline__ float blockReduceSum(float v) {
    __shared__ float sh[32];
    int lane = threadIdx.x & 31, wid = threadIdx.x >> 5;
    #pragma unroll
    for (int o = 16; o; o >>= 1) v += __shfl_xor_sync(0xffffffffu, v, o);
    __syncthreads();
    if (lane == 0) sh[wid] = v;
    __syncthreads();
    float r = (lane < (int)(blockDim.x >> 5)) ? sh[lane] : 0.f;
    if (wid == 0) {
        #pragma unroll
        for (int o = 16; o; o >>= 1) r += __shfl_xor_sync(0xffffffffu, r, o);
        if (lane == 0) sh[0] = r;
    }
    __syncthreads();
    return sh[0];
}
__device__ __forceinline__ float2 blockReduceSum2(float a, float b) {
    __shared__ float2 sh[8];
    int lane = threadIdx.x & 31, wid = threadIdx.x >> 5;
    #pragma unroll
    for (int o = 16; o; o >>= 1) {
        a += __shfl_xor_sync(0xffffffffu, a, o);
        b += __shfl_xor_sync(0xffffffffu, b, o);
    }
    if (lane == 0) sh[wid] = make_float2(a, b);
    __syncthreads();
    if (wid == 0) {
        float2 r = (lane < 8) ? sh[lane] : make_float2(0.f, 0.f);
        #pragma unroll
        for (int o = 4; o; o >>= 1) {
            r.x += __shfl_xor_sync(0xffffffffu, r.x, o);
            r.y += __shfl_xor_sync(0xffffffffu, r.y, o);
        }
        if (lane == 0) sh[0] = r;
    }
    __syncthreads();
    return sh[0];
}

// ---------------- weight prep ----------------
__global__ void transpose_to_bf16(const float* __restrict__ src,
                                  __nv_bfloat16* __restrict__ dst,
                                  int K, int N) {
    __shared__ float tile[64][65];
    const float* s = src + (size_t)blockIdx.z * K * N;
    __nv_bfloat16* d = dst + (size_t)blockIdx.z * K * N;
    int n0 = blockIdx.x * 64, k0 = blockIdx.y * 64;
    int tid = threadIdx.x;
    #pragma unroll
    for (int e = 0; e < 8; e++) {
        int idx = tid + e * 256;
        int r = idx >> 5, c = idx & 31;
        float2 v = *reinterpret_cast<const float2*>(s + (size_t)(k0 + r) * N + n0 + c * 2);
        tile[c * 2][r]     = v.x;
        tile[c * 2 + 1][r] = v.y;
    }
    __syncthreads();
    #pragma unroll
    for (int e = 0; e < 8; e++) {
        int idx = tid + e * 256;
        int r = idx >> 5, c = (idx & 31) * 2;
        __nv_bfloat162 v = __floats2bfloat162_rn(tile[r][c], tile[r][c + 1]);
        *reinterpret_cast<__nv_bfloat162*>(d + (size_t)(n0 + r) * K + k0 + c) = v;
    }
}

__global__ void convert_bf16_kernel4(const float4* __restrict__ src,
                                     __nv_bfloat162* __restrict__ dst, long n4) {
    long i = (long)blockIdx.x * blockDim.x + threadIdx.x;
    if (i < n4) {
        float4 v = src[i];
        dst[i * 2]     = __floats2bfloat162_rn(v.x, v.y);
        dst[i * 2 + 1] = __floats2bfloat162_rn(v.z, v.w);
    }
}

// ---------------- embedding ----------------
__global__ void embed_kernel(const int* __restrict__ tokens,
                             const float* __restrict__ wte,
                             const float* __restrict__ wpe,
                             float* __restrict__ x) {
    int i = blockIdx.x * blockDim.x + threadIdx.x;
    if (i >= MR * DD) return;
    int row = i / DD, d = i - row * DD;
    int s = row & (SS - 1);
    x[i] = wte[(size_t)tokens[row] * DD + d] + wpe[(size_t)s * DD + d];
}

// ---------------- layernorm -> bf16 ----------------
__global__ void layernorm_kernel(const float* __restrict__ in,
                                 const float* __restrict__ g,
                                 const float* __restrict__ b,
                                 __nv_bfloat16* __restrict__ out) {
    int row = blockIdx.x;
    const float* x = in + (size_t)row * DD;
    int t = threadIdx.x;
    float v0 = x[t], v1 = x[t + 256], v2 = x[t + 512];
    float2 r = blockReduceSum2(v0 + v1 + v2, v0 * v0 + v1 * v1 + v2 * v2);
    float mu = r.x * (1.0f / 768.0f);
    float var = r.y * (1.0f / 768.0f) - mu * mu;
    float rstd = rsqrtf(var + 1e-5f);
    __nv_bfloat16* o = out + (size_t)row * DD;
    o[t]       = __float2bfloat16((v0 - mu) * rstd * g[t]       + b[t]);
    o[t + 256] = __float2bfloat16((v1 - mu) * rstd * g[t + 256] + b[t + 256]);
    o[t + 512] = __float2bfloat16((v2 - mu) * rstd * g[t + 512] + b[t + 512]);
}

// ================= mma.sync NT GEMM, single-barrier 3-stage pipeline ========
#define GBM 128
#define GBK 64
#define ROWB 144
#define ABUF 18432   // 128 * 144

template <bool FUSE, int BN, bool ATOMIC>
__global__ __launch_bounds__(256, 2)
void gemm_mma_kernel(const __nv_bfloat16* __restrict__ A,
                     const __nv_bfloat16* __restrict__ B,
                     float* __restrict__ Cf,
                     __nv_bfloat16* __restrict__ Cbf,
                     const float* __restrict__ bias,
                     const float* __restrict__ res,
                     int N, int K, int ldc, int act,
                     float* __restrict__ pm, float* __restrict__ ps) {
    constexpr int BBUF = BN * ROWB;
    constexpr int BUFS = ABUF + BBUF;
    constexpr int NNB  = BN / 32;
    extern __shared__ __align__(128) uint8_t gsm[];
    uint32_t sbase = smem_u32(gsm);
    int tid = threadIdx.x;
    int m0 = blockIdx.x * GBM, n0 = blockIdx.y * BN;
    int nk = K / GBK;
    int kbase = 0;
    if (ATOMIC) {
        nk = K / GBK / gridDim.z;
        kbase = blockIdx.z * nk;
    }

    auto issue = [&](int c) {
        int k0 = (kbase + c) * GBK;
        int st = c % 3;
        uint32_t dA = sbase + st * BUFS;
        uint32_t dB = dA + ABUF;
        #pragma unroll
        for (int e = 0; e < 4; e++) {
            int idx = tid + e * 256;
            int r = idx >> 3, cc = idx & 7;
            cp_async16(dA + r * ROWB + cc * 16,
                       A + (size_t)(m0 + r) * K + k0 + cc * 8, true);
        }
        #pragma unroll
        for (int e = 0; e < BN / 32; e++) {
            int idx = tid + e * 256;
            int r = idx >> 3, cc = idx & 7;
            int gn = n0 + r;
            cp_async16(dB + r * ROWB + cc * 16,
                       B + (size_t)gn * K + k0 + cc * 8, gn < N);
        }
        CP_COMMIT();
    };

    int warp = tid >> 5, lane = tid & 31;
    int wm = warp >> 1, wn = warp & 1;
    int lr = lane & 15, lc = lane >> 4;
    float acc[2][2 * NNB][4];
    #pragma unroll
    for (int i = 0; i < 2; i++)
        #pragma unroll
        for (int j = 0; j < 2 * NNB; j++)
            #pragma unroll
            for (int q = 0; q < 4; q++) acc[i][j][q] = 0.f;

    issue(0);
    if (nk > 1) issue(1);
    // single-barrier mainloop: wait -> sync -> compute(c) -> issue(c+2)
    for (int c = 0; c < nk; c++) {
        if (c + 1 < nk) { CP_WAIT(1); } else { CP_WAIT(0); }
        __syncthreads();
        uint32_t aB = sbase + (c % 3) * BUFS;
        uint32_t bB = aB + ABUF;
        #pragma unroll
        for (int kk = 0; kk < 4; kk++) {
            uint32_t a[2][4];
            #pragma unroll
            for (int mi = 0; mi < 2; mi++) {
                uint32_t addr = aB + (uint32_t)((wm * 32 + mi * 16 + lr) * ROWB
                                                + (kk * 16 + lc * 8) * 2);
                ldmatrix_x4(a[mi][0], a[mi][1], a[mi][2], a[mi][3], addr);
            }
            #pragma unroll
            for (int nb = 0; nb < NNB; nb++) {
                uint32_t b0, b1, b2, b3;
                uint32_t addr = bB + (uint32_t)((wn * (BN / 2) + nb * 16 + lr) * ROWB
                                                + (kk * 16 + lc * 8) * 2);
                ldmatrix_x4(b0, b1, b2, b3, addr);
                #pragma unroll
                for (int mi = 0; mi < 2; mi++) {
                    mma_bf16(acc[mi][nb * 2],     a[mi], b0, b2);
                    mma_bf16(acc[mi][nb * 2 + 1], a[mi], b1, b3);
                }
            }
        }
        if (c + 2 < nk) issue(c + 2);
    }

    // --- epilogue ---
    int mrow = m0 + wm * 32;
    int ncol = n0 + wn * (BN / 2);
    int tr = lane >> 2, tc = (lane & 3) * 2;
    bool vec = ((ldc & 1) == 0);
    float tm[2][2], ts[2][2];
    if (FUSE) {
        #pragma unroll
        for (int i = 0; i < 2; i++)
            #pragma unroll
            for (int j = 0; j < 2; j++) { tm[i][j] = -INFINITY; ts[i][j] = 0.f; }
    }
    #pragma unroll
    for (int mi = 0; mi < 2; mi++) {
        #pragma unroll
        for (int ni = 0; ni < 2 * NNB; ni++) {
            #pragma unroll
            for (int h = 0; h < 2; h++) {
                int row = mrow + mi * 16 + tr + h * 8;
                int col = ncol + ni * 8 + tc;
                float v0 = acc[mi][ni][h * 2];
                float v1 = acc[mi][ni][h * 2 + 1];
                if (ATOMIC) {
                    if (bias && blockIdx.z == 0) {
                        v0 += bias[col];
                        if (col + 1 < N) v1 += bias[col + 1];
                    }
                    if (col < N)     atomicAdd(Cf + (size_t)row * ldc + col, v0);
                    if (col + 1 < N) atomicAdd(Cf + (size_t)row * ldc + col + 1, v1);
                    continue;
                }
                if (bias) { v0 += bias[col]; if (col + 1 < N) v1 += bias[col + 1]; }
                if (res) {
                    const float* rp = res + (size_t)row * ldc + col;
                    v0 += rp[0];
                    if (col + 1 < N) v1 += rp[1];
                }
                if (act) {
                    v0 = v0 * 0.5f * (1.0f + erff(v0 * 0.70710678118654752f));
                    v1 = v1 * 0.5f * (1.0f + erff(v1 * 0.70710678118654752f));
                }
                if (FUSE) {
                    if (col < N)     ms_update(tm[mi][h], ts[mi][h], v0);
                    if (col + 1 < N) ms_update(tm[mi][h], ts[mi][h], v1);
                }
                if (vec && col + 1 < N) {
                    if (Cf) *reinterpret_cast<float2*>(Cf + (size_t)row * ldc + col)
                                = make_float2(v0, v1);
                    else    *reinterpret_cast<__nv_bfloat162*>(Cbf + (size_t)row * ldc + col)
                                = __floats2bfloat162_rn(v0, v1);
                } else {
                    if (col < N) {
                        if (Cf) Cf[(size_t)row * ldc + col] = v0;
                        else    Cbf[(size_t)row * ldc + col] = __float2bfloat16(v0);
                    }
                    if (col + 1 < N) {
                        if (Cf) Cf[(size_t)row * ldc + col + 1] = v1;
                        else    Cbf[(size_t)row * ldc + col + 1] = __float2bfloat16(v1);
                    }
                }
            }
        }
    }
    if (FUSE) {
        float2* red = reinterpret_cast<float2*>(gsm);
        __syncthreads();
        #pragma unroll
        for (int mi = 0; mi < 2; mi++) {
            #pragma unroll
            for (int h = 0; h < 2; h++) {
                float m = tm[mi][h], s = ts[mi][h];
                #pragma unroll
                for (int o = 1; o <= 2; o <<= 1) {
                    float m2 = __shfl_xor_sync(0xffffffffu, m, o);
                    float s2 = __shfl_xor_sync(0xffffffffu, s, o);
                    ms_combine(m, s, m2, s2);
                }
                if ((lane & 3) == 0) {
                    int row_local = wm * 32 + mi * 16 + tr + h * 8;
                    red[row_local * 2 + wn] = make_float2(m, s);
                }
            }
        }
        __syncthreads();
        if (tid < 128) {
            float2 p0 = red[tid * 2], p1 = red[tid * 2 + 1];
            float m = p0.x, s = p0.y;
            ms_combine(m, s, p1.x, p1.y);
            pm[(size_t)(m0 + tid) * NT + blockIdx.y] = m;
            ps[(size_t)(m0 + tid) * NT + blockIdx.y] = s;
        }
    }
}

#define GS128 (3 * (ABUF + 128 * ROWB))   // 110592
#define GS64  (3 * (ABUF + 64 * ROWB))    // 82944

// ============ fused flash attention, 3-stage KV, single barrier =============
#define FQROWB 144
#define FQ_OFF 0
#define FKV_OFF 18432                 // 3 stages of (K 9216 + V 9216)
#define FSTAGE  18432
#define FSMEM   (FKV_OFF + 3 * FSTAGE)   // 73728

__global__ __launch_bounds__(256, 2)
void flash_attn_kernel(const __nv_bfloat16* __restrict__ qkv,
                       __nv_bfloat16* __restrict__ o) {
    extern __shared__ __align__(128) uint8_t fsm[];
    uint32_t sbase = smem_u32(fsm);
    int tid = threadIdx.x;
    int q0 = (gridDim.x - 1 - blockIdx.x) * 128;
    int bh = blockIdx.y, b = bh / HH, h = bh - b * HH;
    const size_t rowbase = (size_t)b * SS * D3;
    const int qoff = h * DH, koff = DD + h * DH, voff = 2 * DD + h * DH;

    auto issue_q = [&]() {
        #pragma unroll
        for (int e = 0; e < 4; e++) {
            int idx = tid + e * 256;
            int r = idx >> 3, c = idx & 7;
            cp_async16(sbase + FQ_OFF + r * FQROWB + c * 16,
                       qkv + rowbase + (size_t)(q0 + r) * D3 + qoff + c * 8, true);
        }
        CP_COMMIT();
    };
    auto issue_kv = [&](int t) {
        int kv0 = t * 64;
        uint32_t kd = sbase + FKV_OFF + (t % 3) * FSTAGE;
        uint32_t vd = kd + 9216;
        #pragma unroll
        for (int e = 0; e < 2; e++) {
            int idx = tid + e * 256;
            int r = idx >> 3, c = idx & 7;
            const size_t g = rowbase + (size_t)(kv0 + r) * D3;
            cp_async16(kd + r * FQROWB + c * 16, qkv + g + koff + c * 8, true);
            cp_async16(vd + r * FQROWB + c * 16, qkv + g + voff + c * 8, true);
        }
        CP_COMMIT();
    };

    int warp = tid >> 5, lane = tid & 31;
    int lr = lane & 15, lc = lane >> 4;
    int tr = lane >> 2, qd = lane & 3;
    int wq = q0 + warp * 16;

    float of[8][4];
    #pragma unroll
    for (int i = 0; i < 8; i++)
        #pragma unroll
        for (int j = 0; j < 4; j++) of[i][j] = 0.f;
    float m0r = -INFINITY, m1r = -INFINITY, l0r = 0.f, l1r = 0.f;

    int nt = q0 / 64 + 2;
    issue_q();
    issue_kv(0);
    if (nt > 1) issue_kv(1);

    const float sc = 0.03608439182435161f;  // 1/sqrt(768)

    for (int t = 0; t < nt; t++) {
        if (t + 1 < nt) { CP_WAIT(1); } else { CP_WAIT(0); }
        __syncthreads();
        int kv0 = t * 64;
        uint32_t kB = sbase + FKV_OFF + (t % 3) * FSTAGE;
        uint32_t vB = kB + 9216;

        float sf[8][4];
        #pragma unroll
        for (int i = 0; i < 8; i++)
            #pragma unroll
            for (int j = 0; j < 4; j++) sf[i][j] = 0.f;
        #pragma unroll
        for (int ks = 0; ks < 4; ks++) {
            uint32_t aq[4];
            uint32_t qa = sbase + FQ_OFF + (uint32_t)((warp * 16 + lr) * FQROWB
                                                      + (ks * 16 + lc * 8) * 2);
            ldmatrix_x4(aq[0], aq[1], aq[2], aq[3], qa);
            #pragma unroll
            for (int nb2 = 0; nb2 < 4; nb2++) {
                uint32_t b0, b1, b2, b3;
                uint32_t ka = kB + (uint32_t)((nb2 * 16 + lr) * FQROWB
                                              + (ks * 16 + lc * 8) * 2);
                ldmatrix_x4(b0, b1, b2, b3, ka);
                mma_bf16(sf[nb2 * 2],     aq, b0, b2);
                mma_bf16(sf[nb2 * 2 + 1], aq, b1, b3);
            }
        }
        #pragma unroll
        for (int i = 0; i < 8; i++)
            #pragma unroll
            for (int j = 0; j < 4; j++) sf[i][j] *= sc;
        if (kv0 + 63 > wq) {
            #pragma unroll
            for (int nb = 0; nb < 8; nb++) {
                #pragma unroll
                for (int j = 0; j < 4; j++) {
                    int col = kv0 + nb * 8 + qd * 2 + (j & 1);
                    int row = wq + tr + (j >> 1) * 8;
                    if (col > row) sf[nb][j] = -INFINITY;
                }
            }
        }
        float tm0 = -INFINITY, tm1 = -INFINITY;
        #pragma unroll
        for (int nb = 0; nb < 8; nb++) {
            tm0 = fmaxf(tm0, fmaxf(sf[nb][0], sf[nb][1]));
            tm1 = fmaxf(tm1, fmaxf(sf[nb][2], sf[nb][3]));
        }
        tm0 = fmaxf(tm0, __shfl_xor_sync(0xffffffffu, tm0, 1));
        tm0 = fmaxf(tm0, __shfl_xor_sync(0xffffffffu, tm0, 2));
        tm1 = fmaxf(tm1, __shfl_xor_sync(0xffffffffu, tm1, 1));
        tm1 = fmaxf(tm1, __shfl_xor_sync(0xffffffffu, tm1, 2));
        float mn0 = fmaxf(m0r, tm0), mn1 = fmaxf(m1r, tm1);
        float f0 = __expf(m0r - mn0), f1 = __expf(m1r - mn1);
        m0r = mn0; m1r = mn1;
        float rs0 = 0.f, rs1 = 0.f;
        #pragma unroll
        for (int nb = 0; nb < 8; nb++) {
            sf[nb][0] = __expf(sf[nb][0] - mn0);
            sf[nb][1] = __expf(sf[nb][1] - mn0);
            sf[nb][2] = __expf(sf[nb][2] - mn1);
            sf[nb][3] = __expf(sf[nb][3] - mn1);
            rs0 += sf[nb][0] + sf[nb][1];
            rs1 += sf[nb][2] + sf[nb][3];
        }
        rs0 += __shfl_xor_sync(0xffffffffu, rs0, 1);
        rs0 += __shfl_xor_sync(0xffffffffu, rs0, 2);
        rs1 += __shfl_xor_sync(0xffffffffu, rs1, 1);
        rs1 += __shfl_xor_sync(0xffffffffu, rs1, 2);
        l0r = l0r * f0 + rs0;
        l1r = l1r * f1 + rs1;
        #pragma unroll
        for (int nb = 0; nb < 8; nb++) {
            of[nb][0] *= f0; of[nb][1] *= f0;
            of[nb][2] *= f1; of[nb][3] *= f1;
        }
        #pragma unroll
        for (int ks = 0; ks < 4; ks++) {
            uint32_t ap[4];
            ap[0] = pack_bf16x2(sf[2 * ks][0],     sf[2 * ks][1]);
            ap[1] = pack_bf16x2(sf[2 * ks][2],     sf[2 * ks][3]);
            ap[2] = pack_bf16x2(sf[2 * ks + 1][0], sf[2 * ks + 1][1]);
            ap[3] = pack_bf16x2(sf[2 * ks + 1][2], sf[2 * ks + 1][3]);
            #pragma unroll
            for (int nb2 = 0; nb2 < 4; nb2++) {
                int g = lane >> 3;
                int kvr = ks * 16 + (g & 1) * 8 + (lane & 7);
                int dhc = nb2 * 16 + (g >> 1) * 8;
                uint32_t va = vB + (uint32_t)(kvr * FQROWB + dhc * 2);
                uint32_t r0, r1, r2, r3;
                ldmatrix_x4_trans(r0, r1, r2, r3, va);
                mma_bf16(of[nb2 * 2],     ap, r0, r1);
                mma_bf16(of[nb2 * 2 + 1], ap, r2, r3);
            }
        }
        if (t + 2 < nt) issue_kv(t + 2);
    }

    float inv0 = 1.0f / l0r, inv1 = 1.0f / l1r;
    size_t obase = (size_t)b * SS * DD + (size_t)h * DH;
    #pragma unroll
    for (int nb = 0; nb < 8; nb++) {
        int col = nb * 8 + qd * 2;
        int row0 = wq + tr, row1 = row0 + 8;
        __nv_bfloat162 v0 = __floats2bfloat162_rn(of[nb][0] * inv0, of[nb][1] * inv0);
        __nv_bfloat162 v1 = __floats2bfloat162_rn(of[nb][2] * inv1, of[nb][3] * inv1);
        *reinterpret_cast<__nv_bfloat162*>(o + obase + (size_t)row0 * DD + col) = v0;
        *reinterpret_cast<__nv_bfloat162*>(o + obase + (size_t)row1 * DD + col) = v1;
    }
}

// ---- finish log_softmax from GEMM partials ---------------------------------
__global__ __launch_bounds__(512)
void logsoftmax_finish_kernel(float* __restrict__ logits,
                              const float* __restrict__ pm,
                              const float* __restrict__ ps,
                              const int* __restrict__ target,
                              float* __restrict__ picked) {
    __shared__ float shm[16], shs[16], bc[1];
    int row = blockIdx.x;
    float* x = logits + (size_t)row * VV;
    int t = threadIdx.x, lane = t & 31, wid = t >> 5;

    float m = -INFINITY, s = 0.f;
    const float* pmr = pm + (size_t)row * NT;
    const float* psr = ps + (size_t)row * NT;
    for (int i = t; i < NT; i += 512)
        ms_combine(m, s, pmr[i], psr[i]);
    #pragma unroll
    for (int o = 16; o; o >>= 1) {
        float m2 = __shfl_xor_sync(0xffffffffu, m, o);
        float s2 = __shfl_xor_sync(0xffffffffu, s, o);
        ms_combine(m, s, m2, s2);
    }
    if (lane == 0) { shm[wid] = m; shs[wid] = s; }
    __syncthreads();
    if (t == 0) {
        float M = shm[0], S = shs[0];
        #pragma unroll
        for (int i = 1; i < 16; i++)
            ms_combine(M, S, shm[i], shs[i]);
        bc[0] = M + logf(S);
    }
    __syncthreads();
    float sub = bc[0];
    int tgt = target[row];

    int head = (int)(((16 - ((uintptr_t)x & 15)) & 15) >> 2);
    int nvec = (VV - head) >> 2;
    float* xv = x + head;
    for (int i = t; i < head; i += 512) {
        float lp = x[i] - sub;
        x[i] = lp;
        if (i == tgt) picked[row] = lp;
    }
    for (int i = t; i < nvec; i += 512) {
        float4 v = *reinterpret_cast<const float4*>(xv + i * 4);
        v.x -= sub; v.y -= sub; v.z -= sub; v.w -= sub;
        *reinterpret_cast<float4*>(xv + i * 4) = v;
        int base = head + i * 4;
        if (tgt >= base && tgt < base + 4) {
            float pv = (tgt == base) ? v.x : (tgt == base + 1) ? v.y
                     : (tgt == base + 2) ? v.z : v.w;
            picked[row] = pv;
        }
    }
    for (int i = head + nvec * 4 + t; i < VV; i += 512) {
        float lp = x[i] - sub;
        x[i] = lp;
        if (i == tgt) picked[row] = lp;
    }
}

__global__ void finalize_loss_kernel(const float* __restrict__ picked,
                                     float* __restrict__ out) {
    float s = 0.f;
    for (int i = threadIdx.x; i < MR; i += 256) s += picked[i];
    s = blockReduceSum(s);
    if (threadIdx.x == 0) out[(size_t)MR * VV] = -s * (1.0f / (float)MR);
}

// ---------------- host orchestration ----------------
extern "C" void kernel_launch(void* const* d_in, const int* in_sizes, int n_in,
                              void* d_out, int out_size) {
    const int*   tokens = (const int*)  d_in[0];
    const int*   target = (const int*)  d_in[1];
    const float* wte    = (const float*)d_in[2];
    const float* wpe    = (const float*)d_in[3];
    const float* ln1_g  = (const float*)d_in[4];
    const float* ln1_b  = (const float*)d_in[5];
    const float* qkv_w  = (const float*)d_in[6];
    const float* qkv_b  = (const float*)d_in[7];
    const float* proj_w = (const float*)d_in[8];
    const float* proj_b = (const float*)d_in[9];
    const float* ln2_g  = (const float*)d_in[10];
    const float* ln2_b  = (const float*)d_in[11];
    const float* fc1_w  = (const float*)d_in[12];
    const float* fc1_b  = (const float*)d_in[13];
    const float* fc2_w  = (const float*)d_in[14];
    const float* fc2_b  = (const float*)d_in[15];
    const float* lnf_g  = (const float*)d_in[16];
    const float* lnf_b  = (const float*)d_in[17];
    float* out = (float*)d_out;

    float *gx, *gpicked, *gpm, *gps;
    __nv_bfloat16 *ghb, *gob, *gffb, *gqkvb, *gwteb, *gqkvT, *gprojT, *gfc1T, *gfc2T;
    cudaGetSymbolAddress((void**)&gx,     g_x);
    cudaGetSymbolAddress((void**)&gpicked,g_picked);
    cudaGetSymbolAddress((void**)&gpm,    g_pm);
    cudaGetSymbolAddress((void**)&gps,    g_ps);
    cudaGetSymbolAddress((void**)&ghb,    g_hb);
    cudaGetSymbolAddress((void**)&gob,    g_ob);
    cudaGetSymbolAddress((void**)&gffb,   g_ffb);
    cudaGetSymbolAddress((void**)&gqkvb,  g_qkvb);
    cudaGetSymbolAddress((void**)&gwteb,  g_wteb);
    cudaGetSymbolAddress((void**)&gqkvT,  g_qkvT);
    cudaGetSymbolAddress((void**)&gprojT, g_projT);
    cudaGetSymbolAddress((void**)&gfc1T,  g_fc1T);
    cudaGetSymbolAddress((void**)&gfc2T,  g_fc2T);

    cudaFuncSetAttribute(flash_attn_kernel,
                         cudaFuncAttributeMaxDynamicSharedMemorySize, FSMEM);
    cudaFuncSetAttribute(gemm_mma_kernel<false, 128, false>,
                         cudaFuncAttributeMaxDynamicSharedMemorySize, GS128);
    cudaFuncSetAttribute(gemm_mma_kernel<true, 128, false>,
                         cudaFuncAttributeMaxDynamicSharedMemorySize, GS128);
    cudaFuncSetAttribute(gemm_mma_kernel<false, 64, false>,
                         cudaFuncAttributeMaxDynamicSharedMemorySize, GS64);
    cudaFuncSetAttribute(gemm_mma_kernel<false, 64, true>,
                         cudaFuncAttributeMaxDynamicSharedMemorySize, GS64);

    {
        long n4 = (long)VV * DD / 4;
        convert_bf16_kernel4<<<(int)((n4 + 255) / 256), 256>>>(
            (const float4*)wte, (__nv_bfloat162*)gwteb, n4);
    }
    transpose_to_bf16<<<dim3(D3 / 64,  DD / 64,  LL), 256>>>(qkv_w,  gqkvT,  DD,  D3);
    transpose_to_bf16<<<dim3(DD / 64,  DD / 64,  LL), 256>>>(proj_w, gprojT, DD,  DD);
    transpose_to_bf16<<<dim3(FF_ / 64, DD / 64,  LL), 256>>>(fc1_w,  gfc1T,  DD,  FF_);
    transpose_to_bf16<<<dim3(DD / 64,  FF_ / 64, LL), 256>>>(fc2_w,  gfc2T,  FF_, DD);

    embed_kernel<<<(MR * DD + 255) / 256, 256>>>(tokens, wte, wpe, gx);

    for (int l = 0; l < LL; l++) {
        layernorm_kernel<<<MR, 256>>>(gx, ln1_g + (size_t)l * DD, ln1_b + (size_t)l * DD, ghb);

        gemm_mma_kernel<false, 128, false><<<dim3(MR / GBM, D3 / 128), 256, GS128>>>(
            ghb, gqkvT + (size_t)l * DD * D3, nullptr, gqkvb,
            qkv_b + (size_t)l * D3, nullptr, D3, DD, D3, 0, nullptr, nullptr);

        flash_attn_kernel<<<dim3(SS / 128, BB * HH), 256, FSMEM>>>(gqkvb, gob);

        gemm_mma_kernel<false, 64, true><<<dim3(MR / GBM, DD / 64, 2), 256, GS64>>>(
            gob, gprojT + (size_t)l * DD * DD, gx, nullptr,
            proj_b + (size_t)l * DD, nullptr, DD, DD, DD, 0, nullptr, nullptr);

        layernorm_kernel<<<MR, 256>>>(gx, ln2_g + (size_t)l * DD, ln2_b + (size_t)l * DD, ghb);

        gemm_mma_kernel<false, 64, false><<<dim3(MR / GBM, FF_ / 64), 256, GS64>>>(
            ghb, gfc1T + (size_t)l * DD * FF_, nullptr, gffb,
            fc1_b + (size_t)l * FF_, nullptr, FF_, DD, FF_, 1, nullptr, nullptr);

        gemm_mma_kernel<false, 64, true><<<dim3(MR / GBM, DD / 64, 2), 256, GS64>>>(
            gffb, gfc2T + (size_t)l * FF_ * DD, gx, nullptr,
            fc2_b + (size_t)l * DD, nullptr, DD, FF_, DD, 0, nullptr, nullptr);
    }

    layernorm_kernel<<<MR, 256>>>(gx, lnf_g, lnf_b, ghb);

    gemm_mma_kernel<true, 128, false><<<dim3(MR / GBM, NT), 256, GS128>>>(
        ghb, gwteb, out, nullptr, nullptr, nullptr, VV, DD, VV, 0, gpm, gps);

    logsoftmax_finish_kernel<<<MR, 512>>>(out, gpm, gps, target, gpicked);
    finalize_loss_kernel<<<1, 256>>>(gpicked, out);
}

// round 12
// speedup vs baseline: 6.4003x; 1.0189x over previous
#include <cuda_runtime.h>
#include <cuda_bf16.h>
#include <math.h>
#include <stdint.h>

// ---------------- problem constants ----------------
#define BB   2
#define SS   1024
#define DD   768
#define HH   12
#define DH   64
#define FF_  3072
#define LL   12
#define VV   50257
#define MR   2048          // B*S rows
#define D3   2304          // 3*D
#define NT   393           // ceil(VV/128) logits n-tiles
#define NQT  8             // q-tiles per (b,h)
#define NITEM (BB * HH * NQT)   // 192 flash items

// ---------------- scratch (static device memory) ----------------
__device__ float g_x   [MR * DD];
__device__ float g_picked[MR];
__device__ float g_pm  [MR * NT];
__device__ float g_ps  [MR * NT];
__device__ float g_opart[2 * NITEM * 8192];   // flash partial O (fp32)
__device__ float g_ml   [2 * NITEM * 256];    // flash partial (m,l)

__device__ __nv_bfloat16 g_hb  [MR * DD];
__device__ __nv_bfloat16 g_ob  [MR * DD];
__device__ __nv_bfloat16 g_ffb [MR * FF_];
__device__ __nv_bfloat16 g_qkvb[MR * D3];

__device__ __nv_bfloat16 g_wteb [VV * DD];
__device__ __nv_bfloat16 g_qkvT [LL * DD * D3];
__device__ __nv_bfloat16 g_projT[LL * DD * DD];
__device__ __nv_bfloat16 g_fc1T [LL * DD * FF_];
__device__ __nv_bfloat16 g_fc2T [LL * FF_ * DD];

// ================= low-level helpers (baseline PTX only) =================
__device__ __forceinline__ uint32_t smem_u32(const void* p) {
    uint32_t a;
    asm("{ .reg .u64 t; cvta.to.shared.u64 t, %1; cvt.u32.u64 %0, t; }" : "=r"(a) : "l"(p));
    return a;
}
__device__ __forceinline__ void cp_async16(uint32_t dst, const void* src, bool valid) {
    int sz = valid ? 16 : 0;
    asm volatile("cp.async.cg.shared.global [%0], [%1], 16, %2;"
                 :: "r"(dst), "l"(src), "r"(sz) : "memory");
}
#define CP_COMMIT()  asm volatile("cp.async.commit_group;" ::: "memory")
#define CP_WAIT(n)   asm volatile("cp.async.wait_group %0;" :: "n"(n) : "memory")

__device__ __forceinline__ void ldmatrix_x4(uint32_t& r0, uint32_t& r1,
                                            uint32_t& r2, uint32_t& r3, uint32_t addr) {
    asm volatile("ldmatrix.sync.aligned.m8n8.x4.shared.b16 {%0,%1,%2,%3}, [%4];"
                 : "=r"(r0), "=r"(r1), "=r"(r2), "=r"(r3) : "r"(addr));
}
__device__ __forceinline__ void ldmatrix_x4_trans(uint32_t& r0, uint32_t& r1,
                                                  uint32_t& r2, uint32_t& r3, uint32_t addr) {
    asm volatile("ldmatrix.sync.aligned.m8n8.x4.trans.shared.b16 {%0,%1,%2,%3}, [%4];"
                 : "=r"(r0), "=r"(r1), "=r"(r2), "=r"(r3) : "r"(addr));
}
__device__ __forceinline__ void mma_bf16(float* c, const uint32_t* a,
                                         uint32_t b0, uint32_t b1) {
    asm volatile(
        "mma.sync.aligned.m16n8k16.row.col.f32.bf16.bf16.f32 "
        "{%0,%1,%2,%3}, {%4,%5,%6,%7}, {%8,%9}, {%0,%1,%2,%3};"
        : "+f"(c[0]), "+f"(c[1]), "+f"(c[2]), "+f"(c[3])
        : "r"(a[0]), "r"(a[1]), "r"(a[2]), "r"(a[3]), "r"(b0), "r"(b1));
}
__device__ __forceinline__ uint32_t pack_bf16x2(float lo, float hi) {
    __nv_bfloat162 h = __floats2bfloat162_rn(lo, hi);
    return *reinterpret_cast<uint32_t*>(&h);
}
__device__ __forceinline__ void ms_update(float& m, float& s, float v) {
    if (v > m) { s = s * __expf(m - v) + 1.0f; m = v; }
    else       { s += __expf(v - m); }
}
__device__ __forceinline__ void ms_combine(float& m, float& s, float m2, float s2) {
    float mn = fmaxf(m, m2);
    float e1 = (m  > -INFINITY) ? __expf(m  - mn) : 0.f;
    float e2 = (m2 > -INFINITY) ? __expf(m2 - mn) : 0.f;
    s = s * e1 + s2 * e2;
    m = mn;
}

// ---------------- block reductions ----------------
__device__ __forceinline__ float blockReduceSum(float v) {
    __shared__ float sh[32];
    int lane = threadIdx.x & 31, wid = threadIdx.x >> 5;
    #pragma unroll
    for (int o = 16; o; o >>= 1) v += __shfl_xor_sync(0xffffffffu, v, o);
    __syncthreads();
    if (lane == 0) sh[wid] = v;
    __syncthreads();
    float r = (lane < (int)(blockDim.x >> 5)) ? sh[lane] : 0.f;
    if (wid == 0) {
        #pragma unroll
        for (int o = 16; o; o >>= 1) r += __shfl_xor_sync(0xffffffffu, r, o);
        if (lane == 0) sh[0] = r;
    }
    __syncthreads();
    return sh[0];
}
__device__ __forceinline__ float2 blockReduceSum2(float a, float b) {
    __shared__ float2 sh[8];
    int lane = threadIdx.x & 31, wid = threadIdx.x >> 5;
    #pragma unroll
    for (int o = 16; o; o >>= 1) {
        a += __shfl_xor_sync(0xffffffffu, a, o);
        b += __shfl_xor_sync(0xffffffffu, b, o);
    }
    if (lane == 0) sh[wid] = make_float2(a, b);
    __syncthreads();
    if (wid == 0) {
        float2 r = (lane < 8) ? sh[lane] : make_float2(0.f, 0.f);
        #pragma unroll
        for (int o = 4; o; o >>= 1) {
            r.x += __shfl_xor_sync(0xffffffffu, r.x, o);
            r.y += __shfl_xor_sync(0xffffffffu, r.y, o);
        }
        if (lane == 0) sh[0] = r;
    }
    __syncthreads();
    return sh[0];
}

// ---------------- weight prep ----------------
__global__ void transpose_to_bf16(const float* __restrict__ src,
                                  __nv_bfloat16* __restrict__ dst,
                                  int K, int N) {
    __shared__ float tile[64][65];
    const float* s = src + (size_t)blockIdx.z * K * N;
    __nv_bfloat16* d = dst + (size_t)blockIdx.z * K * N;
    int n0 = blockIdx.x * 64, k0 = blockIdx.y * 64;
    int tid = threadIdx.x;
    #pragma unroll
    for (int e = 0; e < 8; e++) {
        int idx = tid + e * 256;
        int r = idx >> 5, c = idx & 31;
        float2 v = *reinterpret_cast<const float2*>(s + (size_t)(k0 + r) * N + n0 + c * 2);
        tile[c * 2][r]     = v.x;
        tile[c * 2 + 1][r] = v.y;
    }
    __syncthreads();
    #pragma unroll
    for (int e = 0; e < 8; e++) {
        int idx = tid + e * 256;
        int r = idx >> 5, c = (idx & 31) * 2;
        __nv_bfloat162 v = __floats2bfloat162_rn(tile[r][c], tile[r][c + 1]);
        *reinterpret_cast<__nv_bfloat162*>(d + (size_t)(n0 + r) * K + k0 + c) = v;
    }
}

__global__ void convert_bf16_kernel4(const float4* __restrict__ src,
                                     __nv_bfloat162* __restrict__ dst, long n4) {
    long i = (long)blockIdx.x * blockDim.x + threadIdx.x;
    if (i < n4) {
        float4 v = src[i];
        dst[i * 2]     = __floats2bfloat162_rn(v.x, v.y);
        dst[i * 2 + 1] = __floats2bfloat162_rn(v.z, v.w);
    }
}

// ---------------- embedding ----------------
__global__ void embed_kernel(const int* __restrict__ tokens,
                             const float* __restrict__ wte,
                             const float* __restrict__ wpe,
                             float* __restrict__ x) {
    int i = blockIdx.x * blockDim.x + threadIdx.x;
    if (i >= MR * DD) return;
    int row = i / DD, d = i - row * DD;
    int s = row & (SS - 1);
    x[i] = wte[(size_t)tokens[row] * DD + d] + wpe[(size_t)s * DD + d];
}

// ---------------- layernorm -> bf16 ----------------
__global__ void layernorm_kernel(const float* __restrict__ in,
                                 const float* __restrict__ g,
                                 const float* __restrict__ b,
                                 __nv_bfloat16* __restrict__ out) {
    int row = blockIdx.x;
    const float* x = in + (size_t)row * DD;
    int t = threadIdx.x;
    float v0 = x[t], v1 = x[t + 256], v2 = x[t + 512];
    float2 r = blockReduceSum2(v0 + v1 + v2, v0 * v0 + v1 * v1 + v2 * v2);
    float mu = r.x * (1.0f / 768.0f);
    float var = r.y * (1.0f / 768.0f) - mu * mu;
    float rstd = rsqrtf(var + 1e-5f);
    __nv_bfloat16* o = out + (size_t)row * DD;
    o[t]       = __float2bfloat16((v0 - mu) * rstd * g[t]       + b[t]);
    o[t + 256] = __float2bfloat16((v1 - mu) * rstd * g[t + 256] + b[t + 256]);
    o[t + 512] = __float2bfloat16((v2 - mu) * rstd * g[t + 512] + b[t + 512]);
}

// ================= mma.sync NT GEMM, single-barrier 3-stage pipeline ========
#define GBM 128
#define GBK 64
#define ROWB 144
#define ABUF 18432   // 128 * 144

template <bool FUSE, int BN, bool ATOMIC>
__global__ __launch_bounds__(256, 2)
void gemm_mma_kernel(const __nv_bfloat16* __restrict__ A,
                     const __nv_bfloat16* __restrict__ B,
                     float* __restrict__ Cf,
                     __nv_bfloat16* __restrict__ Cbf,
                     const float* __restrict__ bias,
                     const float* __restrict__ res,
                     int N, int K, int ldc, int act,
                     float* __restrict__ pm, float* __restrict__ ps) {
    constexpr int BBUF = BN * ROWB;
    constexpr int BUFS = ABUF + BBUF;
    constexpr int NNB  = BN / 32;
    extern __shared__ __align__(128) uint8_t gsm[];
    uint32_t sbase = smem_u32(gsm);
    int tid = threadIdx.x;
    int m0 = blockIdx.x * GBM, n0 = blockIdx.y * BN;
    int nk = K / GBK;
    int kbase = 0;
    if (ATOMIC) {
        nk = K / GBK / gridDim.z;
        kbase = blockIdx.z * nk;
    }

    auto issue = [&](int c) {
        int k0 = (kbase + c) * GBK;
        int st = c % 3;
        uint32_t dA = sbase + st * BUFS;
        uint32_t dB = dA + ABUF;
        #pragma unroll
        for (int e = 0; e < 4; e++) {
            int idx = tid + e * 256;
            int r = idx >> 3, cc = idx & 7;
            cp_async16(dA + r * ROWB + cc * 16,
                       A + (size_t)(m0 + r) * K + k0 + cc * 8, true);
        }
        #pragma unroll
        for (int e = 0; e < BN / 32; e++) {
            int idx = tid + e * 256;
            int r = idx >> 3, cc = idx & 7;
            int gn = n0 + r;
            cp_async16(dB + r * ROWB + cc * 16,
                       B + (size_t)gn * K + k0 + cc * 8, gn < N);
        }
        CP_COMMIT();
    };

    int warp = tid >> 5, lane = tid & 31;
    int wm = warp >> 1, wn = warp & 1;
    int lr = lane & 15, lc = lane >> 4;
    float acc[2][2 * NNB][4];
    #pragma unroll
    for (int i = 0; i < 2; i++)
        #pragma unroll
        for (int j = 0; j < 2 * NNB; j++)
            #pragma unroll
            for (int q = 0; q < 4; q++) acc[i][j][q] = 0.f;

    issue(0);
    if (nk > 1) issue(1);
    for (int c = 0; c < nk; c++) {
        if (c + 1 < nk) { CP_WAIT(1); } else { CP_WAIT(0); }
        __syncthreads();
        uint32_t aB = sbase + (c % 3) * BUFS;
        uint32_t bB = aB + ABUF;
        #pragma unroll
        for (int kk = 0; kk < 4; kk++) {
            uint32_t a[2][4];
            #pragma unroll
            for (int mi = 0; mi < 2; mi++) {
                uint32_t addr = aB + (uint32_t)((wm * 32 + mi * 16 + lr) * ROWB
                                                + (kk * 16 + lc * 8) * 2);
                ldmatrix_x4(a[mi][0], a[mi][1], a[mi][2], a[mi][3], addr);
            }
            #pragma unroll
            for (int nb = 0; nb < NNB; nb++) {
                uint32_t b0, b1, b2, b3;
                uint32_t addr = bB + (uint32_t)((wn * (BN / 2) + nb * 16 + lr) * ROWB
                                                + (kk * 16 + lc * 8) * 2);
                ldmatrix_x4(b0, b1, b2, b3, addr);
                #pragma unroll
                for (int mi = 0; mi < 2; mi++) {
                    mma_bf16(acc[mi][nb * 2],     a[mi], b0, b2);
                    mma_bf16(acc[mi][nb * 2 + 1], a[mi], b1, b3);
                }
            }
        }
        if (c + 2 < nk) issue(c + 2);
    }

    // --- epilogue ---
    int mrow = m0 + wm * 32;
    int ncol = n0 + wn * (BN / 2);
    int tr = lane >> 2, tc = (lane & 3) * 2;
    bool vec = ((ldc & 1) == 0);
    float tm[2][2], ts[2][2];
    if (FUSE) {
        #pragma unroll
        for (int i = 0; i < 2; i++)
            #pragma unroll
            for (int j = 0; j < 2; j++) { tm[i][j] = -INFINITY; ts[i][j] = 0.f; }
    }
    #pragma unroll
    for (int mi = 0; mi < 2; mi++) {
        #pragma unroll
        for (int ni = 0; ni < 2 * NNB; ni++) {
            #pragma unroll
            for (int h = 0; h < 2; h++) {
                int row = mrow + mi * 16 + tr + h * 8;
                int col = ncol + ni * 8 + tc;
                float v0 = acc[mi][ni][h * 2];
                float v1 = acc[mi][ni][h * 2 + 1];
                if (ATOMIC) {
                    if (bias && blockIdx.z == 0) {
                        v0 += bias[col];
                        if (col + 1 < N) v1 += bias[col + 1];
                    }
                    if (col < N)     atomicAdd(Cf + (size_t)row * ldc + col, v0);
                    if (col + 1 < N) atomicAdd(Cf + (size_t)row * ldc + col + 1, v1);
                    continue;
                }
                if (bias) { v0 += bias[col]; if (col + 1 < N) v1 += bias[col + 1]; }
                if (res) {
                    const float* rp = res + (size_t)row * ldc + col;
                    v0 += rp[0];
                    if (col + 1 < N) v1 += rp[1];
                }
                if (act) {
                    v0 = v0 * 0.5f * (1.0f + erff(v0 * 0.70710678118654752f));
                    v1 = v1 * 0.5f * (1.0f + erff(v1 * 0.70710678118654752f));
                }
                if (FUSE) {
                    if (col < N)     ms_update(tm[mi][h], ts[mi][h], v0);
                    if (col + 1 < N) ms_update(tm[mi][h], ts[mi][h], v1);
                }
                if (vec && col + 1 < N) {
                    if (Cf) *reinterpret_cast<float2*>(Cf + (size_t)row * ldc + col)
                                = make_float2(v0, v1);
                    else    *reinterpret_cast<__nv_bfloat162*>(Cbf + (size_t)row * ldc + col)
                                = __floats2bfloat162_rn(v0, v1);
                } else {
                    if (col < N) {
                        if (Cf) Cf[(size_t)row * ldc + col] = v0;
                        else    Cbf[(size_t)row * ldc + col] = __float2bfloat16(v0);
                    }
                    if (col + 1 < N) {
                        if (Cf) Cf[(size_t)row * ldc + col + 1] = v1;
                        else    Cbf[(size_t)row * ldc + col + 1] = __float2bfloat16(v1);
                    }
                }
            }
        }
    }
    if (FUSE) {
        float2* red = reinterpret_cast<float2*>(gsm);
        __syncthreads();
        #pragma unroll
        for (int mi = 0; mi < 2; mi++) {
            #pragma unroll
            for (int h = 0; h < 2; h++) {
                float m = tm[mi][h], s = ts[mi][h];
                #pragma unroll
                for (int o = 1; o <= 2; o <<= 1) {
                    float m2 = __shfl_xor_sync(0xffffffffu, m, o);
                    float s2 = __shfl_xor_sync(0xffffffffu, s, o);
                    ms_combine(m, s, m2, s2);
                }
                if ((lane & 3) == 0) {
                    int row_local = wm * 32 + mi * 16 + tr + h * 8;
                    red[row_local * 2 + wn] = make_float2(m, s);
                }
            }
        }
        __syncthreads();
        if (tid < 128) {
            float2 p0 = red[tid * 2], p1 = red[tid * 2 + 1];
            float m = p0.x, s = p0.y;
            ms_combine(m, s, p1.x, p1.y);
            pm[(size_t)(m0 + tid) * NT + blockIdx.y] = m;
            ps[(size_t)(m0 + tid) * NT + blockIdx.y] = s;
        }
    }
}

#define GS128 (3 * (ABUF + 128 * ROWB))   // 110592
#define GS64  (3 * (ABUF + 64 * ROWB))    // 82944

// ============ flash attention partial: split-KV, 3-stage, 1 barrier =========
#define FQROWB 144
#define FQ_OFF 0
#define FKV_OFF 18432
#define FSTAGE  18432
#define FSMEM   (FKV_OFF + 3 * FSTAGE)   // 73728

__global__ __launch_bounds__(256, 2)
void flash_partial_kernel(const __nv_bfloat16* __restrict__ qkv,
                          float* __restrict__ opart,
                          float* __restrict__ mlout) {
    extern __shared__ __align__(128) uint8_t fsm[];
    uint32_t sbase = smem_u32(fsm);
    int tid = threadIdx.x;
    int qt = blockIdx.x;
    int q0 = qt * 128;
    int bh = blockIdx.y, b = bh / HH, h = bh - b * HH;
    int split = blockIdx.z;
    const size_t rowbase = (size_t)b * SS * D3;
    const int qoff = h * DH, koff = DD + h * DH, voff = 2 * DD + h * DH;

    int nt = q0 / 64 + 2;         // always even
    int nh = nt >> 1;
    int ts = split * nh, te = ts + nh;

    auto issue_q = [&]() {
        #pragma unroll
        for (int e = 0; e < 4; e++) {
            int idx = tid + e * 256;
            int r = idx >> 3, c = idx & 7;
            cp_async16(sbase + FQ_OFF + r * FQROWB + c * 16,
                       qkv + rowbase + (size_t)(q0 + r) * D3 + qoff + c * 8, true);
        }
        CP_COMMIT();
    };
    auto issue_kv = [&](int t) {
        int kv0 = t * 64;
        uint32_t kd = sbase + FKV_OFF + ((t - ts) % 3) * FSTAGE;
        uint32_t vd = kd + 9216;
        #pragma unroll
        for (int e = 0; e < 2; e++) {
            int idx = tid + e * 256;
            int r = idx >> 3, c = idx & 7;
            const size_t g = rowbase + (size_t)(kv0 + r) * D3;
            cp_async16(kd + r * FQROWB + c * 16, qkv + g + koff + c * 8, true);
            cp_async16(vd + r * FQROWB + c * 16, qkv + g + voff + c * 8, true);
        }
        CP_COMMIT();
    };

    int warp = tid >> 5, lane = tid & 31;
    int lr = lane & 15, lc = lane >> 4;
    int tr = lane >> 2, qd = lane & 3;
    int wq = q0 + warp * 16;

    float of[8][4];
    #pragma unroll
    for (int i = 0; i < 8; i++)
        #pragma unroll
        for (int j = 0; j < 4; j++) of[i][j] = 0.f;
    float m0r = -INFINITY, m1r = -INFINITY, l0r = 0.f, l1r = 0.f;

    issue_q();
    issue_kv(ts);
    if (te - ts > 1) issue_kv(ts + 1);

    const float sc = 0.03608439182435161f;  // 1/sqrt(768)

    for (int t = ts; t < te; t++) {
        if (t + 1 < te) { CP_WAIT(1); } else { CP_WAIT(0); }
        __syncthreads();
        int kv0 = t * 64;
        uint32_t kB = sbase + FKV_OFF + ((t - ts) % 3) * FSTAGE;
        uint32_t vB = kB + 9216;

        float sf[8][4];
        #pragma unroll
        for (int i = 0; i < 8; i++)
            #pragma unroll
            for (int j = 0; j < 4; j++) sf[i][j] = 0.f;
        #pragma unroll
        for (int ks = 0; ks < 4; ks++) {
            uint32_t aq[4];
            uint32_t qa = sbase + FQ_OFF + (uint32_t)((warp * 16 + lr) * FQROWB
                                                      + (ks * 16 + lc * 8) * 2);
            ldmatrix_x4(aq[0], aq[1], aq[2], aq[3], qa);
            #pragma unroll
            for (int nb2 = 0; nb2 < 4; nb2++) {
                uint32_t b0, b1, b2, b3;
                uint32_t ka = kB + (uint32_t)((nb2 * 16 + lr) * FQROWB
                                              + (ks * 16 + lc * 8) * 2);
                ldmatrix_x4(b0, b1, b2, b3, ka);
                mma_bf16(sf[nb2 * 2],     aq, b0, b2);
                mma_bf16(sf[nb2 * 2 + 1], aq, b1, b3);
            }
        }
        #pragma unroll
        for (int i = 0; i < 8; i++)
            #pragma unroll
            for (int j = 0; j < 4; j++) sf[i][j] *= sc;
        if (kv0 + 63 > wq) {
            #pragma unroll
            for (int nb = 0; nb < 8; nb++) {
                #pragma unroll
                for (int j = 0; j < 4; j++) {
                    int col = kv0 + nb * 8 + qd * 2 + (j & 1);
                    int row = wq + tr + (j >> 1) * 8;
                    if (col > row) sf[nb][j] = -INFINITY;
                }
            }
        }
        float tm0 = -INFINITY, tm1 = -INFINITY;
        #pragma unroll
        for (int nb = 0; nb < 8; nb++) {
            tm0 = fmaxf(tm0, fmaxf(sf[nb][0], sf[nb][1]));
            tm1 = fmaxf(tm1, fmaxf(sf[nb][2], sf[nb][3]));
        }
        tm0 = fmaxf(tm0, __shfl_xor_sync(0xffffffffu, tm0, 1));
        tm0 = fmaxf(tm0, __shfl_xor_sync(0xffffffffu, tm0, 2));
        tm1 = fmaxf(tm1, __shfl_xor_sync(0xffffffffu, tm1, 1));
        tm1 = fmaxf(tm1, __shfl_xor_sync(0xffffffffu, tm1, 2));
        float mn0 = fmaxf(m0r, tm0), mn1 = fmaxf(m1r, tm1);
        // clamp for fully-masked rows (split 1 near diagonal): avoids inf-inf
        float mnc0 = fmaxf(mn0, -1e30f), mnc1 = fmaxf(mn1, -1e30f);
        float f0 = __expf(m0r - mnc0), f1 = __expf(m1r - mnc1);
        m0r = mn0; m1r = mn1;
        float rs0 = 0.f, rs1 = 0.f;
        #pragma unroll
        for (int nb = 0; nb < 8; nb++) {
            sf[nb][0] = __expf(sf[nb][0] - mnc0);
            sf[nb][1] = __expf(sf[nb][1] - mnc0);
            sf[nb][2] = __expf(sf[nb][2] - mnc1);
            sf[nb][3] = __expf(sf[nb][3] - mnc1);
            rs0 += sf[nb][0] + sf[nb][1];
            rs1 += sf[nb][2] + sf[nb][3];
        }
        rs0 += __shfl_xor_sync(0xffffffffu, rs0, 1);
        rs0 += __shfl_xor_sync(0xffffffffu, rs0, 2);
        rs1 += __shfl_xor_sync(0xffffffffu, rs1, 1);
        rs1 += __shfl_xor_sync(0xffffffffu, rs1, 2);
        l0r = l0r * f0 + rs0;
        l1r = l1r * f1 + rs1;
        #pragma unroll
        for (int nb = 0; nb < 8; nb++) {
            of[nb][0] *= f0; of[nb][1] *= f0;
            of[nb][2] *= f1; of[nb][3] *= f1;
        }
        #pragma unroll
        for (int ks = 0; ks < 4; ks++) {
            uint32_t ap[4];
            ap[0] = pack_bf16x2(sf[2 * ks][0],     sf[2 * ks][1]);
            ap[1] = pack_bf16x2(sf[2 * ks][2],     sf[2 * ks][3]);
            ap[2] = pack_bf16x2(sf[2 * ks + 1][0], sf[2 * ks + 1][1]);
            ap[3] = pack_bf16x2(sf[2 * ks + 1][2], sf[2 * ks + 1][3]);
            #pragma unroll
            for (int nb2 = 0; nb2 < 4; nb2++) {
                int g = lane >> 3;
                int kvr = ks * 16 + (g & 1) * 8 + (lane & 7);
                int dhc = nb2 * 16 + (g >> 1) * 8;
                uint32_t va = vB + (uint32_t)(kvr * FQROWB + dhc * 2);
                uint32_t r0, r1, r2, r3;
                ldmatrix_x4_trans(r0, r1, r2, r3, va);
                mma_bf16(of[nb2 * 2],     ap, r0, r1);
                mma_bf16(of[nb2 * 2 + 1], ap, r2, r3);
            }
        }
        if (t + 2 < te) issue_kv(t + 2);
    }

    // ---- write unnormalized partials ----
    int item = bh * NQT + qt;
    float* op = opart + ((size_t)split * NITEM + item) * 8192;
    float* ml = mlout + ((size_t)split * NITEM + item) * 256;
    #pragma unroll
    for (int nb = 0; nb < 8; nb++) {
        int col = nb * 8 + qd * 2;
        int r0 = warp * 16 + tr, r1 = r0 + 8;
        *reinterpret_cast<float2*>(op + r0 * 64 + col) = make_float2(of[nb][0], of[nb][1]);
        *reinterpret_cast<float2*>(op + r1 * 64 + col) = make_float2(of[nb][2], of[nb][3]);
    }
    if (qd == 0) {
        int r0 = warp * 16 + tr, r1 = r0 + 8;
        *reinterpret_cast<float2*>(ml + r0 * 2) = make_float2(m0r, l0r);
        *reinterpret_cast<float2*>(ml + r1 * 2) = make_float2(m1r, l1r);
    }
}

// ---- merge the two KV splits ----
__global__ __launch_bounds__(256)
void flash_merge_kernel(const float* __restrict__ opart,
                        const float* __restrict__ ml,
                        __nv_bfloat16* __restrict__ o) {
    __shared__ float sf0[128], sf1[128], sinv[128];
    int item = blockIdx.x;
    int bh = item / NQT, qt = item - bh * NQT;
    int b = bh / HH, h = bh - b * HH;
    int tid = threadIdx.x;
    if (tid < 128) {
        float2 p0 = *reinterpret_cast<const float2*>(ml + (size_t)item * 256 + tid * 2);
        float2 p1 = *reinterpret_cast<const float2*>(ml + ((size_t)NITEM + item) * 256 + tid * 2);
        float m = fmaxf(p0.x, p1.x);
        float e0 = (p0.x > -1e30f) ? __expf(p0.x - m) : 0.f;
        float e1 = (p1.x > -1e30f) ? __expf(p1.x - m) : 0.f;
        float l = p0.y * e0 + p1.y * e1;
        sf0[tid] = e0; sf1[tid] = e1; sinv[tid] = 1.0f / l;
    }
    __syncthreads();
    const float* O0 = opart + (size_t)item * 8192;
    const float* O1 = opart + ((size_t)NITEM + item) * 8192;
    size_t obase = (size_t)b * SS * DD + (size_t)(qt * 128) * DD + (size_t)h * DH;
    for (int e = tid; e < 4096; e += 256) {
        int row = e >> 5, cp = (e & 31) * 2;
        float2 a = *reinterpret_cast<const float2*>(O0 + row * 64 + cp);
        float2 c = *reinterpret_cast<const float2*>(O1 + row * 64 + cp);
        float w0 = sf0[row], w1 = sf1[row], iv = sinv[row];
        __nv_bfloat162 v = __floats2bfloat162_rn((a.x * w0 + c.x * w1) * iv,
                                                 (a.y * w0 + c.y * w1) * iv);
        *reinterpret_cast<__nv_bfloat162*>(o + obase + (size_t)row * DD + cp) = v;
    }
}

// ---- finish log_softmax from GEMM partials ---------------------------------
__global__ __launch_bounds__(512)
void logsoftmax_finish_kernel(float* __restrict__ logits,
                              const float* __restrict__ pm,
                              const float* __restrict__ ps,
                              const int* __restrict__ target,
                              float* __restrict__ picked) {
    __shared__ float shm[16], shs[16], bc[1];
    int row = blockIdx.x;
    float* x = logits + (size_t)row * VV;
    int t = threadIdx.x, lane = t & 31, wid = t >> 5;

    float m = -INFINITY, s = 0.f;
    const float* pmr = pm + (size_t)row * NT;
    const float* psr = ps + (size_t)row * NT;
    for (int i = t; i < NT; i += 512)
        ms_combine(m, s, pmr[i], psr[i]);
    #pragma unroll
    for (int o = 16; o; o >>= 1) {
        float m2 = __shfl_xor_sync(0xffffffffu, m, o);
        float s2 = __shfl_xor_sync(0xffffffffu, s, o);
        ms_combine(m, s, m2, s2);
    }
    if (lane == 0) { shm[wid] = m; shs[wid] = s; }
    __syncthreads();
    if (t == 0) {
        float M = shm[0], S = shs[0];
        #pragma unroll
        for (int i = 1; i < 16; i++)
            ms_combine(M, S, shm[i], shs[i]);
        bc[0] = M + logf(S);
    }
    __syncthreads();
    float sub = bc[0];
    int tgt = target[row];

    int head = (int)(((16 - ((uintptr_t)x & 15)) & 15) >> 2);
    int nvec = (VV - head) >> 2;
    float* xv = x + head;
    for (int i = t; i < head; i += 512) {
        float lp = x[i] - sub;
        x[i] = lp;
        if (i == tgt) picked[row] = lp;
    }
    for (int i = t; i < nvec; i += 512) {
        float4 v = *reinterpret_cast<const float4*>(xv + i * 4);
        v.x -= sub; v.y -= sub; v.z -= sub; v.w -= sub;
        *reinterpret_cast<float4*>(xv + i * 4) = v;
        int base = head + i * 4;
        if (tgt >= base && tgt < base + 4) {
            float pv = (tgt == base) ? v.x : (tgt == base + 1) ? v.y
                     : (tgt == base + 2) ? v.z : v.w;
            picked[row] = pv;
        }
    }
    for (int i = head + nvec * 4 + t; i < VV; i += 512) {
        float lp = x[i] - sub;
        x[i] = lp;
        if (i == tgt) picked[row] = lp;
    }
}

__global__ void finalize_loss_kernel(const float* __restrict__ picked,
                                     float* __restrict__ out) {
    float s = 0.f;
    for (int i = threadIdx.x; i < MR; i += 256) s += picked[i];
    s = blockReduceSum(s);
    if (threadIdx.x == 0) out[(size_t)MR * VV] = -s * (1.0f / (float)MR);
}

// ---------------- host orchestration ----------------
extern "C" void kernel_launch(void* const* d_in, const int* in_sizes, int n_in,
                              void* d_out, int out_size) {
    const int*   tokens = (const int*)  d_in[0];
    const int*   target = (const int*)  d_in[1];
    const float* wte    = (const float*)d_in[2];
    const float* wpe    = (const float*)d_in[3];
    const float* ln1_g  = (const float*)d_in[4];
    const float* ln1_b  = (const float*)d_in[5];
    const float* qkv_w  = (const float*)d_in[6];
    const float* qkv_b  = (const float*)d_in[7];
    const float* proj_w = (const float*)d_in[8];
    const float* proj_b = (const float*)d_in[9];
    const float* ln2_g  = (const float*)d_in[10];
    const float* ln2_b  = (const float*)d_in[11];
    const float* fc1_w  = (const float*)d_in[12];
    const float* fc1_b  = (const float*)d_in[13];
    const float* fc2_w  = (const float*)d_in[14];
    const float* fc2_b  = (const float*)d_in[15];
    const float* lnf_g  = (const float*)d_in[16];
    const float* lnf_b  = (const float*)d_in[17];
    float* out = (float*)d_out;

    float *gx, *gpicked, *gpm, *gps, *gopart, *gml;
    __nv_bfloat16 *ghb, *gob, *gffb, *gqkvb, *gwteb, *gqkvT, *gprojT, *gfc1T, *gfc2T;
    cudaGetSymbolAddress((void**)&gx,     g_x);
    cudaGetSymbolAddress((void**)&gpicked,g_picked);
    cudaGetSymbolAddress((void**)&gpm,    g_pm);
    cudaGetSymbolAddress((void**)&gps,    g_ps);
    cudaGetSymbolAddress((void**)&gopart, g_opart);
    cudaGetSymbolAddress((void**)&gml,    g_ml);
    cudaGetSymbolAddress((void**)&ghb,    g_hb);
    cudaGetSymbolAddress((void**)&gob,    g_ob);
    cudaGetSymbolAddress((void**)&gffb,   g_ffb);
    cudaGetSymbolAddress((void**)&gqkvb,  g_qkvb);
    cudaGetSymbolAddress((void**)&gwteb,  g_wteb);
    cudaGetSymbolAddress((void**)&gqkvT,  g_qkvT);
    cudaGetSymbolAddress((void**)&gprojT, g_projT);
    cudaGetSymbolAddress((void**)&gfc1T,  g_fc1T);
    cudaGetSymbolAddress((void**)&gfc2T,  g_fc2T);

    cudaFuncSetAttribute(flash_partial_kernel,
                         cudaFuncAttributeMaxDynamicSharedMemorySize, FSMEM);
    cudaFuncSetAttribute(gemm_mma_kernel<false, 128, false>,
                         cudaFuncAttributeMaxDynamicSharedMemorySize, GS128);
    cudaFuncSetAttribute(gemm_mma_kernel<true, 128, false>,
                         cudaFuncAttributeMaxDynamicSharedMemorySize, GS128);
    cudaFuncSetAttribute(gemm_mma_kernel<false, 64, false>,
                         cudaFuncAttributeMaxDynamicSharedMemorySize, GS64);
    cudaFuncSetAttribute(gemm_mma_kernel<false, 64, true>,
                         cudaFuncAttributeMaxDynamicSharedMemorySize, GS64);

    {
        long n4 = (long)VV * DD / 4;
        convert_bf16_kernel4<<<(int)((n4 + 255) / 256), 256>>>(
            (const float4*)wte, (__nv_bfloat162*)gwteb, n4);
    }
    transpose_to_bf16<<<dim3(D3 / 64,  DD / 64,  LL), 256>>>(qkv_w,  gqkvT,  DD,  D3);
    transpose_to_bf16<<<dim3(DD / 64,  DD / 64,  LL), 256>>>(proj_w, gprojT, DD,  DD);
    transpose_to_bf16<<<dim3(FF_ / 64, DD / 64,  LL), 256>>>(fc1_w,  gfc1T,  DD,  FF_);
    transpose_to_bf16<<<dim3(DD / 64,  FF_ / 64, LL), 256>>>(fc2_w,  gfc2T,  FF_, DD);

    embed_kernel<<<(MR * DD + 255) / 256, 256>>>(tokens, wte, wpe, gx);

    for (int l = 0; l < LL; l++) {
        layernorm_kernel<<<MR, 256>>>(gx, ln1_g + (size_t)l * DD, ln1_b + (size_t)l * DD, ghb);

        gemm_mma_kernel<false, 128, false><<<dim3(MR / GBM, D3 / 128), 256, GS128>>>(
            ghb, gqkvT + (size_t)l * DD * D3, nullptr, gqkvb,
            qkv_b + (size_t)l * D3, nullptr, D3, DD, D3, 0, nullptr, nullptr);

        flash_partial_kernel<<<dim3(NQT, BB * HH, 2), 256, FSMEM>>>(gqkvb, gopart, gml);
        flash_merge_kernel<<<NITEM, 256>>>(gopart, gml, gob);

        gemm_mma_kernel<false, 64, true><<<dim3(MR / GBM, DD / 64, 2), 256, GS64>>>(
            gob, gprojT + (size_t)l * DD * DD, gx, nullptr,
            proj_b + (size_t)l * DD, nullptr, DD, DD, DD, 0, nullptr, nullptr);

        layernorm_kernel<<<MR, 256>>>(gx, ln2_g + (size_t)l * DD, ln2_b + (size_t)l * DD, ghb);

        gemm_mma_kernel<false, 64, false><<<dim3(MR / GBM, FF_ / 64), 256, GS64>>>(
            ghb, gfc1T + (size_t)l * DD * FF_, nullptr, gffb,
            fc1_b + (size_t)l * FF_, nullptr, FF_, DD, FF_, 1, nullptr, nullptr);

        gemm_mma_kernel<false, 64, true><<<dim3(MR / GBM, DD / 64, 2), 256, GS64>>>(
            gffb, gfc2T + (size_t)l * FF_ * DD, gx, nullptr,
            fc2_b + (size_t)l * DD, nullptr, DD, FF_, DD, 0, nullptr, nullptr);
    }

    layernorm_kernel<<<MR, 256>>>(gx, lnf_g, lnf_b, ghb);

    gemm_mma_kernel<true, 128, false><<<dim3(MR / GBM, NT), 256, GS128>>>(
        ghb, gwteb, out, nullptr, nullptr, nullptr, VV, DD, VV, 0, gpm, gps);

    logsoftmax_finish_kernel<<<MR, 512>>>(out, gpm, gps, target, gpicked);
    finalize_loss_kernel<<<1, 256>>>(gpicked, out);
}